// round 1
// baseline (speedup 1.0000x reference)
#include <cuda_runtime.h>
#include <math.h>

// ---------------------------------------------------------------------------
// MultiQueryAttention: B=2, S=2048, HIDDEN=2048, NH=16, NKV=2, D=128
// Round 1: exact fp32 baseline. 5 launches:
//   sgemm(Q, bias, *scale) -> sgemm(K) -> sgemm(V) -> flash_attn -> sgemm(O)
// ---------------------------------------------------------------------------

#define BATCH      2
#define SEQ        2048
#define HID        2048
#define NH         16
#define NKV        2
#define HD         128
#define KVDIM      (NKV * HD)      // 256
#define BS_ROWS    (BATCH * SEQ)   // 4096
#define REP        (NH / NKV)      // 8

// Scratch (device globals — no allocation allowed)
__device__ float g_q [BS_ROWS * HID];    // 32 MB (pre-scaled by 1/sqrt(D))
__device__ float g_k [BS_ROWS * KVDIM];  // 4 MB
__device__ float g_v [BS_ROWS * KVDIM];  // 4 MB
__device__ float g_ao[BS_ROWS * HID];    // 32 MB (attention output, pre-Wo)

// ---------------------------------------------------------------------------
// SGEMM: C[M,N] = (A[M,K] @ B[K,N] + bias[N]) * alpha
// BM=128, BN=128, BK=16, 256 threads, 8x8 per thread. All dims divide tiles.
// ---------------------------------------------------------------------------
__global__ __launch_bounds__(256) void sgemm_bias_kernel(
    const float* __restrict__ A, const float* __restrict__ B,
    const float* __restrict__ bias, float* __restrict__ C,
    int M, int N, int K, float alpha)
{
    __shared__ float As[16][128];   // stored transposed: As[k][m]
    __shared__ float Bs[16][128];   // Bs[k][n]

    const int tid = threadIdx.x;
    const int blockRow = blockIdx.y * 128;
    const int blockCol = blockIdx.x * 128;

    // A-load mapping: 128 rows x 16 k = 512 float4, 2 per thread
    const int aRow  = tid >> 2;          // 0..63
    const int aCol  = (tid & 3) * 4;     // 0,4,8,12
    // B-load mapping: 16 k x 128 n = 512 float4, 2 per thread
    const int bRow  = tid >> 5;          // 0..7
    const int bCol  = (tid & 31) * 4;

    const int ty = tid >> 4;   // 0..15
    const int tx = tid & 15;   // 0..15

    float acc[8][8];
#pragma unroll
    for (int i = 0; i < 8; i++)
#pragma unroll
        for (int j = 0; j < 8; j++) acc[i][j] = 0.f;

    for (int k0 = 0; k0 < K; k0 += 16) {
#pragma unroll
        for (int t = 0; t < 2; t++) {
            int r = aRow + t * 64;
            float4 av = *(const float4*)(A + (size_t)(blockRow + r) * K + k0 + aCol);
            As[aCol + 0][r] = av.x;
            As[aCol + 1][r] = av.y;
            As[aCol + 2][r] = av.z;
            As[aCol + 3][r] = av.w;
        }
#pragma unroll
        for (int t = 0; t < 2; t++) {
            int r = bRow + t * 8;
            *(float4*)(&Bs[r][bCol]) =
                *(const float4*)(B + (size_t)(k0 + r) * N + blockCol + bCol);
        }
        __syncthreads();

#pragma unroll
        for (int kk = 0; kk < 16; kk++) {
            float ra[8], rb[8];
            *(float4*)&ra[0] = *(const float4*)&As[kk][ty * 8];
            *(float4*)&ra[4] = *(const float4*)&As[kk][ty * 8 + 4];
            *(float4*)&rb[0] = *(const float4*)&Bs[kk][tx * 8];
            *(float4*)&rb[4] = *(const float4*)&Bs[kk][tx * 8 + 4];
#pragma unroll
            for (int i = 0; i < 8; i++)
#pragma unroll
                for (int j = 0; j < 8; j++)
                    acc[i][j] = fmaf(ra[i], rb[j], acc[i][j]);
        }
        __syncthreads();
    }

    // Epilogue: (acc + bias) * alpha
#pragma unroll
    for (int i = 0; i < 8; i++) {
        int row = blockRow + ty * 8 + i;
#pragma unroll
        for (int j4 = 0; j4 < 8; j4 += 4) {
            int col = blockCol + tx * 8 + j4;
            float4 bv = *(const float4*)(bias + col);
            float4 ov;
            ov.x = (acc[i][j4 + 0] + bv.x) * alpha;
            ov.y = (acc[i][j4 + 1] + bv.y) * alpha;
            ov.z = (acc[i][j4 + 2] + bv.z) * alpha;
            ov.w = (acc[i][j4 + 3] + bv.w) * alpha;
            *(float4*)(C + (size_t)row * N + col) = ov;
        }
    }
}

// ---------------------------------------------------------------------------
// Flash attention (fp32, online softmax). One CTA = (b, h, 64 q-rows).
// Loops over 32 KV tiles of 64 rows. 256 threads.
// SMEM: Qs[64][132] Ks[64][132] Vs[64][128] Ss[64][68]  (~115 KB dynamic)
// ---------------------------------------------------------------------------
#define QS_STRIDE 132
#define SS_STRIDE 68
#define FA_SMEM_FLOATS (64 * QS_STRIDE + 64 * QS_STRIDE + 64 * 128 + 64 * SS_STRIDE)

__global__ __launch_bounds__(256) void flash_attn_kernel()
{
    extern __shared__ float smem[];
    float* Qs = smem;                          // [64][132]
    float* Ks = Qs + 64 * QS_STRIDE;           // [64][132]
    float* Vs = Ks + 64 * QS_STRIDE;           // [64][128]
    float* Ss = Vs + 64 * 128;                 // [64][68]

    const int tid   = threadIdx.x;
    const int lane  = tid & 31;
    const int w     = tid >> 5;     // warp 0..7 -> owns rows w*8..w*8+7
    const int qtile = blockIdx.x;   // 0..31
    const int h     = blockIdx.y;   // 0..15
    const int b     = blockIdx.z;   // 0..1
    const int kvh   = h / REP;      // 0..1

    const float* qbase = g_q + ((size_t)(b * SEQ + qtile * 64)) * HID + h * HD;

    // Load Q tile: 64 rows x 128 cols = 2048 float4, 8 per thread
#pragma unroll
    for (int it = 0; it < 8; it++) {
        int idx = it * 256 + tid;
        int r  = idx >> 5;        // 0..63
        int c4 = (idx & 31) * 4;  // 0..124
        *(float4*)(&Qs[r * QS_STRIDE + c4]) =
            *(const float4*)(qbase + (size_t)r * HID + c4);
    }

    float m[8], l[8], acc[8][4];
#pragma unroll
    for (int i = 0; i < 8; i++) {
        m[i] = -INFINITY; l[i] = 0.f;
        acc[i][0] = acc[i][1] = acc[i][2] = acc[i][3] = 0.f;
    }

    const int ty2 = tid >> 4;   // 0..15 -> q-row group ty2*4
    const int tx2 = tid & 15;   // 0..15 -> k-cols {tx2, tx2+16, tx2+32, tx2+48}

    for (int kt = 0; kt < SEQ / 64; kt++) {
        __syncthreads();  // protect Ks/Vs/Ss from previous iteration readers
        const float* kbase = g_k + ((size_t)(b * SEQ + kt * 64)) * KVDIM + kvh * HD;
        const float* vbase = g_v + ((size_t)(b * SEQ + kt * 64)) * KVDIM + kvh * HD;
#pragma unroll
        for (int it = 0; it < 8; it++) {
            int idx = it * 256 + tid;
            int r  = idx >> 5;
            int c4 = (idx & 31) * 4;
            *(float4*)(&Ks[r * QS_STRIDE + c4]) =
                *(const float4*)(kbase + (size_t)r * KVDIM + c4);
            *(float4*)(&Vs[r * 128 + c4]) =
                *(const float4*)(vbase + (size_t)r * KVDIM + c4);
        }
        __syncthreads();

        // ---- scores: S = Q @ K^T  (64x64, each thread 4x4) ----
        {
            float s[4][4];
#pragma unroll
            for (int i = 0; i < 4; i++)
#pragma unroll
                for (int j = 0; j < 4; j++) s[i][j] = 0.f;

            const float4* Qs4 = (const float4*)Qs;
            const float4* Ks4 = (const float4*)Ks;
            const int r0 = ty2 * 4;
#pragma unroll 4
            for (int kk4 = 0; kk4 < 32; kk4++) {
                float4 qv[4], kv[4];
#pragma unroll
                for (int i = 0; i < 4; i++)
                    qv[i] = Qs4[(r0 + i) * (QS_STRIDE / 4) + kk4];
#pragma unroll
                for (int j = 0; j < 4; j++)
                    kv[j] = Ks4[(tx2 + 16 * j) * (QS_STRIDE / 4) + kk4];
#pragma unroll
                for (int i = 0; i < 4; i++)
#pragma unroll
                    for (int j = 0; j < 4; j++) {
                        s[i][j] = fmaf(qv[i].x, kv[j].x, s[i][j]);
                        s[i][j] = fmaf(qv[i].y, kv[j].y, s[i][j]);
                        s[i][j] = fmaf(qv[i].z, kv[j].z, s[i][j]);
                        s[i][j] = fmaf(qv[i].w, kv[j].w, s[i][j]);
                    }
            }
#pragma unroll
            for (int i = 0; i < 4; i++)
#pragma unroll
                for (int j = 0; j < 4; j++)
                    Ss[(r0 + i) * SS_STRIDE + tx2 + 16 * j] = s[i][j];
        }
        __syncthreads();

        // ---- online softmax: warp w handles rows w*8 .. w*8+7 ----
#pragma unroll
        for (int i = 0; i < 8; i++) {
            int r = w * 8 + i;
            float x0 = Ss[r * SS_STRIDE + lane];
            float x1 = Ss[r * SS_STRIDE + 32 + lane];
            float mx = fmaxf(x0, x1);
#pragma unroll
            for (int off = 16; off > 0; off >>= 1)
                mx = fmaxf(mx, __shfl_xor_sync(0xffffffffu, mx, off));
            float mnew = fmaxf(m[i], mx);
            float corr = __expf(m[i] - mnew);
            float p0 = __expf(x0 - mnew);
            float p1 = __expf(x1 - mnew);
            Ss[r * SS_STRIDE + lane] = p0;
            Ss[r * SS_STRIDE + 32 + lane] = p1;
            float ps = p0 + p1;
#pragma unroll
            for (int off = 16; off > 0; off >>= 1)
                ps += __shfl_xor_sync(0xffffffffu, ps, off);
            l[i] = l[i] * corr + ps;
            m[i] = mnew;
            acc[i][0] *= corr; acc[i][1] *= corr;
            acc[i][2] *= corr; acc[i][3] *= corr;
        }
        __syncwarp();

        // ---- AV: acc[i][0..3] += P[w*8+i][c] * V[c][lane*4..+3] ----
        {
            const float4* Vs4 = (const float4*)Vs;
#pragma unroll 4
            for (int c = 0; c < 64; c++) {
                float4 v = Vs4[c * 32 + lane];
#pragma unroll
                for (int i = 0; i < 8; i++) {
                    float p = Ss[(w * 8 + i) * SS_STRIDE + c];
                    acc[i][0] = fmaf(p, v.x, acc[i][0]);
                    acc[i][1] = fmaf(p, v.y, acc[i][1]);
                    acc[i][2] = fmaf(p, v.z, acc[i][2]);
                    acc[i][3] = fmaf(p, v.w, acc[i][3]);
                }
            }
        }
    }

    // ---- epilogue: normalize and write [B,S,NH,D] ----
#pragma unroll
    for (int i = 0; i < 8; i++) {
        float inv = 1.0f / l[i];
        size_t row = (size_t)(b * SEQ + qtile * 64 + w * 8 + i);
        float4 ov;
        ov.x = acc[i][0] * inv; ov.y = acc[i][1] * inv;
        ov.z = acc[i][2] * inv; ov.w = acc[i][3] * inv;
        *(float4*)(g_ao + row * HID + h * HD + lane * 4) = ov;
    }
}

// ---------------------------------------------------------------------------
// kernel_launch
// ---------------------------------------------------------------------------
extern "C" void kernel_launch(void* const* d_in, const int* in_sizes, int n_in,
                              void* d_out, int out_size)
{
    (void)in_sizes; (void)n_in; (void)out_size;
    const float* hidden = (const float*)d_in[0];
    const float* Wq = (const float*)d_in[1];
    const float* bq = (const float*)d_in[2];
    const float* Wk = (const float*)d_in[3];
    const float* bk = (const float*)d_in[4];
    const float* Wv = (const float*)d_in[5];
    const float* bv = (const float*)d_in[6];
    const float* Wo = (const float*)d_in[7];
    const float* bo = (const float*)d_in[8];
    float* out = (float*)d_out;

    float* q; float* k; float* v; float* ao;
    cudaGetSymbolAddress((void**)&q,  g_q);
    cudaGetSymbolAddress((void**)&k,  g_k);
    cudaGetSymbolAddress((void**)&v,  g_v);
    cudaGetSymbolAddress((void**)&ao, g_ao);

    const float scaling = 0.08838834764831845f;  // 128^-0.5

    dim3 blk(256);
    dim3 gridQ(HID / 128, BS_ROWS / 128);    // (16, 32)
    dim3 gridKV(KVDIM / 128, BS_ROWS / 128); // (2, 32)

    sgemm_bias_kernel<<<gridQ, blk>>>(hidden, Wq, bq, q, BS_ROWS, HID, HID, scaling);
    sgemm_bias_kernel<<<gridKV, blk>>>(hidden, Wk, bk, k, BS_ROWS, KVDIM, HID, 1.0f);
    sgemm_bias_kernel<<<gridKV, blk>>>(hidden, Wv, bv, v, BS_ROWS, KVDIM, HID, 1.0f);

    static int fa_smem_set = 0;
    int fa_smem = FA_SMEM_FLOATS * (int)sizeof(float);
    if (!fa_smem_set) {
        cudaFuncSetAttribute(flash_attn_kernel,
                             cudaFuncAttributeMaxDynamicSharedMemorySize, fa_smem);
        fa_smem_set = 1;
    }
    dim3 gridFA(SEQ / 64, NH, BATCH);        // (32, 16, 2)
    flash_attn_kernel<<<gridFA, blk, fa_smem>>>();

    sgemm_bias_kernel<<<gridQ, blk>>>(ao, Wo, bo, out, BS_ROWS, HID, HID, 1.0f);
}

// round 3
// speedup vs baseline: 1.3537x; 1.3537x over previous
#include <cuda_runtime.h>
#include <cuda_bf16.h>
#include <math.h>
#include <stdint.h>

// ---------------------------------------------------------------------------
// MultiQueryAttention: B=2, S=2048, HIDDEN=2048, NH=16, NKV=2, D=128
// Round 3: projections via mma.sync bf16 (hi/lo split x3, fp32 accum).
//          (tcgen05 unavailable: harness PTX target is sm_100, not sm_100a.)
//          Flash attention still fp32 FMA.
// ---------------------------------------------------------------------------

#define BATCH      2
#define SEQ        2048
#define HID        2048
#define NH         16
#define NKV        2
#define HD         128
#define KVDIM      (NKV * HD)      // 256
#define BS_ROWS    (BATCH * SEQ)   // 4096
#define REP        (NH / NKV)      // 8

// ---------------- scratch (device globals; no allocation allowed) ----------
__device__ float g_q [BS_ROWS * HID];
__device__ float g_k [BS_ROWS * KVDIM];
__device__ float g_v [BS_ROWS * KVDIM];
__device__ float g_ao[BS_ROWS * HID];

__device__ __nv_bfloat16 g_ah [BS_ROWS * HID];   // hidden hi
__device__ __nv_bfloat16 g_al [BS_ROWS * HID];   // hidden lo
__device__ __nv_bfloat16 g_aoh[BS_ROWS * HID];   // attn-out hi
__device__ __nv_bfloat16 g_aol[BS_ROWS * HID];   // attn-out lo
__device__ __nv_bfloat16 g_wqh[HID * HID],   g_wql[HID * HID];     // Wq^T
__device__ __nv_bfloat16 g_woh[HID * HID],   g_wol[HID * HID];     // Wo^T
__device__ __nv_bfloat16 g_wkh[KVDIM * HID], g_wkl[KVDIM * HID];   // Wk^T
__device__ __nv_bfloat16 g_wvh[KVDIM * HID], g_wvl[KVDIM * HID];   // Wv^T

// ---------------------------------------------------------------------------
// mma.sync m16n8k16 row.col f32.bf16.bf16.f32 (sm_80+; works on sm_100 target)
// ---------------------------------------------------------------------------
static __device__ __forceinline__ void mma16816(
    float* d, const uint32_t* a, const uint32_t* b)
{
    asm volatile(
        "mma.sync.aligned.m16n8k16.row.col.f32.bf16.bf16.f32 "
        "{%0,%1,%2,%3}, {%4,%5,%6,%7}, {%8,%9}, {%0,%1,%2,%3};"
        : "+f"(d[0]), "+f"(d[1]), "+f"(d[2]), "+f"(d[3])
        : "r"(a[0]), "r"(a[1]), "r"(a[2]), "r"(a[3]), "r"(b[0]), "r"(b[1]));
}

// ---------------------------------------------------------------------------
// Warp-tiled bf16x3 GEMM: C[M,N] = (sum_k A[m,k]*Bt[n,k] + bias[n]) * alpha
// A hi/lo [M,K] row-major, Bt hi/lo [N,K] row-major (= col-major B for mma).
// CTA tile 128x128, K-chunk 32, 8 warps (2x4), warp tile 64x32.
// SMEM pitch 40 halves -> conflict-free 32-bit fragment loads.
// ---------------------------------------------------------------------------
#define PITCH 40

__global__ __launch_bounds__(256, 2) void gemm_mma_kernel(
    const __nv_bfloat16* __restrict__ Ahi, const __nv_bfloat16* __restrict__ Alo,
    const __nv_bfloat16* __restrict__ Bhi, const __nv_bfloat16* __restrict__ Blo,
    const float* __restrict__ bias, float* __restrict__ C,
    int N, int K, float alpha)
{
    __shared__ __align__(16) __nv_bfloat16 As_hi[128 * PITCH];
    __shared__ __align__(16) __nv_bfloat16 As_lo[128 * PITCH];
    __shared__ __align__(16) __nv_bfloat16 Bs_hi[128 * PITCH];
    __shared__ __align__(16) __nv_bfloat16 Bs_lo[128 * PITCH];

    const int tid    = threadIdx.x;
    const int lane   = tid & 31;
    const int wid    = tid >> 5;
    const int warp_m = wid >> 2;    // 0..1
    const int warp_n = wid & 3;     // 0..3
    const int g      = lane >> 2;   // 0..7
    const int tg     = lane & 3;    // 0..3

    const int blockRow = blockIdx.y * 128;
    const int blockCol = blockIdx.x * 128;

    float acc[4][4][4];
#pragma unroll
    for (int mi = 0; mi < 4; mi++)
#pragma unroll
        for (int ni = 0; ni < 4; ni++)
#pragma unroll
            for (int t = 0; t < 4; t++) acc[mi][ni][t] = 0.f;

    for (int k0 = 0; k0 < K; k0 += 32) {
        // --- load tiles: 128 rows x 32 halves per operand, 2 uint4/thread ---
#pragma unroll
        for (int it = 0; it < 2; it++) {
            int idx = it * 256 + tid;
            int m  = idx >> 2;        // 0..127
            int kq = idx & 3;         // 0..3 (x8 halves)
            size_t ga = (size_t)(blockRow + m) * K + k0 + kq * 8;
            size_t gb = (size_t)(blockCol + m) * K + k0 + kq * 8;
            int so = m * PITCH + kq * 8;
            *(uint4*)(As_hi + so) = *(const uint4*)(Ahi + ga);
            *(uint4*)(As_lo + so) = *(const uint4*)(Alo + ga);
            *(uint4*)(Bs_hi + so) = *(const uint4*)(Bhi + gb);
            *(uint4*)(Bs_lo + so) = *(const uint4*)(Blo + gb);
        }
        __syncthreads();

#pragma unroll
        for (int ks = 0; ks < 2; ks++) {
            const int c0 = ks * 16 + tg * 2;
            uint32_t ah[4][4], al[4][4];
#pragma unroll
            for (int mi = 0; mi < 4; mi++) {
                int r0 = warp_m * 64 + mi * 16 + g;
                ah[mi][0] = *(const uint32_t*)(As_hi + r0 * PITCH + c0);
                ah[mi][1] = *(const uint32_t*)(As_hi + (r0 + 8) * PITCH + c0);
                ah[mi][2] = *(const uint32_t*)(As_hi + r0 * PITCH + c0 + 8);
                ah[mi][3] = *(const uint32_t*)(As_hi + (r0 + 8) * PITCH + c0 + 8);
                al[mi][0] = *(const uint32_t*)(As_lo + r0 * PITCH + c0);
                al[mi][1] = *(const uint32_t*)(As_lo + (r0 + 8) * PITCH + c0);
                al[mi][2] = *(const uint32_t*)(As_lo + r0 * PITCH + c0 + 8);
                al[mi][3] = *(const uint32_t*)(As_lo + (r0 + 8) * PITCH + c0 + 8);
            }
#pragma unroll
            for (int ni = 0; ni < 4; ni++) {
                int n0 = warp_n * 32 + ni * 8 + g;
                uint32_t bh[2], bl[2];
                bh[0] = *(const uint32_t*)(Bs_hi + n0 * PITCH + c0);
                bh[1] = *(const uint32_t*)(Bs_hi + n0 * PITCH + c0 + 8);
                bl[0] = *(const uint32_t*)(Bs_lo + n0 * PITCH + c0);
                bl[1] = *(const uint32_t*)(Bs_lo + n0 * PITCH + c0 + 8);
#pragma unroll
                for (int mi = 0; mi < 4; mi++) {
                    mma16816(acc[mi][ni], ah[mi], bh);
                    mma16816(acc[mi][ni], ah[mi], bl);
                    mma16816(acc[mi][ni], al[mi], bh);
                }
            }
        }
        __syncthreads();
    }

    // --- epilogue: (acc + bias) * alpha ---
#pragma unroll
    for (int mi = 0; mi < 4; mi++) {
#pragma unroll
        for (int ni = 0; ni < 4; ni++) {
            int row0 = blockRow + warp_m * 64 + mi * 16 + g;
            int col  = blockCol + warp_n * 32 + ni * 8 + tg * 2;
            float2 b2 = *(const float2*)(bias + col);
            float2 o0, o1;
            o0.x = (acc[mi][ni][0] + b2.x) * alpha;
            o0.y = (acc[mi][ni][1] + b2.y) * alpha;
            o1.x = (acc[mi][ni][2] + b2.x) * alpha;
            o1.y = (acc[mi][ni][3] + b2.y) * alpha;
            *(float2*)(C + (size_t)row0 * N + col)       = o0;
            *(float2*)(C + (size_t)(row0 + 8) * N + col) = o1;
        }
    }
}

// ---------------------------------------------------------------------------
// split: fp32 -> bf16 hi + bf16 lo (8 elems/thread)
// ---------------------------------------------------------------------------
__global__ __launch_bounds__(256) void split_kernel(
    const float* __restrict__ X, __nv_bfloat16* __restrict__ hi,
    __nv_bfloat16* __restrict__ lo)
{
    size_t base = ((size_t)blockIdx.x * 256 + threadIdx.x) * 8;
    float4 a = *(const float4*)(X + base);
    float4 b = *(const float4*)(X + base + 4);
    float x[8] = {a.x, a.y, a.z, a.w, b.x, b.y, b.z, b.w};
    __nv_bfloat16 h[8], l[8];
#pragma unroll
    for (int j = 0; j < 8; j++) {
        h[j] = __float2bfloat16(x[j]);
        l[j] = __float2bfloat16(x[j] - __bfloat162float(h[j]));
    }
    *(uint4*)(hi + base) = *(uint4*)h;
    *(uint4*)(lo + base) = *(uint4*)l;
}

// ---------------------------------------------------------------------------
// transpose + split: W[K,N] fp32 -> W^T hi/lo [N,K] bf16
// ---------------------------------------------------------------------------
__global__ __launch_bounds__(256) void transpose_split_kernel(
    const float* __restrict__ W, __nv_bfloat16* __restrict__ hiT,
    __nv_bfloat16* __restrict__ loT, int K, int N)
{
    __shared__ float tile[32][33];
    const int n0 = blockIdx.x * 32;
    const int k0 = blockIdx.y * 32;
    const int tx = threadIdx.x & 31;
    const int ty = threadIdx.x >> 5;   // 0..7
#pragma unroll
    for (int i = 0; i < 4; i++)
        tile[ty + i * 8][tx] = W[(size_t)(k0 + ty + i * 8) * N + n0 + tx];
    __syncthreads();
#pragma unroll
    for (int i = 0; i < 4; i++) {
        int r = ty + i * 8;              // n-local
        float x = tile[tx][r];
        __nv_bfloat16 h = __float2bfloat16(x);
        __nv_bfloat16 l = __float2bfloat16(x - __bfloat162float(h));
        size_t o = (size_t)(n0 + r) * K + k0 + tx;
        hiT[o] = h;
        loT[o] = l;
    }
}

// ---------------------------------------------------------------------------
// Flash attention (fp32, online softmax) — unchanged from round 1
// ---------------------------------------------------------------------------
#define QS_STRIDE 132
#define SS_STRIDE 68
#define FA_SMEM_FLOATS (64 * QS_STRIDE + 64 * QS_STRIDE + 64 * 128 + 64 * SS_STRIDE)

__global__ __launch_bounds__(256) void flash_attn_kernel()
{
    extern __shared__ float fsm[];
    float* Qs = fsm;
    float* Ks = Qs + 64 * QS_STRIDE;
    float* Vs = Ks + 64 * QS_STRIDE;
    float* Ss = Vs + 64 * 128;

    const int tid   = threadIdx.x;
    const int lane  = tid & 31;
    const int w     = tid >> 5;
    const int qtile = blockIdx.x;
    const int h     = blockIdx.y;
    const int b     = blockIdx.z;
    const int kvh   = h / REP;

    const float* qbase = g_q + ((size_t)(b * SEQ + qtile * 64)) * HID + h * HD;

#pragma unroll
    for (int it = 0; it < 8; it++) {
        int idx = it * 256 + tid;
        int r  = idx >> 5;
        int c4 = (idx & 31) * 4;
        *(float4*)(&Qs[r * QS_STRIDE + c4]) =
            *(const float4*)(qbase + (size_t)r * HID + c4);
    }

    float m[8], l[8], acc[8][4];
#pragma unroll
    for (int i = 0; i < 8; i++) {
        m[i] = -INFINITY; l[i] = 0.f;
        acc[i][0] = acc[i][1] = acc[i][2] = acc[i][3] = 0.f;
    }

    const int ty2 = tid >> 4;
    const int tx2 = tid & 15;

    for (int kt = 0; kt < SEQ / 64; kt++) {
        __syncthreads();
        const float* kbase = g_k + ((size_t)(b * SEQ + kt * 64)) * KVDIM + kvh * HD;
        const float* vbase = g_v + ((size_t)(b * SEQ + kt * 64)) * KVDIM + kvh * HD;
#pragma unroll
        for (int it = 0; it < 8; it++) {
            int idx = it * 256 + tid;
            int r  = idx >> 5;
            int c4 = (idx & 31) * 4;
            *(float4*)(&Ks[r * QS_STRIDE + c4]) =
                *(const float4*)(kbase + (size_t)r * KVDIM + c4);
            *(float4*)(&Vs[r * 128 + c4]) =
                *(const float4*)(vbase + (size_t)r * KVDIM + c4);
        }
        __syncthreads();

        {
            float s[4][4];
#pragma unroll
            for (int i = 0; i < 4; i++)
#pragma unroll
                for (int j = 0; j < 4; j++) s[i][j] = 0.f;

            const float4* Qs4 = (const float4*)Qs;
            const float4* Ks4 = (const float4*)Ks;
            const int r0 = ty2 * 4;
#pragma unroll 4
            for (int kk4 = 0; kk4 < 32; kk4++) {
                float4 qv[4], kv[4];
#pragma unroll
                for (int i = 0; i < 4; i++)
                    qv[i] = Qs4[(r0 + i) * (QS_STRIDE / 4) + kk4];
#pragma unroll
                for (int j = 0; j < 4; j++)
                    kv[j] = Ks4[(tx2 + 16 * j) * (QS_STRIDE / 4) + kk4];
#pragma unroll
                for (int i = 0; i < 4; i++)
#pragma unroll
                    for (int j = 0; j < 4; j++) {
                        s[i][j] = fmaf(qv[i].x, kv[j].x, s[i][j]);
                        s[i][j] = fmaf(qv[i].y, kv[j].y, s[i][j]);
                        s[i][j] = fmaf(qv[i].z, kv[j].z, s[i][j]);
                        s[i][j] = fmaf(qv[i].w, kv[j].w, s[i][j]);
                    }
            }
#pragma unroll
            for (int i = 0; i < 4; i++)
#pragma unroll
                for (int j = 0; j < 4; j++)
                    Ss[(r0 + i) * SS_STRIDE + tx2 + 16 * j] = s[i][j];
        }
        __syncthreads();

#pragma unroll
        for (int i = 0; i < 8; i++) {
            int r = w * 8 + i;
            float x0 = Ss[r * SS_STRIDE + lane];
            float x1 = Ss[r * SS_STRIDE + 32 + lane];
            float mx = fmaxf(x0, x1);
#pragma unroll
            for (int off = 16; off > 0; off >>= 1)
                mx = fmaxf(mx, __shfl_xor_sync(0xffffffffu, mx, off));
            float mnew = fmaxf(m[i], mx);
            float corr = __expf(m[i] - mnew);
            float p0 = __expf(x0 - mnew);
            float p1 = __expf(x1 - mnew);
            Ss[r * SS_STRIDE + lane] = p0;
            Ss[r * SS_STRIDE + 32 + lane] = p1;
            float ps = p0 + p1;
#pragma unroll
            for (int off = 16; off > 0; off >>= 1)
                ps += __shfl_xor_sync(0xffffffffu, ps, off);
            l[i] = l[i] * corr + ps;
            m[i] = mnew;
            acc[i][0] *= corr; acc[i][1] *= corr;
            acc[i][2] *= corr; acc[i][3] *= corr;
        }
        __syncwarp();

        {
            const float4* Vs4 = (const float4*)Vs;
#pragma unroll 4
            for (int c = 0; c < 64; c++) {
                float4 v = Vs4[c * 32 + lane];
#pragma unroll
                for (int i = 0; i < 8; i++) {
                    float p = Ss[(w * 8 + i) * SS_STRIDE + c];
                    acc[i][0] = fmaf(p, v.x, acc[i][0]);
                    acc[i][1] = fmaf(p, v.y, acc[i][1]);
                    acc[i][2] = fmaf(p, v.z, acc[i][2]);
                    acc[i][3] = fmaf(p, v.w, acc[i][3]);
                }
            }
        }
    }

#pragma unroll
    for (int i = 0; i < 8; i++) {
        float inv = 1.0f / l[i];
        size_t row = (size_t)(b * SEQ + qtile * 64 + w * 8 + i);
        float4 ov;
        ov.x = acc[i][0] * inv; ov.y = acc[i][1] * inv;
        ov.z = acc[i][2] * inv; ov.w = acc[i][3] * inv;
        *(float4*)(g_ao + row * HID + h * HD + lane * 4) = ov;
    }
}

// ---------------------------------------------------------------------------
// kernel_launch
// ---------------------------------------------------------------------------
extern "C" void kernel_launch(void* const* d_in, const int* in_sizes, int n_in,
                              void* d_out, int out_size)
{
    (void)in_sizes; (void)n_in; (void)out_size;
    const float* hidden = (const float*)d_in[0];
    const float* Wq = (const float*)d_in[1];
    const float* bq = (const float*)d_in[2];
    const float* Wk = (const float*)d_in[3];
    const float* bk = (const float*)d_in[4];
    const float* Wv = (const float*)d_in[5];
    const float* bv = (const float*)d_in[6];
    const float* Wo = (const float*)d_in[7];
    const float* bo = (const float*)d_in[8];
    float* out = (float*)d_out;

    float *q, *k, *v, *ao;
    __nv_bfloat16 *ah, *al, *aoh, *aol;
    __nv_bfloat16 *wqh, *wql, *wkh, *wkl, *wvh, *wvl, *woh, *wol;
    cudaGetSymbolAddress((void**)&q,   g_q);
    cudaGetSymbolAddress((void**)&k,   g_k);
    cudaGetSymbolAddress((void**)&v,   g_v);
    cudaGetSymbolAddress((void**)&ao,  g_ao);
    cudaGetSymbolAddress((void**)&ah,  g_ah);
    cudaGetSymbolAddress((void**)&al,  g_al);
    cudaGetSymbolAddress((void**)&aoh, g_aoh);
    cudaGetSymbolAddress((void**)&aol, g_aol);
    cudaGetSymbolAddress((void**)&wqh, g_wqh);
    cudaGetSymbolAddress((void**)&wql, g_wql);
    cudaGetSymbolAddress((void**)&wkh, g_wkh);
    cudaGetSymbolAddress((void**)&wkl, g_wkl);
    cudaGetSymbolAddress((void**)&wvh, g_wvh);
    cudaGetSymbolAddress((void**)&wvl, g_wvl);
    cudaGetSymbolAddress((void**)&woh, g_woh);
    cudaGetSymbolAddress((void**)&wol, g_wol);

    static int attr_set = 0;
    if (!attr_set) {
        cudaFuncSetAttribute(flash_attn_kernel,
                             cudaFuncAttributeMaxDynamicSharedMemorySize,
                             FA_SMEM_FLOATS * (int)sizeof(float));
        attr_set = 1;
    }

    const float scaling = 0.08838834764831845f;  // 128^-0.5

    // 1) split hidden, transpose+split weights
    split_kernel<<<(BS_ROWS * HID / 8) / 256, 256>>>(hidden, ah, al);
    transpose_split_kernel<<<dim3(HID / 32,   HID / 32), 256>>>(Wq, wqh, wql, HID, HID);
    transpose_split_kernel<<<dim3(KVDIM / 32, HID / 32), 256>>>(Wk, wkh, wkl, HID, KVDIM);
    transpose_split_kernel<<<dim3(KVDIM / 32, HID / 32), 256>>>(Wv, wvh, wvl, HID, KVDIM);
    transpose_split_kernel<<<dim3(HID / 32,   HID / 32), 256>>>(Wo, woh, wol, HID, HID);

    // 2) projections on tensor cores (mma.sync bf16 x3)
    gemm_mma_kernel<<<dim3(HID / 128,   BS_ROWS / 128), 256>>>(
        ah, al, wqh, wql, bq, q, HID, HID, scaling);
    gemm_mma_kernel<<<dim3(KVDIM / 128, BS_ROWS / 128), 256>>>(
        ah, al, wkh, wkl, bk, k, KVDIM, HID, 1.0f);
    gemm_mma_kernel<<<dim3(KVDIM / 128, BS_ROWS / 128), 256>>>(
        ah, al, wvh, wvl, bv, v, KVDIM, HID, 1.0f);

    // 3) attention (fp32)
    flash_attn_kernel<<<dim3(SEQ / 64, NH, BATCH), 256,
                        FA_SMEM_FLOATS * (int)sizeof(float)>>>();

    // 4) split attention output, O-projection
    split_kernel<<<(BS_ROWS * HID / 8) / 256, 256>>>(ao, aoh, aol);
    gemm_mma_kernel<<<dim3(HID / 128, BS_ROWS / 128), 256>>>(
        aoh, aol, woh, wol, bo, out, HID, HID, 1.0f);
}

// round 4
// speedup vs baseline: 2.3134x; 1.7090x over previous
#include <cuda_runtime.h>
#include <cuda_bf16.h>
#include <cuda_fp16.h>
#include <math.h>
#include <stdint.h>

// ---------------------------------------------------------------------------
// MultiQueryAttention: B=2, S=2048, HIDDEN=2048, NH=16, NKV=2, D=128
// Round 4: projections mma.sync bf16x3 (emit fp16 qkv), flash attention on
//          tensor cores (fp16 mma.sync), attn-out split written in-epilogue.
// ---------------------------------------------------------------------------

#define BATCH      2
#define SEQ        2048
#define HID        2048
#define NH         16
#define NKV        2
#define HD         128
#define KVDIM      (NKV * HD)      // 256
#define BS_ROWS    (BATCH * SEQ)   // 4096
#define REP        (NH / NKV)      // 8

// ---------------- scratch (device globals; no allocation allowed) ----------
__device__ __half g_qh[BS_ROWS * HID];     // q fp16 (pre-scaled)
__device__ __half g_kh[BS_ROWS * KVDIM];   // k fp16
__device__ __half g_vh[BS_ROWS * KVDIM];   // v fp16

__device__ __nv_bfloat16 g_ah [BS_ROWS * HID];   // hidden hi
__device__ __nv_bfloat16 g_al [BS_ROWS * HID];   // hidden lo
__device__ __nv_bfloat16 g_aoh[BS_ROWS * HID];   // attn-out hi (flash epilogue)
__device__ __nv_bfloat16 g_aol[BS_ROWS * HID];   // attn-out lo
__device__ __nv_bfloat16 g_wqh[HID * HID],   g_wql[HID * HID];     // Wq^T
__device__ __nv_bfloat16 g_woh[HID * HID],   g_wol[HID * HID];     // Wo^T
__device__ __nv_bfloat16 g_wkh[KVDIM * HID], g_wkl[KVDIM * HID];   // Wk^T
__device__ __nv_bfloat16 g_wvh[KVDIM * HID], g_wvl[KVDIM * HID];   // Wv^T

// ---------------------------------------------------------------------------
// mma.sync m16n8k16 row.col f32 accum (bf16 and f16 operand flavors)
// ---------------------------------------------------------------------------
static __device__ __forceinline__ void mma16816_bf16(
    float* d, const uint32_t* a, const uint32_t* b)
{
    asm volatile(
        "mma.sync.aligned.m16n8k16.row.col.f32.bf16.bf16.f32 "
        "{%0,%1,%2,%3}, {%4,%5,%6,%7}, {%8,%9}, {%0,%1,%2,%3};"
        : "+f"(d[0]), "+f"(d[1]), "+f"(d[2]), "+f"(d[3])
        : "r"(a[0]), "r"(a[1]), "r"(a[2]), "r"(a[3]), "r"(b[0]), "r"(b[1]));
}
static __device__ __forceinline__ void mma16816_f16(
    float* d, const uint32_t* a, const uint32_t* b)
{
    asm volatile(
        "mma.sync.aligned.m16n8k16.row.col.f32.f16.f16.f32 "
        "{%0,%1,%2,%3}, {%4,%5,%6,%7}, {%8,%9}, {%0,%1,%2,%3};"
        : "+f"(d[0]), "+f"(d[1]), "+f"(d[2]), "+f"(d[3])
        : "r"(a[0]), "r"(a[1]), "r"(a[2]), "r"(a[3]), "r"(b[0]), "r"(b[1]));
}

// ---------------------------------------------------------------------------
// Projection GEMM (bf16 hi/lo x3): C[M,N] = (A@Bt^T + bias) * alpha
// Optionally writes fp32 C and/or fp16 Ch.
// ---------------------------------------------------------------------------
#define PITCH 40

__global__ __launch_bounds__(256, 2) void gemm_mma_kernel(
    const __nv_bfloat16* __restrict__ Ahi, const __nv_bfloat16* __restrict__ Alo,
    const __nv_bfloat16* __restrict__ Bhi, const __nv_bfloat16* __restrict__ Blo,
    const float* __restrict__ bias, float* __restrict__ C,
    __half* __restrict__ Ch,
    int N, int K, float alpha)
{
    __shared__ __align__(16) __nv_bfloat16 As_hi[128 * PITCH];
    __shared__ __align__(16) __nv_bfloat16 As_lo[128 * PITCH];
    __shared__ __align__(16) __nv_bfloat16 Bs_hi[128 * PITCH];
    __shared__ __align__(16) __nv_bfloat16 Bs_lo[128 * PITCH];

    const int tid    = threadIdx.x;
    const int lane   = tid & 31;
    const int wid    = tid >> 5;
    const int warp_m = wid >> 2;    // 0..1
    const int warp_n = wid & 3;     // 0..3
    const int g      = lane >> 2;   // 0..7
    const int tg     = lane & 3;    // 0..3

    const int blockRow = blockIdx.y * 128;
    const int blockCol = blockIdx.x * 128;

    float acc[4][4][4];
#pragma unroll
    for (int mi = 0; mi < 4; mi++)
#pragma unroll
        for (int ni = 0; ni < 4; ni++)
#pragma unroll
            for (int t = 0; t < 4; t++) acc[mi][ni][t] = 0.f;

    for (int k0 = 0; k0 < K; k0 += 32) {
#pragma unroll
        for (int it = 0; it < 2; it++) {
            int idx = it * 256 + tid;
            int m  = idx >> 2;
            int kq = idx & 3;
            size_t ga = (size_t)(blockRow + m) * K + k0 + kq * 8;
            size_t gb = (size_t)(blockCol + m) * K + k0 + kq * 8;
            int so = m * PITCH + kq * 8;
            *(uint4*)(As_hi + so) = *(const uint4*)(Ahi + ga);
            *(uint4*)(As_lo + so) = *(const uint4*)(Alo + ga);
            *(uint4*)(Bs_hi + so) = *(const uint4*)(Bhi + gb);
            *(uint4*)(Bs_lo + so) = *(const uint4*)(Blo + gb);
        }
        __syncthreads();

#pragma unroll
        for (int ks = 0; ks < 2; ks++) {
            const int c0 = ks * 16 + tg * 2;
            uint32_t ah[4][4], al[4][4];
#pragma unroll
            for (int mi = 0; mi < 4; mi++) {
                int r0 = warp_m * 64 + mi * 16 + g;
                ah[mi][0] = *(const uint32_t*)(As_hi + r0 * PITCH + c0);
                ah[mi][1] = *(const uint32_t*)(As_hi + (r0 + 8) * PITCH + c0);
                ah[mi][2] = *(const uint32_t*)(As_hi + r0 * PITCH + c0 + 8);
                ah[mi][3] = *(const uint32_t*)(As_hi + (r0 + 8) * PITCH + c0 + 8);
                al[mi][0] = *(const uint32_t*)(As_lo + r0 * PITCH + c0);
                al[mi][1] = *(const uint32_t*)(As_lo + (r0 + 8) * PITCH + c0);
                al[mi][2] = *(const uint32_t*)(As_lo + r0 * PITCH + c0 + 8);
                al[mi][3] = *(const uint32_t*)(As_lo + (r0 + 8) * PITCH + c0 + 8);
            }
#pragma unroll
            for (int ni = 0; ni < 4; ni++) {
                int n0 = warp_n * 32 + ni * 8 + g;
                uint32_t bh[2], bl[2];
                bh[0] = *(const uint32_t*)(Bs_hi + n0 * PITCH + c0);
                bh[1] = *(const uint32_t*)(Bs_hi + n0 * PITCH + c0 + 8);
                bl[0] = *(const uint32_t*)(Bs_lo + n0 * PITCH + c0);
                bl[1] = *(const uint32_t*)(Bs_lo + n0 * PITCH + c0 + 8);
#pragma unroll
                for (int mi = 0; mi < 4; mi++) {
                    mma16816_bf16(acc[mi][ni], ah[mi], bh);
                    mma16816_bf16(acc[mi][ni], ah[mi], bl);
                    mma16816_bf16(acc[mi][ni], al[mi], bh);
                }
            }
        }
        __syncthreads();
    }

#pragma unroll
    for (int mi = 0; mi < 4; mi++) {
#pragma unroll
        for (int ni = 0; ni < 4; ni++) {
            int row0 = blockRow + warp_m * 64 + mi * 16 + g;
            int col  = blockCol + warp_n * 32 + ni * 8 + tg * 2;
            float2 b2 = *(const float2*)(bias + col);
            float2 o0, o1;
            o0.x = (acc[mi][ni][0] + b2.x) * alpha;
            o0.y = (acc[mi][ni][1] + b2.y) * alpha;
            o1.x = (acc[mi][ni][2] + b2.x) * alpha;
            o1.y = (acc[mi][ni][3] + b2.y) * alpha;
            if (C) {
                *(float2*)(C + (size_t)row0 * N + col)       = o0;
                *(float2*)(C + (size_t)(row0 + 8) * N + col) = o1;
            }
            if (Ch) {
                *(__half2*)(Ch + (size_t)row0 * N + col) =
                    __floats2half2_rn(o0.x, o0.y);
                *(__half2*)(Ch + (size_t)(row0 + 8) * N + col) =
                    __floats2half2_rn(o1.x, o1.y);
            }
        }
    }
}

// ---------------------------------------------------------------------------
// split / transpose_split prep kernels (unchanged)
// ---------------------------------------------------------------------------
__global__ __launch_bounds__(256) void split_kernel(
    const float* __restrict__ X, __nv_bfloat16* __restrict__ hi,
    __nv_bfloat16* __restrict__ lo)
{
    size_t base = ((size_t)blockIdx.x * 256 + threadIdx.x) * 8;
    float4 a = *(const float4*)(X + base);
    float4 b = *(const float4*)(X + base + 4);
    float x[8] = {a.x, a.y, a.z, a.w, b.x, b.y, b.z, b.w};
    __nv_bfloat16 h[8], l[8];
#pragma unroll
    for (int j = 0; j < 8; j++) {
        h[j] = __float2bfloat16(x[j]);
        l[j] = __float2bfloat16(x[j] - __bfloat162float(h[j]));
    }
    *(uint4*)(hi + base) = *(uint4*)h;
    *(uint4*)(lo + base) = *(uint4*)l;
}

__global__ __launch_bounds__(256) void transpose_split_kernel(
    const float* __restrict__ W, __nv_bfloat16* __restrict__ hiT,
    __nv_bfloat16* __restrict__ loT, int K, int N)
{
    __shared__ float tile[32][33];
    const int n0 = blockIdx.x * 32;
    const int k0 = blockIdx.y * 32;
    const int tx = threadIdx.x & 31;
    const int ty = threadIdx.x >> 5;
#pragma unroll
    for (int i = 0; i < 4; i++)
        tile[ty + i * 8][tx] = W[(size_t)(k0 + ty + i * 8) * N + n0 + tx];
    __syncthreads();
#pragma unroll
    for (int i = 0; i < 4; i++) {
        int r = ty + i * 8;
        float x = tile[tx][r];
        __nv_bfloat16 h = __float2bfloat16(x);
        __nv_bfloat16 l = __float2bfloat16(x - __bfloat162float(h));
        size_t o = (size_t)(n0 + r) * K + k0 + tx;
        hiT[o] = h;
        loT[o] = l;
    }
}

// ---------------------------------------------------------------------------
// Flash attention on tensor cores (fp16 operands, fp32 accum).
// CTA = (qtile of 64 rows, head, batch). 8 warps: grid 4(m) x 2(n).
// Per KV tile of 64: S=QK^T (mma) -> Sf -> online softmax -> Ps fp16 ->
// O += P V (mma, V transposed in SMEM). Epilogue writes bf16 hi/lo split.
// ---------------------------------------------------------------------------
#define QK_PITCH 136     // halves; Qh/Kh [64][136]
#define VT_PITCH 72      // halves; Vt [128][72], Ps [64][72]
#define SF_PITCH 68      // floats; Sf [64][68]

#define OFF_QH   0
#define OFF_KH   17408
#define OFF_VT   34816
#define OFF_PS   53248
#define OFF_SF   62464
#define OFF_CORR 79872
#define OFF_LROW 80128
#define FA_SMEM  80384

__global__ __launch_bounds__(256) void flash_tc_kernel()
{
    extern __shared__ char sm[];
    __half* Qh = (__half*)(sm + OFF_QH);
    __half* Kh = (__half*)(sm + OFF_KH);
    __half* Vt = (__half*)(sm + OFF_VT);
    __half* Ps = (__half*)(sm + OFF_PS);
    float*  Sf = (float*)(sm + OFF_SF);
    float*  corr_row = (float*)(sm + OFF_CORR);
    float*  lrow     = (float*)(sm + OFF_LROW);

    const int tid  = threadIdx.x;
    const int lane = tid & 31;
    const int w    = tid >> 5;      // 0..7
    const int wm   = w >> 1;        // 0..3 (16 rows each)
    const int wn   = w & 1;         // 0..1
    const int g    = lane >> 2;     // 0..7
    const int tg   = lane & 3;      // 0..3

    const int qtile = blockIdx.x;   // 0..31
    const int h     = blockIdx.y;   // 0..15
    const int b     = blockIdx.z;   // 0..1
    const int kvh   = h / REP;

    // ---- load Q tile (64 x 128 fp16) ----
    const __half* qbase = g_qh + ((size_t)(b * SEQ + qtile * 64)) * HID + h * HD;
#pragma unroll
    for (int it = 0; it < 4; it++) {
        int idx = it * 256 + tid;
        int r  = idx >> 4;
        int d0 = (idx & 15) * 8;
        *(uint4*)(Qh + r * QK_PITCH + d0) =
            *(const uint4*)(qbase + (size_t)r * HID + d0);
    }
    __syncthreads();

    // ---- preload Q fragments (held in regs for all 32 KV tiles) ----
    uint32_t qf[8][4];
    {
        const int r0 = wm * 16 + g;
#pragma unroll
        for (int ks = 0; ks < 8; ks++) {
            const int c0 = ks * 16 + tg * 2;
            qf[ks][0] = *(const uint32_t*)(Qh + r0 * QK_PITCH + c0);
            qf[ks][1] = *(const uint32_t*)(Qh + (r0 + 8) * QK_PITCH + c0);
            qf[ks][2] = *(const uint32_t*)(Qh + r0 * QK_PITCH + c0 + 8);
            qf[ks][3] = *(const uint32_t*)(Qh + (r0 + 8) * QK_PITCH + c0 + 8);
        }
    }

    float m[8], l[8];
#pragma unroll
    for (int i = 0; i < 8; i++) { m[i] = -INFINITY; l[i] = 0.f; }

    float acc_o[8][4];
#pragma unroll
    for (int ni = 0; ni < 8; ni++)
#pragma unroll
        for (int t = 0; t < 4; t++) acc_o[ni][t] = 0.f;

    const __half* kroot = g_kh + (size_t)(b * SEQ) * KVDIM + kvh * HD;
    const __half* vroot = g_vh + (size_t)(b * SEQ) * KVDIM + kvh * HD;

    for (int kt = 0; kt < SEQ / 64; kt++) {
        __syncthreads();   // prev PV readers done before overwrite
        const __half* kbase = kroot + (size_t)(kt * 64) * KVDIM;
        const __half* vbase = vroot + (size_t)(kt * 64) * KVDIM;
        // K tile: [64 kv][128 d]
#pragma unroll
        for (int it = 0; it < 4; it++) {
            int idx = it * 256 + tid;
            int r  = idx >> 4;
            int d0 = (idx & 15) * 8;
            *(uint4*)(Kh + r * QK_PITCH + d0) =
                *(const uint4*)(kbase + (size_t)r * KVDIM + d0);
        }
        // V tile transposed: Vt[d][c] = V[c][d]
#pragma unroll
        for (int it = 0; it < 4; it++) {
            int idx = it * 256 + tid;
            int c  = idx & 63;
            int d0 = (idx >> 6) * 8;
            uint4 raw = *(const uint4*)(vbase + (size_t)c * KVDIM + d0);
            const __half* hv = (const __half*)&raw;
#pragma unroll
            for (int j = 0; j < 8; j++)
                Vt[(d0 + j) * VT_PITCH + c] = hv[j];
        }
        __syncthreads();

        // ---- S = Q K^T : warp tile 16(m) x 32(n) ----
        {
            float acc_s[4][4];
#pragma unroll
            for (int ni = 0; ni < 4; ni++)
#pragma unroll
                for (int t = 0; t < 4; t++) acc_s[ni][t] = 0.f;
#pragma unroll
            for (int ks = 0; ks < 8; ks++) {
                const int c0 = ks * 16 + tg * 2;
#pragma unroll
                for (int ni = 0; ni < 4; ni++) {
                    const int n0 = wn * 32 + ni * 8 + g;
                    uint32_t bb[2];
                    bb[0] = *(const uint32_t*)(Kh + n0 * QK_PITCH + c0);
                    bb[1] = *(const uint32_t*)(Kh + n0 * QK_PITCH + c0 + 8);
                    mma16816_f16(acc_s[ni], qf[ks], bb);
                }
            }
            const int r0 = wm * 16 + g;
#pragma unroll
            for (int ni = 0; ni < 4; ni++) {
                const int col = wn * 32 + ni * 8 + tg * 2;
                *(float2*)(Sf + r0 * SF_PITCH + col) =
                    make_float2(acc_s[ni][0], acc_s[ni][1]);
                *(float2*)(Sf + (r0 + 8) * SF_PITCH + col) =
                    make_float2(acc_s[ni][2], acc_s[ni][3]);
            }
        }
        __syncthreads();

        // ---- online softmax: warp w owns rows w*8 .. w*8+7 ----
#pragma unroll
        for (int i = 0; i < 8; i++) {
            const int r = w * 8 + i;
            float x0 = Sf[r * SF_PITCH + lane];
            float x1 = Sf[r * SF_PITCH + 32 + lane];
            float mx = fmaxf(x0, x1);
#pragma unroll
            for (int off = 16; off > 0; off >>= 1)
                mx = fmaxf(mx, __shfl_xor_sync(0xffffffffu, mx, off));
            float mnew = fmaxf(m[i], mx);
            float corr = __expf(m[i] - mnew);
            float p0 = __expf(x0 - mnew);
            float p1 = __expf(x1 - mnew);
            Ps[r * VT_PITCH + lane]      = __float2half_rn(p0);
            Ps[r * VT_PITCH + 32 + lane] = __float2half_rn(p1);
            float ps = p0 + p1;
#pragma unroll
            for (int off = 16; off > 0; off >>= 1)
                ps += __shfl_xor_sync(0xffffffffu, ps, off);
            l[i] = l[i] * corr + ps;
            m[i] = mnew;
            if (lane == 0) corr_row[r] = corr;
        }
        __syncthreads();

        // ---- O = O*corr + P V : warp tile 16(m) x 64(n) ----
        {
            const int r0 = wm * 16 + g;
            const float c0r = corr_row[r0];
            const float c1r = corr_row[r0 + 8];
#pragma unroll
            for (int ni = 0; ni < 8; ni++) {
                acc_o[ni][0] *= c0r; acc_o[ni][1] *= c0r;
                acc_o[ni][2] *= c1r; acc_o[ni][3] *= c1r;
            }
#pragma unroll
            for (int ks = 0; ks < 4; ks++) {
                const int c0 = ks * 16 + tg * 2;
                uint32_t pa[4];
                pa[0] = *(const uint32_t*)(Ps + r0 * VT_PITCH + c0);
                pa[1] = *(const uint32_t*)(Ps + (r0 + 8) * VT_PITCH + c0);
                pa[2] = *(const uint32_t*)(Ps + r0 * VT_PITCH + c0 + 8);
                pa[3] = *(const uint32_t*)(Ps + (r0 + 8) * VT_PITCH + c0 + 8);
#pragma unroll
                for (int ni = 0; ni < 8; ni++) {
                    const int n0 = wn * 64 + ni * 8 + g;
                    uint32_t bb[2];
                    bb[0] = *(const uint32_t*)(Vt + n0 * VT_PITCH + c0);
                    bb[1] = *(const uint32_t*)(Vt + n0 * VT_PITCH + c0 + 8);
                    mma16816_f16(acc_o[ni], pa, bb);
                }
            }
        }
    }

    // ---- publish l, epilogue: normalize + bf16 hi/lo split write ----
    if (lane == 0) {
#pragma unroll
        for (int i = 0; i < 8; i++) lrow[w * 8 + i] = l[i];
    }
    __syncthreads();

    {
        const int r0 = wm * 16 + g;
        const float inv0 = 1.0f / lrow[r0];
        const float inv1 = 1.0f / lrow[r0 + 8];
        const size_t tok0 = (size_t)(b * SEQ + qtile * 64 + r0);
#pragma unroll
        for (int ni = 0; ni < 8; ni++) {
            const int col = wn * 64 + ni * 8 + tg * 2;
            const size_t base0 = tok0 * HID + h * HD + col;
            const size_t base1 = (tok0 + 8) * HID + h * HD + col;
            float v00 = acc_o[ni][0] * inv0, v01 = acc_o[ni][1] * inv0;
            float v10 = acc_o[ni][2] * inv1, v11 = acc_o[ni][3] * inv1;
            __nv_bfloat16 h00 = __float2bfloat16(v00);
            __nv_bfloat16 h01 = __float2bfloat16(v01);
            __nv_bfloat16 h10 = __float2bfloat16(v10);
            __nv_bfloat16 h11 = __float2bfloat16(v11);
            __nv_bfloat162 hh0; hh0.x = h00; hh0.y = h01;
            __nv_bfloat162 hh1; hh1.x = h10; hh1.y = h11;
            __nv_bfloat162 ll0;
            ll0.x = __float2bfloat16(v00 - __bfloat162float(h00));
            ll0.y = __float2bfloat16(v01 - __bfloat162float(h01));
            __nv_bfloat162 ll1;
            ll1.x = __float2bfloat16(v10 - __bfloat162float(h10));
            ll1.y = __float2bfloat16(v11 - __bfloat162float(h11));
            *(__nv_bfloat162*)(g_aoh + base0) = hh0;
            *(__nv_bfloat162*)(g_aol + base0) = ll0;
            *(__nv_bfloat162*)(g_aoh + base1) = hh1;
            *(__nv_bfloat162*)(g_aol + base1) = ll1;
        }
    }
}

// ---------------------------------------------------------------------------
// kernel_launch
// ---------------------------------------------------------------------------
extern "C" void kernel_launch(void* const* d_in, const int* in_sizes, int n_in,
                              void* d_out, int out_size)
{
    (void)in_sizes; (void)n_in; (void)out_size;
    const float* hidden = (const float*)d_in[0];
    const float* Wq = (const float*)d_in[1];
    const float* bq = (const float*)d_in[2];
    const float* Wk = (const float*)d_in[3];
    const float* bk = (const float*)d_in[4];
    const float* Wv = (const float*)d_in[5];
    const float* bv = (const float*)d_in[6];
    const float* Wo = (const float*)d_in[7];
    const float* bo = (const float*)d_in[8];
    float* out = (float*)d_out;

    __half *qh, *kh, *vh;
    __nv_bfloat16 *ah, *al, *aoh, *aol;
    __nv_bfloat16 *wqh, *wql, *wkh, *wkl, *wvh, *wvl, *woh, *wol;
    cudaGetSymbolAddress((void**)&qh,  g_qh);
    cudaGetSymbolAddress((void**)&kh,  g_kh);
    cudaGetSymbolAddress((void**)&vh,  g_vh);
    cudaGetSymbolAddress((void**)&ah,  g_ah);
    cudaGetSymbolAddress((void**)&al,  g_al);
    cudaGetSymbolAddress((void**)&aoh, g_aoh);
    cudaGetSymbolAddress((void**)&aol, g_aol);
    cudaGetSymbolAddress((void**)&wqh, g_wqh);
    cudaGetSymbolAddress((void**)&wql, g_wql);
    cudaGetSymbolAddress((void**)&wkh, g_wkh);
    cudaGetSymbolAddress((void**)&wkl, g_wkl);
    cudaGetSymbolAddress((void**)&wvh, g_wvh);
    cudaGetSymbolAddress((void**)&wvl, g_wvl);
    cudaGetSymbolAddress((void**)&woh, g_woh);
    cudaGetSymbolAddress((void**)&wol, g_wol);

    static int attr_set = 0;
    if (!attr_set) {
        cudaFuncSetAttribute(flash_tc_kernel,
                             cudaFuncAttributeMaxDynamicSharedMemorySize, FA_SMEM);
        attr_set = 1;
    }

    const float scaling = 0.08838834764831845f;  // 128^-0.5

    // 1) split hidden, transpose+split weights
    split_kernel<<<(BS_ROWS * HID / 8) / 256, 256>>>(hidden, ah, al);
    transpose_split_kernel<<<dim3(HID / 32,   HID / 32), 256>>>(Wq, wqh, wql, HID, HID);
    transpose_split_kernel<<<dim3(KVDIM / 32, HID / 32), 256>>>(Wk, wkh, wkl, HID, KVDIM);
    transpose_split_kernel<<<dim3(KVDIM / 32, HID / 32), 256>>>(Wv, wvh, wvl, HID, KVDIM);
    transpose_split_kernel<<<dim3(HID / 32,   HID / 32), 256>>>(Wo, woh, wol, HID, HID);

    // 2) projections -> fp16 q/k/v
    gemm_mma_kernel<<<dim3(HID / 128,   BS_ROWS / 128), 256>>>(
        ah, al, wqh, wql, bq, nullptr, qh, HID, HID, scaling);
    gemm_mma_kernel<<<dim3(KVDIM / 128, BS_ROWS / 128), 256>>>(
        ah, al, wkh, wkl, bk, nullptr, kh, KVDIM, HID, 1.0f);
    gemm_mma_kernel<<<dim3(KVDIM / 128, BS_ROWS / 128), 256>>>(
        ah, al, wvh, wvl, bv, nullptr, vh, KVDIM, HID, 1.0f);

    // 3) flash attention on tensor cores (writes aoh/aol split directly)
    flash_tc_kernel<<<dim3(SEQ / 64, NH, BATCH), 256, FA_SMEM>>>();

    // 4) O-projection -> fp32 out
    gemm_mma_kernel<<<dim3(HID / 128, BS_ROWS / 128), 256>>>(
        aoh, aol, woh, wol, bo, out, nullptr, HID, HID, 1.0f);
}

// round 5
// speedup vs baseline: 2.6848x; 1.1605x over previous
#include <cuda_runtime.h>
#include <cuda_bf16.h>
#include <cuda_fp16.h>
#include <math.h>
#include <stdint.h>

// ---------------------------------------------------------------------------
// MultiQueryAttention: B=2, S=2048, HIDDEN=2048, NH=16, NKV=2, D=128
// Round 5: cp.async double-buffered projection GEMMs; flash at 2 CTAs/SM.
// ---------------------------------------------------------------------------

#define BATCH      2
#define SEQ        2048
#define HID        2048
#define NH         16
#define NKV        2
#define HD         128
#define KVDIM      (NKV * HD)      // 256
#define BS_ROWS    (BATCH * SEQ)   // 4096
#define REP        (NH / NKV)      // 8

// ---------------- scratch (device globals; no allocation allowed) ----------
__device__ __half g_qh[BS_ROWS * HID];     // q fp16 (pre-scaled)
__device__ __half g_kh[BS_ROWS * KVDIM];   // k fp16
__device__ __half g_vh[BS_ROWS * KVDIM];   // v fp16

__device__ __nv_bfloat16 g_ah [BS_ROWS * HID];   // hidden hi
__device__ __nv_bfloat16 g_al [BS_ROWS * HID];   // hidden lo
__device__ __nv_bfloat16 g_aoh[BS_ROWS * HID];   // attn-out hi (flash epilogue)
__device__ __nv_bfloat16 g_aol[BS_ROWS * HID];   // attn-out lo
__device__ __nv_bfloat16 g_wqh[HID * HID],   g_wql[HID * HID];     // Wq^T
__device__ __nv_bfloat16 g_woh[HID * HID],   g_wol[HID * HID];     // Wo^T
__device__ __nv_bfloat16 g_wkh[KVDIM * HID], g_wkl[KVDIM * HID];   // Wk^T
__device__ __nv_bfloat16 g_wvh[KVDIM * HID], g_wvl[KVDIM * HID];   // Wv^T

// ---------------------------------------------------------------------------
// mma.sync m16n8k16 row.col f32 accum (bf16 and f16 operand flavors)
// ---------------------------------------------------------------------------
static __device__ __forceinline__ void mma16816_bf16(
    float* d, const uint32_t* a, const uint32_t* b)
{
    asm volatile(
        "mma.sync.aligned.m16n8k16.row.col.f32.bf16.bf16.f32 "
        "{%0,%1,%2,%3}, {%4,%5,%6,%7}, {%8,%9}, {%0,%1,%2,%3};"
        : "+f"(d[0]), "+f"(d[1]), "+f"(d[2]), "+f"(d[3])
        : "r"(a[0]), "r"(a[1]), "r"(a[2]), "r"(a[3]), "r"(b[0]), "r"(b[1]));
}
static __device__ __forceinline__ void mma16816_f16(
    float* d, const uint32_t* a, const uint32_t* b)
{
    asm volatile(
        "mma.sync.aligned.m16n8k16.row.col.f32.f16.f16.f32 "
        "{%0,%1,%2,%3}, {%4,%5,%6,%7}, {%8,%9}, {%0,%1,%2,%3};"
        : "+f"(d[0]), "+f"(d[1]), "+f"(d[2]), "+f"(d[3])
        : "r"(a[0]), "r"(a[1]), "r"(a[2]), "r"(a[3]), "r"(b[0]), "r"(b[1]));
}

static __device__ __forceinline__ void cp_async16(void* sptr, const void* gptr) {
    uint32_t s = (uint32_t)__cvta_generic_to_shared(sptr);
    asm volatile("cp.async.cg.shared.global [%0], [%1], 16;"
                 :: "r"(s), "l"(gptr) : "memory");
}
#define CP_COMMIT() asm volatile("cp.async.commit_group;" ::: "memory")
#define CP_WAIT0()  asm volatile("cp.async.wait_group 0;" ::: "memory")

// ---------------------------------------------------------------------------
// Projection GEMM (bf16 hi/lo x3): C[M,N] = (A@Bt^T + bias) * alpha
// cp.async 2-stage pipeline. Dynamic SMEM: 2 stages x 4 operands x 128x40.
// ---------------------------------------------------------------------------
#define PITCH    40
#define OP_BYTES (128 * PITCH * 2)          // 10240
#define STAGE_SZ (4 * OP_BYTES)             // 40960
#define GEMM_SMEM (2 * STAGE_SZ)            // 81920

__global__ __launch_bounds__(256, 2) void gemm_mma_kernel(
    const __nv_bfloat16* __restrict__ Ahi, const __nv_bfloat16* __restrict__ Alo,
    const __nv_bfloat16* __restrict__ Bhi, const __nv_bfloat16* __restrict__ Blo,
    const float* __restrict__ bias, float* __restrict__ C,
    __half* __restrict__ Ch,
    int N, int K, float alpha)
{
    extern __shared__ char gsm[];

    const int tid    = threadIdx.x;
    const int lane   = tid & 31;
    const int wid    = tid >> 5;
    const int warp_m = wid >> 2;    // 0..1
    const int warp_n = wid & 3;     // 0..3
    const int g      = lane >> 2;   // 0..7
    const int tg     = lane & 3;    // 0..3

    const int blockRow = blockIdx.y * 128;
    const int blockCol = blockIdx.x * 128;

    float acc[4][4][4];
#pragma unroll
    for (int mi = 0; mi < 4; mi++)
#pragma unroll
        for (int ni = 0; ni < 4; ni++)
#pragma unroll
            for (int t = 0; t < 4; t++) acc[mi][ni][t] = 0.f;

    const int nch = K / 32;

    // issue loads for chunk c into stage stg
    auto issue = [&](int c, int stg) {
        char* base = gsm + stg * STAGE_SZ;
#pragma unroll
        for (int it = 0; it < 2; it++) {
            int idx = it * 256 + tid;
            int m  = idx >> 2;
            int kq = idx & 3;
            size_t ga = (size_t)(blockRow + m) * K + c * 32 + kq * 8;
            size_t gb = (size_t)(blockCol + m) * K + c * 32 + kq * 8;
            int so = (m * PITCH + kq * 8) * 2;
            cp_async16(base + 0 * OP_BYTES + so, Ahi + ga);
            cp_async16(base + 1 * OP_BYTES + so, Alo + ga);
            cp_async16(base + 2 * OP_BYTES + so, Bhi + gb);
            cp_async16(base + 3 * OP_BYTES + so, Blo + gb);
        }
        CP_COMMIT();
    };

    issue(0, 0);

    for (int c = 0; c < nch; c++) {
        const int b = c & 1;
        CP_WAIT0();
        __syncthreads();
        if (c + 1 < nch) issue(c + 1, 1 - b);

        const __nv_bfloat16* As_hi = (const __nv_bfloat16*)(gsm + b * STAGE_SZ);
        const __nv_bfloat16* As_lo = (const __nv_bfloat16*)(gsm + b * STAGE_SZ + OP_BYTES);
        const __nv_bfloat16* Bs_hi = (const __nv_bfloat16*)(gsm + b * STAGE_SZ + 2 * OP_BYTES);
        const __nv_bfloat16* Bs_lo = (const __nv_bfloat16*)(gsm + b * STAGE_SZ + 3 * OP_BYTES);

#pragma unroll
        for (int ks = 0; ks < 2; ks++) {
            const int c0 = ks * 16 + tg * 2;
            uint32_t ah[4][4], al[4][4];
#pragma unroll
            for (int mi = 0; mi < 4; mi++) {
                int r0 = warp_m * 64 + mi * 16 + g;
                ah[mi][0] = *(const uint32_t*)(As_hi + r0 * PITCH + c0);
                ah[mi][1] = *(const uint32_t*)(As_hi + (r0 + 8) * PITCH + c0);
                ah[mi][2] = *(const uint32_t*)(As_hi + r0 * PITCH + c0 + 8);
                ah[mi][3] = *(const uint32_t*)(As_hi + (r0 + 8) * PITCH + c0 + 8);
                al[mi][0] = *(const uint32_t*)(As_lo + r0 * PITCH + c0);
                al[mi][1] = *(const uint32_t*)(As_lo + (r0 + 8) * PITCH + c0);
                al[mi][2] = *(const uint32_t*)(As_lo + r0 * PITCH + c0 + 8);
                al[mi][3] = *(const uint32_t*)(As_lo + (r0 + 8) * PITCH + c0 + 8);
            }
#pragma unroll
            for (int ni = 0; ni < 4; ni++) {
                int n0 = warp_n * 32 + ni * 8 + g;
                uint32_t bh[2], bl[2];
                bh[0] = *(const uint32_t*)(Bs_hi + n0 * PITCH + c0);
                bh[1] = *(const uint32_t*)(Bs_hi + n0 * PITCH + c0 + 8);
                bl[0] = *(const uint32_t*)(Bs_lo + n0 * PITCH + c0);
                bl[1] = *(const uint32_t*)(Bs_lo + n0 * PITCH + c0 + 8);
#pragma unroll
                for (int mi = 0; mi < 4; mi++) {
                    mma16816_bf16(acc[mi][ni], ah[mi], bh);
                    mma16816_bf16(acc[mi][ni], ah[mi], bl);
                    mma16816_bf16(acc[mi][ni], al[mi], bh);
                }
            }
        }
        __syncthreads();
    }

#pragma unroll
    for (int mi = 0; mi < 4; mi++) {
#pragma unroll
        for (int ni = 0; ni < 4; ni++) {
            int row0 = blockRow + warp_m * 64 + mi * 16 + g;
            int col  = blockCol + warp_n * 32 + ni * 8 + tg * 2;
            float2 b2 = *(const float2*)(bias + col);
            float2 o0, o1;
            o0.x = (acc[mi][ni][0] + b2.x) * alpha;
            o0.y = (acc[mi][ni][1] + b2.y) * alpha;
            o1.x = (acc[mi][ni][2] + b2.x) * alpha;
            o1.y = (acc[mi][ni][3] + b2.y) * alpha;
            if (C) {
                *(float2*)(C + (size_t)row0 * N + col)       = o0;
                *(float2*)(C + (size_t)(row0 + 8) * N + col) = o1;
            }
            if (Ch) {
                *(__half2*)(Ch + (size_t)row0 * N + col) =
                    __floats2half2_rn(o0.x, o0.y);
                *(__half2*)(Ch + (size_t)(row0 + 8) * N + col) =
                    __floats2half2_rn(o1.x, o1.y);
            }
        }
    }
}

// ---------------------------------------------------------------------------
// split / transpose_split prep kernels (unchanged)
// ---------------------------------------------------------------------------
__global__ __launch_bounds__(256) void split_kernel(
    const float* __restrict__ X, __nv_bfloat16* __restrict__ hi,
    __nv_bfloat16* __restrict__ lo)
{
    size_t base = ((size_t)blockIdx.x * 256 + threadIdx.x) * 8;
    float4 a = *(const float4*)(X + base);
    float4 b = *(const float4*)(X + base + 4);
    float x[8] = {a.x, a.y, a.z, a.w, b.x, b.y, b.z, b.w};
    __nv_bfloat16 h[8], l[8];
#pragma unroll
    for (int j = 0; j < 8; j++) {
        h[j] = __float2bfloat16(x[j]);
        l[j] = __float2bfloat16(x[j] - __bfloat162float(h[j]));
    }
    *(uint4*)(hi + base) = *(uint4*)h;
    *(uint4*)(lo + base) = *(uint4*)l;
}

__global__ __launch_bounds__(256) void transpose_split_kernel(
    const float* __restrict__ W, __nv_bfloat16* __restrict__ hiT,
    __nv_bfloat16* __restrict__ loT, int K, int N)
{
    __shared__ float tile[32][33];
    const int n0 = blockIdx.x * 32;
    const int k0 = blockIdx.y * 32;
    const int tx = threadIdx.x & 31;
    const int ty = threadIdx.x >> 5;
#pragma unroll
    for (int i = 0; i < 4; i++)
        tile[ty + i * 8][tx] = W[(size_t)(k0 + ty + i * 8) * N + n0 + tx];
    __syncthreads();
#pragma unroll
    for (int i = 0; i < 4; i++) {
        int r = ty + i * 8;
        float x = tile[tx][r];
        __nv_bfloat16 h = __float2bfloat16(x);
        __nv_bfloat16 l = __float2bfloat16(x - __bfloat162float(h));
        size_t o = (size_t)(n0 + r) * K + k0 + tx;
        hiT[o] = h;
        loT[o] = l;
    }
}

// ---------------------------------------------------------------------------
// Flash attention on tensor cores (fp16 operands, fp32 accum). 2 CTAs/SM.
// ---------------------------------------------------------------------------
#define QK_PITCH 136     // halves; Qh/Kh [64][136]
#define VT_PITCH 72      // halves; Vt [128][72], Ps [64][72]
#define SF_PITCH 68      // floats; Sf [64][68]

#define OFF_QH   0
#define OFF_KH   17408
#define OFF_VT   34816
#define OFF_PS   53248
#define OFF_SF   62464
#define OFF_CORR 79872
#define OFF_LROW 80128
#define FA_SMEM  80384

__global__ __launch_bounds__(256, 2) void flash_tc_kernel()
{
    extern __shared__ char sm[];
    __half* Qh = (__half*)(sm + OFF_QH);
    __half* Kh = (__half*)(sm + OFF_KH);
    __half* Vt = (__half*)(sm + OFF_VT);
    __half* Ps = (__half*)(sm + OFF_PS);
    float*  Sf = (float*)(sm + OFF_SF);
    float*  corr_row = (float*)(sm + OFF_CORR);
    float*  lrow     = (float*)(sm + OFF_LROW);

    const int tid  = threadIdx.x;
    const int lane = tid & 31;
    const int w    = tid >> 5;      // 0..7
    const int wm   = w >> 1;        // 0..3 (16 rows each)
    const int wn   = w & 1;         // 0..1
    const int g    = lane >> 2;     // 0..7
    const int tg   = lane & 3;      // 0..3

    const int qtile = blockIdx.x;   // 0..31
    const int h     = blockIdx.y;   // 0..15
    const int b     = blockIdx.z;   // 0..1
    const int kvh   = h / REP;

    const __half* qbase = g_qh + ((size_t)(b * SEQ + qtile * 64)) * HID + h * HD;
#pragma unroll
    for (int it = 0; it < 4; it++) {
        int idx = it * 256 + tid;
        int r  = idx >> 4;
        int d0 = (idx & 15) * 8;
        *(uint4*)(Qh + r * QK_PITCH + d0) =
            *(const uint4*)(qbase + (size_t)r * HID + d0);
    }
    __syncthreads();

    uint32_t qf[8][4];
    {
        const int r0 = wm * 16 + g;
#pragma unroll
        for (int ks = 0; ks < 8; ks++) {
            const int c0 = ks * 16 + tg * 2;
            qf[ks][0] = *(const uint32_t*)(Qh + r0 * QK_PITCH + c0);
            qf[ks][1] = *(const uint32_t*)(Qh + (r0 + 8) * QK_PITCH + c0);
            qf[ks][2] = *(const uint32_t*)(Qh + r0 * QK_PITCH + c0 + 8);
            qf[ks][3] = *(const uint32_t*)(Qh + (r0 + 8) * QK_PITCH + c0 + 8);
        }
    }

    float m[8], l[8];
#pragma unroll
    for (int i = 0; i < 8; i++) { m[i] = -INFINITY; l[i] = 0.f; }

    float acc_o[8][4];
#pragma unroll
    for (int ni = 0; ni < 8; ni++)
#pragma unroll
        for (int t = 0; t < 4; t++) acc_o[ni][t] = 0.f;

    const __half* kroot = g_kh + (size_t)(b * SEQ) * KVDIM + kvh * HD;
    const __half* vroot = g_vh + (size_t)(b * SEQ) * KVDIM + kvh * HD;

    for (int kt = 0; kt < SEQ / 64; kt++) {
        __syncthreads();
        const __half* kbase = kroot + (size_t)(kt * 64) * KVDIM;
        const __half* vbase = vroot + (size_t)(kt * 64) * KVDIM;
#pragma unroll
        for (int it = 0; it < 4; it++) {
            int idx = it * 256 + tid;
            int r  = idx >> 4;
            int d0 = (idx & 15) * 8;
            *(uint4*)(Kh + r * QK_PITCH + d0) =
                *(const uint4*)(kbase + (size_t)r * KVDIM + d0);
        }
#pragma unroll
        for (int it = 0; it < 4; it++) {
            int idx = it * 256 + tid;
            int c  = idx & 63;
            int d0 = (idx >> 6) * 8;
            uint4 raw = *(const uint4*)(vbase + (size_t)c * KVDIM + d0);
            const __half* hv = (const __half*)&raw;
#pragma unroll
            for (int j = 0; j < 8; j++)
                Vt[(d0 + j) * VT_PITCH + c] = hv[j];
        }
        __syncthreads();

        // ---- S = Q K^T ----
        {
            float acc_s[4][4];
#pragma unroll
            for (int ni = 0; ni < 4; ni++)
#pragma unroll
                for (int t = 0; t < 4; t++) acc_s[ni][t] = 0.f;
#pragma unroll
            for (int ks = 0; ks < 8; ks++) {
                const int c0 = ks * 16 + tg * 2;
#pragma unroll
                for (int ni = 0; ni < 4; ni++) {
                    const int n0 = wn * 32 + ni * 8 + g;
                    uint32_t bb[2];
                    bb[0] = *(const uint32_t*)(Kh + n0 * QK_PITCH + c0);
                    bb[1] = *(const uint32_t*)(Kh + n0 * QK_PITCH + c0 + 8);
                    mma16816_f16(acc_s[ni], qf[ks], bb);
                }
            }
            const int r0 = wm * 16 + g;
#pragma unroll
            for (int ni = 0; ni < 4; ni++) {
                const int col = wn * 32 + ni * 8 + tg * 2;
                *(float2*)(Sf + r0 * SF_PITCH + col) =
                    make_float2(acc_s[ni][0], acc_s[ni][1]);
                *(float2*)(Sf + (r0 + 8) * SF_PITCH + col) =
                    make_float2(acc_s[ni][2], acc_s[ni][3]);
            }
        }
        __syncthreads();

        // ---- online softmax ----
#pragma unroll
        for (int i = 0; i < 8; i++) {
            const int r = w * 8 + i;
            float x0 = Sf[r * SF_PITCH + lane];
            float x1 = Sf[r * SF_PITCH + 32 + lane];
            float mx = fmaxf(x0, x1);
#pragma unroll
            for (int off = 16; off > 0; off >>= 1)
                mx = fmaxf(mx, __shfl_xor_sync(0xffffffffu, mx, off));
            float mnew = fmaxf(m[i], mx);
            float corr = __expf(m[i] - mnew);
            float p0 = __expf(x0 - mnew);
            float p1 = __expf(x1 - mnew);
            Ps[r * VT_PITCH + lane]      = __float2half_rn(p0);
            Ps[r * VT_PITCH + 32 + lane] = __float2half_rn(p1);
            float ps = p0 + p1;
#pragma unroll
            for (int off = 16; off > 0; off >>= 1)
                ps += __shfl_xor_sync(0xffffffffu, ps, off);
            l[i] = l[i] * corr + ps;
            m[i] = mnew;
            if (lane == 0) corr_row[r] = corr;
        }
        __syncthreads();

        // ---- O = O*corr + P V ----
        {
            const int r0 = wm * 16 + g;
            const float c0r = corr_row[r0];
            const float c1r = corr_row[r0 + 8];
#pragma unroll
            for (int ni = 0; ni < 8; ni++) {
                acc_o[ni][0] *= c0r; acc_o[ni][1] *= c0r;
                acc_o[ni][2] *= c1r; acc_o[ni][3] *= c1r;
            }
#pragma unroll
            for (int ks = 0; ks < 4; ks++) {
                const int c0 = ks * 16 + tg * 2;
                uint32_t pa[4];
                pa[0] = *(const uint32_t*)(Ps + r0 * VT_PITCH + c0);
                pa[1] = *(const uint32_t*)(Ps + (r0 + 8) * VT_PITCH + c0);
                pa[2] = *(const uint32_t*)(Ps + r0 * VT_PITCH + c0 + 8);
                pa[3] = *(const uint32_t*)(Ps + (r0 + 8) * VT_PITCH + c0 + 8);
#pragma unroll
                for (int ni = 0; ni < 8; ni++) {
                    const int n0 = wn * 64 + ni * 8 + g;
                    uint32_t bb[2];
                    bb[0] = *(const uint32_t*)(Vt + n0 * VT_PITCH + c0);
                    bb[1] = *(const uint32_t*)(Vt + n0 * VT_PITCH + c0 + 8);
                    mma16816_f16(acc_o[ni], pa, bb);
                }
            }
        }
    }

    if (lane == 0) {
#pragma unroll
        for (int i = 0; i < 8; i++) lrow[w * 8 + i] = l[i];
    }
    __syncthreads();

    {
        const int r0 = wm * 16 + g;
        const float inv0 = 1.0f / lrow[r0];
        const float inv1 = 1.0f / lrow[r0 + 8];
        const size_t tok0 = (size_t)(b * SEQ + qtile * 64 + r0);
#pragma unroll
        for (int ni = 0; ni < 8; ni++) {
            const int col = wn * 64 + ni * 8 + tg * 2;
            const size_t base0 = tok0 * HID + h * HD + col;
            const size_t base1 = (tok0 + 8) * HID + h * HD + col;
            float v00 = acc_o[ni][0] * inv0, v01 = acc_o[ni][1] * inv0;
            float v10 = acc_o[ni][2] * inv1, v11 = acc_o[ni][3] * inv1;
            __nv_bfloat16 h00 = __float2bfloat16(v00);
            __nv_bfloat16 h01 = __float2bfloat16(v01);
            __nv_bfloat16 h10 = __float2bfloat16(v10);
            __nv_bfloat16 h11 = __float2bfloat16(v11);
            __nv_bfloat162 hh0; hh0.x = h00; hh0.y = h01;
            __nv_bfloat162 hh1; hh1.x = h10; hh1.y = h11;
            __nv_bfloat162 ll0;
            ll0.x = __float2bfloat16(v00 - __bfloat162float(h00));
            ll0.y = __float2bfloat16(v01 - __bfloat162float(h01));
            __nv_bfloat162 ll1;
            ll1.x = __float2bfloat16(v10 - __bfloat162float(h10));
            ll1.y = __float2bfloat16(v11 - __bfloat162float(h11));
            *(__nv_bfloat162*)(g_aoh + base0) = hh0;
            *(__nv_bfloat162*)(g_aol + base0) = ll0;
            *(__nv_bfloat162*)(g_aoh + base1) = hh1;
            *(__nv_bfloat162*)(g_aol + base1) = ll1;
        }
    }
}

// ---------------------------------------------------------------------------
// kernel_launch
// ---------------------------------------------------------------------------
extern "C" void kernel_launch(void* const* d_in, const int* in_sizes, int n_in,
                              void* d_out, int out_size)
{
    (void)in_sizes; (void)n_in; (void)out_size;
    const float* hidden = (const float*)d_in[0];
    const float* Wq = (const float*)d_in[1];
    const float* bq = (const float*)d_in[2];
    const float* Wk = (const float*)d_in[3];
    const float* bk = (const float*)d_in[4];
    const float* Wv = (const float*)d_in[5];
    const float* bv = (const float*)d_in[6];
    const float* Wo = (const float*)d_in[7];
    const float* bo = (const float*)d_in[8];
    float* out = (float*)d_out;

    __half *qh, *kh, *vh;
    __nv_bfloat16 *ah, *al, *aoh, *aol;
    __nv_bfloat16 *wqh, *wql, *wkh, *wkl, *wvh, *wvl, *woh, *wol;
    cudaGetSymbolAddress((void**)&qh,  g_qh);
    cudaGetSymbolAddress((void**)&kh,  g_kh);
    cudaGetSymbolAddress((void**)&vh,  g_vh);
    cudaGetSymbolAddress((void**)&ah,  g_ah);
    cudaGetSymbolAddress((void**)&al,  g_al);
    cudaGetSymbolAddress((void**)&aoh, g_aoh);
    cudaGetSymbolAddress((void**)&aol, g_aol);
    cudaGetSymbolAddress((void**)&wqh, g_wqh);
    cudaGetSymbolAddress((void**)&wql, g_wql);
    cudaGetSymbolAddress((void**)&wkh, g_wkh);
    cudaGetSymbolAddress((void**)&wkl, g_wkl);
    cudaGetSymbolAddress((void**)&wvh, g_wvh);
    cudaGetSymbolAddress((void**)&wvl, g_wvl);
    cudaGetSymbolAddress((void**)&woh, g_woh);
    cudaGetSymbolAddress((void**)&wol, g_wol);

    static int attr_set = 0;
    if (!attr_set) {
        cudaFuncSetAttribute(flash_tc_kernel,
                             cudaFuncAttributeMaxDynamicSharedMemorySize, FA_SMEM);
        cudaFuncSetAttribute(gemm_mma_kernel,
                             cudaFuncAttributeMaxDynamicSharedMemorySize, GEMM_SMEM);
        attr_set = 1;
    }

    const float scaling = 0.08838834764831845f;  // 128^-0.5

    // 1) split hidden, transpose+split weights
    split_kernel<<<(BS_ROWS * HID / 8) / 256, 256>>>(hidden, ah, al);
    transpose_split_kernel<<<dim3(HID / 32,   HID / 32), 256>>>(Wq, wqh, wql, HID, HID);
    transpose_split_kernel<<<dim3(KVDIM / 32, HID / 32), 256>>>(Wk, wkh, wkl, HID, KVDIM);
    transpose_split_kernel<<<dim3(KVDIM / 32, HID / 32), 256>>>(Wv, wvh, wvl, HID, KVDIM);
    transpose_split_kernel<<<dim3(HID / 32,   HID / 32), 256>>>(Wo, woh, wol, HID, HID);

    // 2) projections -> fp16 q/k/v
    gemm_mma_kernel<<<dim3(HID / 128,   BS_ROWS / 128), 256, GEMM_SMEM>>>(
        ah, al, wqh, wql, bq, nullptr, qh, HID, HID, scaling);
    gemm_mma_kernel<<<dim3(KVDIM / 128, BS_ROWS / 128), 256, GEMM_SMEM>>>(
        ah, al, wkh, wkl, bk, nullptr, kh, KVDIM, HID, 1.0f);
    gemm_mma_kernel<<<dim3(KVDIM / 128, BS_ROWS / 128), 256, GEMM_SMEM>>>(
        ah, al, wvh, wvl, bv, nullptr, vh, KVDIM, HID, 1.0f);

    // 3) flash attention on tensor cores (writes aoh/aol split directly)
    flash_tc_kernel<<<dim3(SEQ / 64, NH, BATCH), 256, FA_SMEM>>>();

    // 4) O-projection -> fp32 out
    gemm_mma_kernel<<<dim3(HID / 128, BS_ROWS / 128), 256, GEMM_SMEM>>>(
        aoh, aol, woh, wol, bo, out, nullptr, HID, HID, 1.0f);
}

// round 6
// speedup vs baseline: 4.3868x; 1.6339x over previous
#include <cuda_runtime.h>
#include <cuda_bf16.h>
#include <cuda_fp16.h>
#include <math.h>
#include <stdint.h>

// ---------------------------------------------------------------------------
// MultiQueryAttention: B=2, S=2048, HIDDEN=2048, NH=16, NKV=2, D=128
// Round 6: single-fp16 GEMMs (no hi/lo split), fused QKV projection,
//          fp16 flash attention, fp16 O-proj input.
// ---------------------------------------------------------------------------

#define BATCH      2
#define SEQ        2048
#define HID        2048
#define NH         16
#define NKV        2
#define HD         128
#define KVDIM      (NKV * HD)          // 256
#define QKVS       (HID + 2 * KVDIM)   // 2560 packed qkv width
#define BS_ROWS    (BATCH * SEQ)       // 4096
#define REP        (NH / NKV)          // 8

// ---------------- scratch (device globals; no allocation allowed) ----------
__device__ __half g_ah  [BS_ROWS * HID];    // hidden fp16
__device__ __half g_qkv [BS_ROWS * QKVS];   // packed q|k|v fp16 (q pre-scaled)
__device__ __half g_ao  [BS_ROWS * HID];    // attention out fp16
__device__ __half g_wt  [QKVS * HID];       // packed Wqkv^T fp16 (Wq pre-scaled)
__device__ __half g_wo_t[HID * HID];        // Wo^T fp16
__device__ float  g_bias[QKVS];             // packed bias (bq pre-scaled)

// ---------------------------------------------------------------------------
// mma.sync m16n8k16 row.col f32.f16.f16.f32
// ---------------------------------------------------------------------------
static __device__ __forceinline__ void mma16816_f16(
    float* d, const uint32_t* a, const uint32_t* b)
{
    asm volatile(
        "mma.sync.aligned.m16n8k16.row.col.f32.f16.f16.f32 "
        "{%0,%1,%2,%3}, {%4,%5,%6,%7}, {%8,%9}, {%0,%1,%2,%3};"
        : "+f"(d[0]), "+f"(d[1]), "+f"(d[2]), "+f"(d[3])
        : "r"(a[0]), "r"(a[1]), "r"(a[2]), "r"(a[3]), "r"(b[0]), "r"(b[1]));
}

static __device__ __forceinline__ void cp_async16(void* sptr, const void* gptr) {
    uint32_t s = (uint32_t)__cvta_generic_to_shared(sptr);
    asm volatile("cp.async.cg.shared.global [%0], [%1], 16;"
                 :: "r"(s), "l"(gptr) : "memory");
}
#define CP_COMMIT() asm volatile("cp.async.commit_group;" ::: "memory")
#define CP_WAIT0()  asm volatile("cp.async.wait_group 0;" ::: "memory")

// ---------------------------------------------------------------------------
// fp16 GEMM: C[M,N] = A[M,K] @ Bt[N,K]^T + bias[N]   (fp32 accum)
// CTA 128x128, BK=64, cp.async 2-stage. 8 warps 2x4, warp tile 64x32.
// Writes fp32 C and/or fp16 Ch.
// ---------------------------------------------------------------------------
#define PITCH 72
#define BK    64
#define OPB   (128 * PITCH * 2)    // 18432 bytes per operand tile
#define STG   (2 * OPB)            // 36864 per stage
#define GEMM_SMEM (2 * STG)        // 73728

__global__ __launch_bounds__(256, 2) void gemm_h_kernel(
    const __half* __restrict__ A, const __half* __restrict__ Bt,
    const float* __restrict__ bias, float* __restrict__ C,
    __half* __restrict__ Ch, int N, int K)
{
    extern __shared__ char gsm[];

    const int tid    = threadIdx.x;
    const int lane   = tid & 31;
    const int wid    = tid >> 5;
    const int warp_m = wid >> 2;    // 0..1
    const int warp_n = wid & 3;     // 0..3
    const int g      = lane >> 2;   // 0..7
    const int tg     = lane & 3;    // 0..3

    const int blockRow = blockIdx.y * 128;
    const int blockCol = blockIdx.x * 128;

    float acc[4][4][4];
#pragma unroll
    for (int mi = 0; mi < 4; mi++)
#pragma unroll
        for (int ni = 0; ni < 4; ni++)
#pragma unroll
            for (int t = 0; t < 4; t++) acc[mi][ni][t] = 0.f;

    const int nch = K / BK;   // 32

    auto issue = [&](int c, int stg) {
        char* base = gsm + stg * STG;
#pragma unroll
        for (int it = 0; it < 4; it++) {
            int idx = it * 256 + tid;
            int m  = idx >> 3;     // 0..127
            int kq = idx & 7;      // 0..7 (x8 halves = 16B)
            int so = (m * PITCH + kq * 8) * 2;
            cp_async16(base + so,
                       A + (size_t)(blockRow + m) * K + c * BK + kq * 8);
            cp_async16(base + OPB + so,
                       Bt + (size_t)(blockCol + m) * K + c * BK + kq * 8);
        }
        CP_COMMIT();
    };

    issue(0, 0);

    for (int c = 0; c < nch; c++) {
        const int b = c & 1;
        CP_WAIT0();
        __syncthreads();
        if (c + 1 < nch) issue(c + 1, 1 - b);

        const __half* As = (const __half*)(gsm + b * STG);
        const __half* Bs = (const __half*)(gsm + b * STG + OPB);

#pragma unroll
        for (int ks = 0; ks < 4; ks++) {
            const int c0 = ks * 16 + tg * 2;
            uint32_t av[4][4];
#pragma unroll
            for (int mi = 0; mi < 4; mi++) {
                int r0 = warp_m * 64 + mi * 16 + g;
                av[mi][0] = *(const uint32_t*)(As + r0 * PITCH + c0);
                av[mi][1] = *(const uint32_t*)(As + (r0 + 8) * PITCH + c0);
                av[mi][2] = *(const uint32_t*)(As + r0 * PITCH + c0 + 8);
                av[mi][3] = *(const uint32_t*)(As + (r0 + 8) * PITCH + c0 + 8);
            }
#pragma unroll
            for (int ni = 0; ni < 4; ni++) {
                int n0 = warp_n * 32 + ni * 8 + g;
                uint32_t bb[2];
                bb[0] = *(const uint32_t*)(Bs + n0 * PITCH + c0);
                bb[1] = *(const uint32_t*)(Bs + n0 * PITCH + c0 + 8);
#pragma unroll
                for (int mi = 0; mi < 4; mi++)
                    mma16816_f16(acc[mi][ni], av[mi], bb);
            }
        }
        __syncthreads();
    }

#pragma unroll
    for (int mi = 0; mi < 4; mi++) {
#pragma unroll
        for (int ni = 0; ni < 4; ni++) {
            int row0 = blockRow + warp_m * 64 + mi * 16 + g;
            int col  = blockCol + warp_n * 32 + ni * 8 + tg * 2;
            float2 b2 = *(const float2*)(bias + col);
            float2 o0, o1;
            o0.x = acc[mi][ni][0] + b2.x;
            o0.y = acc[mi][ni][1] + b2.y;
            o1.x = acc[mi][ni][2] + b2.x;
            o1.y = acc[mi][ni][3] + b2.y;
            if (C) {
                *(float2*)(C + (size_t)row0 * N + col)       = o0;
                *(float2*)(C + (size_t)(row0 + 8) * N + col) = o1;
            }
            if (Ch) {
                *(__half2*)(Ch + (size_t)row0 * N + col) =
                    __floats2half2_rn(o0.x, o0.y);
                *(__half2*)(Ch + (size_t)(row0 + 8) * N + col) =
                    __floats2half2_rn(o1.x, o1.y);
            }
        }
    }
}

// ---------------------------------------------------------------------------
// prep kernels
// ---------------------------------------------------------------------------
__global__ __launch_bounds__(256) void convert_h_kernel(
    const float* __restrict__ X, __half* __restrict__ Y)
{
    size_t base = ((size_t)blockIdx.x * 256 + threadIdx.x) * 8;
    float4 a = *(const float4*)(X + base);
    float4 b = *(const float4*)(X + base + 4);
    __half h[8];
    h[0] = __float2half_rn(a.x); h[1] = __float2half_rn(a.y);
    h[2] = __float2half_rn(a.z); h[3] = __float2half_rn(a.w);
    h[4] = __float2half_rn(b.x); h[5] = __float2half_rn(b.y);
    h[6] = __float2half_rn(b.z); h[7] = __float2half_rn(b.w);
    *(uint4*)(Y + base) = *(uint4*)h;
}

// W[K,N] fp32 -> T[(rowoff+n)*K + k] fp16, scaled
__global__ __launch_bounds__(256) void transpose_h_kernel(
    const float* __restrict__ W, __half* __restrict__ T,
    int K, int N, int rowoff, float scale)
{
    __shared__ float tile[32][33];
    const int n0 = blockIdx.x * 32;
    const int k0 = blockIdx.y * 32;
    const int tx = threadIdx.x & 31;
    const int ty = threadIdx.x >> 5;
#pragma unroll
    for (int i = 0; i < 4; i++)
        tile[ty + i * 8][tx] = W[(size_t)(k0 + ty + i * 8) * N + n0 + tx];
    __syncthreads();
#pragma unroll
    for (int i = 0; i < 4; i++) {
        int r = ty + i * 8;
        T[(size_t)(rowoff + n0 + r) * K + k0 + tx] =
            __float2half_rn(tile[tx][r] * scale);
    }
}

__global__ __launch_bounds__(256) void bias_pack_kernel(
    const float* __restrict__ bq, const float* __restrict__ bk,
    const float* __restrict__ bv, float scale)
{
    int i = blockIdx.x * 256 + threadIdx.x;
    if (i < HID)            g_bias[i] = bq[i] * scale;
    else if (i < HID + KVDIM) g_bias[i] = bk[i - HID];
    else if (i < QKVS)      g_bias[i] = bv[i - HID - KVDIM];
}

// ---------------------------------------------------------------------------
// Flash attention on tensor cores (fp16 operands, fp32 accum). 2 CTAs/SM.
// Reads packed g_qkv (stride QKVS); writes fp16 g_ao.
// ---------------------------------------------------------------------------
#define QK_PITCH 136     // halves; Qh/Kh [64][136]
#define VT_PITCH 72      // halves; Vt [128][72], Ps [64][72]
#define SF_PITCH 68      // floats; Sf [64][68]

#define OFF_QH   0
#define OFF_KH   17408
#define OFF_VT   34816
#define OFF_PS   53248
#define OFF_SF   62464
#define OFF_CORR 79872
#define OFF_LROW 80128
#define FA_SMEM  80384

__global__ __launch_bounds__(256, 2) void flash_tc_kernel()
{
    extern __shared__ char sm[];
    __half* Qh = (__half*)(sm + OFF_QH);
    __half* Kh = (__half*)(sm + OFF_KH);
    __half* Vt = (__half*)(sm + OFF_VT);
    __half* Ps = (__half*)(sm + OFF_PS);
    float*  Sf = (float*)(sm + OFF_SF);
    float*  corr_row = (float*)(sm + OFF_CORR);
    float*  lrow     = (float*)(sm + OFF_LROW);

    const int tid  = threadIdx.x;
    const int lane = tid & 31;
    const int w    = tid >> 5;      // 0..7
    const int wm   = w >> 1;        // 0..3
    const int wn   = w & 1;         // 0..1
    const int g    = lane >> 2;     // 0..7
    const int tg   = lane & 3;      // 0..3

    const int qtile = blockIdx.x;   // 0..31
    const int h     = blockIdx.y;   // 0..15
    const int b     = blockIdx.z;   // 0..1
    const int kvh   = h / REP;      // 0..1

    const __half* qbase = g_qkv + (size_t)(b * SEQ + qtile * 64) * QKVS + h * HD;
#pragma unroll
    for (int it = 0; it < 4; it++) {
        int idx = it * 256 + tid;
        int r  = idx >> 4;
        int d0 = (idx & 15) * 8;
        *(uint4*)(Qh + r * QK_PITCH + d0) =
            *(const uint4*)(qbase + (size_t)r * QKVS + d0);
    }
    __syncthreads();

    uint32_t qf[8][4];
    {
        const int r0 = wm * 16 + g;
#pragma unroll
        for (int ks = 0; ks < 8; ks++) {
            const int c0 = ks * 16 + tg * 2;
            qf[ks][0] = *(const uint32_t*)(Qh + r0 * QK_PITCH + c0);
            qf[ks][1] = *(const uint32_t*)(Qh + (r0 + 8) * QK_PITCH + c0);
            qf[ks][2] = *(const uint32_t*)(Qh + r0 * QK_PITCH + c0 + 8);
            qf[ks][3] = *(const uint32_t*)(Qh + (r0 + 8) * QK_PITCH + c0 + 8);
        }
    }

    float m[8], l[8];
#pragma unroll
    for (int i = 0; i < 8; i++) { m[i] = -INFINITY; l[i] = 0.f; }

    float acc_o[8][4];
#pragma unroll
    for (int ni = 0; ni < 8; ni++)
#pragma unroll
        for (int t = 0; t < 4; t++) acc_o[ni][t] = 0.f;

    const __half* kroot = g_qkv + (size_t)(b * SEQ) * QKVS + HID + kvh * HD;
    const __half* vroot = g_qkv + (size_t)(b * SEQ) * QKVS + HID + KVDIM + kvh * HD;

    for (int kt = 0; kt < SEQ / 64; kt++) {
        __syncthreads();
        const __half* kbase = kroot + (size_t)(kt * 64) * QKVS;
        const __half* vbase = vroot + (size_t)(kt * 64) * QKVS;
#pragma unroll
        for (int it = 0; it < 4; it++) {
            int idx = it * 256 + tid;
            int r  = idx >> 4;
            int d0 = (idx & 15) * 8;
            *(uint4*)(Kh + r * QK_PITCH + d0) =
                *(const uint4*)(kbase + (size_t)r * QKVS + d0);
        }
#pragma unroll
        for (int it = 0; it < 4; it++) {
            int idx = it * 256 + tid;
            int c  = idx & 63;
            int d0 = (idx >> 6) * 8;
            uint4 raw = *(const uint4*)(vbase + (size_t)c * QKVS + d0);
            const __half* hv = (const __half*)&raw;
#pragma unroll
            for (int j = 0; j < 8; j++)
                Vt[(d0 + j) * VT_PITCH + c] = hv[j];
        }
        __syncthreads();

        // ---- S = Q K^T ----
        {
            float acc_s[4][4];
#pragma unroll
            for (int ni = 0; ni < 4; ni++)
#pragma unroll
                for (int t = 0; t < 4; t++) acc_s[ni][t] = 0.f;
#pragma unroll
            for (int ks = 0; ks < 8; ks++) {
                const int c0 = ks * 16 + tg * 2;
#pragma unroll
                for (int ni = 0; ni < 4; ni++) {
                    const int n0 = wn * 32 + ni * 8 + g;
                    uint32_t bb[2];
                    bb[0] = *(const uint32_t*)(Kh + n0 * QK_PITCH + c0);
                    bb[1] = *(const uint32_t*)(Kh + n0 * QK_PITCH + c0 + 8);
                    mma16816_f16(acc_s[ni], qf[ks], bb);
                }
            }
            const int r0 = wm * 16 + g;
#pragma unroll
            for (int ni = 0; ni < 4; ni++) {
                const int col = wn * 32 + ni * 8 + tg * 2;
                *(float2*)(Sf + r0 * SF_PITCH + col) =
                    make_float2(acc_s[ni][0], acc_s[ni][1]);
                *(float2*)(Sf + (r0 + 8) * SF_PITCH + col) =
                    make_float2(acc_s[ni][2], acc_s[ni][3]);
            }
        }
        __syncthreads();

        // ---- online softmax ----
#pragma unroll
        for (int i = 0; i < 8; i++) {
            const int r = w * 8 + i;
            float x0 = Sf[r * SF_PITCH + lane];
            float x1 = Sf[r * SF_PITCH + 32 + lane];
            float mx = fmaxf(x0, x1);
#pragma unroll
            for (int off = 16; off > 0; off >>= 1)
                mx = fmaxf(mx, __shfl_xor_sync(0xffffffffu, mx, off));
            float mnew = fmaxf(m[i], mx);
            float corr = __expf(m[i] - mnew);
            float p0 = __expf(x0 - mnew);
            float p1 = __expf(x1 - mnew);
            Ps[r * VT_PITCH + lane]      = __float2half_rn(p0);
            Ps[r * VT_PITCH + 32 + lane] = __float2half_rn(p1);
            float ps = p0 + p1;
#pragma unroll
            for (int off = 16; off > 0; off >>= 1)
                ps += __shfl_xor_sync(0xffffffffu, ps, off);
            l[i] = l[i] * corr + ps;
            m[i] = mnew;
            if (lane == 0) corr_row[r] = corr;
        }
        __syncthreads();

        // ---- O = O*corr + P V ----
        {
            const int r0 = wm * 16 + g;
            const float c0r = corr_row[r0];
            const float c1r = corr_row[r0 + 8];
#pragma unroll
            for (int ni = 0; ni < 8; ni++) {
                acc_o[ni][0] *= c0r; acc_o[ni][1] *= c0r;
                acc_o[ni][2] *= c1r; acc_o[ni][3] *= c1r;
            }
#pragma unroll
            for (int ks = 0; ks < 4; ks++) {
                const int c0 = ks * 16 + tg * 2;
                uint32_t pa[4];
                pa[0] = *(const uint32_t*)(Ps + r0 * VT_PITCH + c0);
                pa[1] = *(const uint32_t*)(Ps + (r0 + 8) * VT_PITCH + c0);
                pa[2] = *(const uint32_t*)(Ps + r0 * VT_PITCH + c0 + 8);
                pa[3] = *(const uint32_t*)(Ps + (r0 + 8) * VT_PITCH + c0 + 8);
#pragma unroll
                for (int ni = 0; ni < 8; ni++) {
                    const int n0 = wn * 64 + ni * 8 + g;
                    uint32_t bb[2];
                    bb[0] = *(const uint32_t*)(Vt + n0 * VT_PITCH + c0);
                    bb[1] = *(const uint32_t*)(Vt + n0 * VT_PITCH + c0 + 8);
                    mma16816_f16(acc_o[ni], pa, bb);
                }
            }
        }
    }

    if (lane == 0) {
#pragma unroll
        for (int i = 0; i < 8; i++) lrow[w * 8 + i] = l[i];
    }
    __syncthreads();

    {
        const int r0 = wm * 16 + g;
        const float inv0 = 1.0f / lrow[r0];
        const float inv1 = 1.0f / lrow[r0 + 8];
        const size_t tok0 = (size_t)(b * SEQ + qtile * 64 + r0);
#pragma unroll
        for (int ni = 0; ni < 8; ni++) {
            const int col = wn * 64 + ni * 8 + tg * 2;
            *(__half2*)(g_ao + tok0 * HID + h * HD + col) =
                __floats2half2_rn(acc_o[ni][0] * inv0, acc_o[ni][1] * inv0);
            *(__half2*)(g_ao + (tok0 + 8) * HID + h * HD + col) =
                __floats2half2_rn(acc_o[ni][2] * inv1, acc_o[ni][3] * inv1);
        }
    }
}

// ---------------------------------------------------------------------------
// kernel_launch
// ---------------------------------------------------------------------------
extern "C" void kernel_launch(void* const* d_in, const int* in_sizes, int n_in,
                              void* d_out, int out_size)
{
    (void)in_sizes; (void)n_in; (void)out_size;
    const float* hidden = (const float*)d_in[0];
    const float* Wq = (const float*)d_in[1];
    const float* bq = (const float*)d_in[2];
    const float* Wk = (const float*)d_in[3];
    const float* bk = (const float*)d_in[4];
    const float* Wv = (const float*)d_in[5];
    const float* bv = (const float*)d_in[6];
    const float* Wo = (const float*)d_in[7];
    const float* bo = (const float*)d_in[8];
    float* out = (float*)d_out;

    __half *ah, *qkv, *ao, *wt, *wot;
    float* biasp;
    cudaGetSymbolAddress((void**)&ah,    g_ah);
    cudaGetSymbolAddress((void**)&qkv,   g_qkv);
    cudaGetSymbolAddress((void**)&ao,    g_ao);
    cudaGetSymbolAddress((void**)&wt,    g_wt);
    cudaGetSymbolAddress((void**)&wot,   g_wo_t);
    cudaGetSymbolAddress((void**)&biasp, g_bias);

    static int attr_set = 0;
    if (!attr_set) {
        cudaFuncSetAttribute(flash_tc_kernel,
                             cudaFuncAttributeMaxDynamicSharedMemorySize, FA_SMEM);
        cudaFuncSetAttribute(gemm_h_kernel,
                             cudaFuncAttributeMaxDynamicSharedMemorySize, GEMM_SMEM);
        attr_set = 1;
    }

    const float scaling = 0.08838834764831845f;  // 128^-0.5

    // 1) prep: hidden -> fp16; pack Wqkv^T (q pre-scaled) + Wo^T; pack bias
    convert_h_kernel<<<(BS_ROWS * HID / 8) / 256, 256>>>(hidden, ah);
    transpose_h_kernel<<<dim3(HID / 32,   HID / 32), 256>>>(Wq, wt,  HID, HID,   0,           scaling);
    transpose_h_kernel<<<dim3(KVDIM / 32, HID / 32), 256>>>(Wk, wt,  HID, KVDIM, HID,         1.0f);
    transpose_h_kernel<<<dim3(KVDIM / 32, HID / 32), 256>>>(Wv, wt,  HID, KVDIM, HID + KVDIM, 1.0f);
    transpose_h_kernel<<<dim3(HID / 32,   HID / 32), 256>>>(Wo, wot, HID, HID,   0,           1.0f);
    bias_pack_kernel<<<QKVS / 256, 256>>>(bq, bk, bv, scaling);

    // 2) fused QKV projection -> packed fp16 qkv
    gemm_h_kernel<<<dim3(QKVS / 128, BS_ROWS / 128), 256, GEMM_SMEM>>>(
        ah, wt, biasp, nullptr, qkv, QKVS, HID);

    // 3) flash attention (fp16 tensor cores) -> fp16 ao
    flash_tc_kernel<<<dim3(SEQ / 64, NH, BATCH), 256, FA_SMEM>>>();

    // 4) O-projection -> fp32 out
    gemm_h_kernel<<<dim3(HID / 128, BS_ROWS / 128), 256, GEMM_SMEM>>>(
        ao, wot, bo, out, nullptr, HID, HID);
}

// round 7
// speedup vs baseline: 7.2745x; 1.6583x over previous
#include <cuda_runtime.h>
#include <cuda_fp16.h>
#include <math.h>
#include <stdint.h>

// ---------------------------------------------------------------------------
// MultiQueryAttention: B=2, S=2048, HIDDEN=2048, NH=16, NKV=2, D=128
// Round 7: flash rewritten — register softmax, ldmatrix(.trans) fragments,
//          cp.async K/V pipeline, 1 sync per KV tile. GEMMs unchanged.
// ---------------------------------------------------------------------------

#define BATCH      2
#define SEQ        2048
#define HID        2048
#define NH         16
#define NKV        2
#define HD         128
#define KVDIM      (NKV * HD)          // 256
#define QKVS       (HID + 2 * KVDIM)   // 2560
#define BS_ROWS    (BATCH * SEQ)       // 4096
#define REP        (NH / NKV)          // 8

// ---------------- scratch ----------------
__device__ __half g_ah  [BS_ROWS * HID];
__device__ __half g_qkv [BS_ROWS * QKVS];
__device__ __half g_ao  [BS_ROWS * HID];
__device__ __half g_wt  [QKVS * HID];
__device__ __half g_wo_t[HID * HID];
__device__ float  g_bias[QKVS];

// ---------------------------------------------------------------------------
// PTX helpers
// ---------------------------------------------------------------------------
static __device__ __forceinline__ void mma16816_f16(
    float* d, const uint32_t* a, const uint32_t* b)
{
    asm volatile(
        "mma.sync.aligned.m16n8k16.row.col.f32.f16.f16.f32 "
        "{%0,%1,%2,%3}, {%4,%5,%6,%7}, {%8,%9}, {%0,%1,%2,%3};"
        : "+f"(d[0]), "+f"(d[1]), "+f"(d[2]), "+f"(d[3])
        : "r"(a[0]), "r"(a[1]), "r"(a[2]), "r"(a[3]), "r"(b[0]), "r"(b[1]));
}
static __device__ __forceinline__ void ldmx4(
    uint32_t& r0, uint32_t& r1, uint32_t& r2, uint32_t& r3, uint32_t addr)
{
    asm volatile("ldmatrix.sync.aligned.m8n8.x4.shared.b16 {%0,%1,%2,%3}, [%4];"
        : "=r"(r0), "=r"(r1), "=r"(r2), "=r"(r3) : "r"(addr));
}
static __device__ __forceinline__ void ldmx4t(
    uint32_t& r0, uint32_t& r1, uint32_t& r2, uint32_t& r3, uint32_t addr)
{
    asm volatile("ldmatrix.sync.aligned.m8n8.x4.trans.shared.b16 {%0,%1,%2,%3}, [%4];"
        : "=r"(r0), "=r"(r1), "=r"(r2), "=r"(r3) : "r"(addr));
}
static __device__ __forceinline__ void cp_async16(void* sptr, const void* gptr) {
    uint32_t s = (uint32_t)__cvta_generic_to_shared(sptr);
    asm volatile("cp.async.cg.shared.global [%0], [%1], 16;"
                 :: "r"(s), "l"(gptr) : "memory");
}
#define CP_COMMIT() asm volatile("cp.async.commit_group;" ::: "memory")
#define CP_WAIT0()  asm volatile("cp.async.wait_group 0;" ::: "memory")

static __device__ __forceinline__ uint32_t pack_h2(float a, float b) {
    __half2 h = __floats2half2_rn(a, b);
    return *reinterpret_cast<uint32_t*>(&h);
}

// ---------------------------------------------------------------------------
// fp16 GEMM (unchanged from round 6)
// ---------------------------------------------------------------------------
#define PITCH 72
#define BK    64
#define OPB   (128 * PITCH * 2)
#define STG   (2 * OPB)
#define GEMM_SMEM (2 * STG)

__global__ __launch_bounds__(256, 2) void gemm_h_kernel(
    const __half* __restrict__ A, const __half* __restrict__ Bt,
    const float* __restrict__ bias, float* __restrict__ C,
    __half* __restrict__ Ch, int N, int K)
{
    extern __shared__ char gsm[];

    const int tid    = threadIdx.x;
    const int lane   = tid & 31;
    const int wid    = tid >> 5;
    const int warp_m = wid >> 2;
    const int warp_n = wid & 3;
    const int g      = lane >> 2;
    const int tg     = lane & 3;

    const int blockRow = blockIdx.y * 128;
    const int blockCol = blockIdx.x * 128;

    float acc[4][4][4];
#pragma unroll
    for (int mi = 0; mi < 4; mi++)
#pragma unroll
        for (int ni = 0; ni < 4; ni++)
#pragma unroll
            for (int t = 0; t < 4; t++) acc[mi][ni][t] = 0.f;

    const int nch = K / BK;

    auto issue = [&](int c, int stg) {
        char* base = gsm + stg * STG;
#pragma unroll
        for (int it = 0; it < 4; it++) {
            int idx = it * 256 + tid;
            int m  = idx >> 3;
            int kq = idx & 7;
            int so = (m * PITCH + kq * 8) * 2;
            cp_async16(base + so,
                       A + (size_t)(blockRow + m) * K + c * BK + kq * 8);
            cp_async16(base + OPB + so,
                       Bt + (size_t)(blockCol + m) * K + c * BK + kq * 8);
        }
        CP_COMMIT();
    };

    issue(0, 0);

    for (int c = 0; c < nch; c++) {
        const int b = c & 1;
        CP_WAIT0();
        __syncthreads();
        if (c + 1 < nch) issue(c + 1, 1 - b);

        const __half* As = (const __half*)(gsm + b * STG);
        const __half* Bs = (const __half*)(gsm + b * STG + OPB);

#pragma unroll
        for (int ks = 0; ks < 4; ks++) {
            const int c0 = ks * 16 + tg * 2;
            uint32_t av[4][4];
#pragma unroll
            for (int mi = 0; mi < 4; mi++) {
                int r0 = warp_m * 64 + mi * 16 + g;
                av[mi][0] = *(const uint32_t*)(As + r0 * PITCH + c0);
                av[mi][1] = *(const uint32_t*)(As + (r0 + 8) * PITCH + c0);
                av[mi][2] = *(const uint32_t*)(As + r0 * PITCH + c0 + 8);
                av[mi][3] = *(const uint32_t*)(As + (r0 + 8) * PITCH + c0 + 8);
            }
#pragma unroll
            for (int ni = 0; ni < 4; ni++) {
                int n0 = warp_n * 32 + ni * 8 + g;
                uint32_t bb[2];
                bb[0] = *(const uint32_t*)(Bs + n0 * PITCH + c0);
                bb[1] = *(const uint32_t*)(Bs + n0 * PITCH + c0 + 8);
#pragma unroll
                for (int mi = 0; mi < 4; mi++)
                    mma16816_f16(acc[mi][ni], av[mi], bb);
            }
        }
        __syncthreads();
    }

#pragma unroll
    for (int mi = 0; mi < 4; mi++) {
#pragma unroll
        for (int ni = 0; ni < 4; ni++) {
            int row0 = blockRow + warp_m * 64 + mi * 16 + g;
            int col  = blockCol + warp_n * 32 + ni * 8 + tg * 2;
            float2 b2 = *(const float2*)(bias + col);
            float2 o0, o1;
            o0.x = acc[mi][ni][0] + b2.x;
            o0.y = acc[mi][ni][1] + b2.y;
            o1.x = acc[mi][ni][2] + b2.x;
            o1.y = acc[mi][ni][3] + b2.y;
            if (C) {
                *(float2*)(C + (size_t)row0 * N + col)       = o0;
                *(float2*)(C + (size_t)(row0 + 8) * N + col) = o1;
            }
            if (Ch) {
                *(__half2*)(Ch + (size_t)row0 * N + col) =
                    __floats2half2_rn(o0.x, o0.y);
                *(__half2*)(Ch + (size_t)(row0 + 8) * N + col) =
                    __floats2half2_rn(o1.x, o1.y);
            }
        }
    }
}

// ---------------------------------------------------------------------------
// prep kernels (unchanged)
// ---------------------------------------------------------------------------
__global__ __launch_bounds__(256) void convert_h_kernel(
    const float* __restrict__ X, __half* __restrict__ Y)
{
    size_t base = ((size_t)blockIdx.x * 256 + threadIdx.x) * 8;
    float4 a = *(const float4*)(X + base);
    float4 b = *(const float4*)(X + base + 4);
    __half h[8];
    h[0] = __float2half_rn(a.x); h[1] = __float2half_rn(a.y);
    h[2] = __float2half_rn(a.z); h[3] = __float2half_rn(a.w);
    h[4] = __float2half_rn(b.x); h[5] = __float2half_rn(b.y);
    h[6] = __float2half_rn(b.z); h[7] = __float2half_rn(b.w);
    *(uint4*)(Y + base) = *(uint4*)h;
}

__global__ __launch_bounds__(256) void transpose_h_kernel(
    const float* __restrict__ W, __half* __restrict__ T,
    int K, int N, int rowoff, float scale)
{
    __shared__ float tile[32][33];
    const int n0 = blockIdx.x * 32;
    const int k0 = blockIdx.y * 32;
    const int tx = threadIdx.x & 31;
    const int ty = threadIdx.x >> 5;
#pragma unroll
    for (int i = 0; i < 4; i++)
        tile[ty + i * 8][tx] = W[(size_t)(k0 + ty + i * 8) * N + n0 + tx];
    __syncthreads();
#pragma unroll
    for (int i = 0; i < 4; i++) {
        int r = ty + i * 8;
        T[(size_t)(rowoff + n0 + r) * K + k0 + tx] =
            __float2half_rn(tile[tx][r] * scale);
    }
}

__global__ __launch_bounds__(256) void bias_pack_kernel(
    const float* __restrict__ bq, const float* __restrict__ bk,
    const float* __restrict__ bv, float scale)
{
    int i = blockIdx.x * 256 + threadIdx.x;
    if (i < HID)              g_bias[i] = bq[i] * scale;
    else if (i < HID + KVDIM) g_bias[i] = bk[i - HID];
    else if (i < QKVS)        g_bias[i] = bv[i - HID - KVDIM];
}

// ---------------------------------------------------------------------------
// Flash attention, round-7 design.
// CTA = 128 q-rows x (head, batch). 8 warps; warp w owns rows w*16..w*16+15,
// full 64-col KV stripe (register softmax) and full 128-d O stripe.
// K/V tiles (64 x 128 halves) double-buffered via cp.async.
// K fragments: ldmatrix.x4; V^T fragments: ldmatrix.x4.trans on row-major V.
// ---------------------------------------------------------------------------
#define FP       136                     // half pitch for Q/K/V tiles
#define Q_HALVES (128 * FP)              // 17408 halves = 34816 B
#define KV_HALVES (64 * FP)              // 8704 halves = 17408 B
#define FA_SMEM  ((Q_HALVES + 4 * KV_HALVES) * 2)   // 104448 B

__global__ __launch_bounds__(256, 1) void flash_tc_kernel()
{
    extern __shared__ __half sh[];
    __half* Qh  = sh;                        // [128][136]
    __half* Kst = sh + Q_HALVES;             // 2 x [64][136]
    __half* Vst = sh + Q_HALVES + 2 * KV_HALVES;

    const int tid  = threadIdx.x;
    const int lane = tid & 31;
    const int w    = tid >> 5;      // 0..7 -> q rows w*16..+15
    const int g    = lane >> 2;     // 0..7
    const int tg   = lane & 3;      // 0..3

    const int qtile = blockIdx.x;   // 0..15 (128 rows each)
    const int h     = blockIdx.y;   // 0..15
    const int b     = blockIdx.z;   // 0..1
    const int kvh   = h / REP;

    const __half* qbase = g_qkv + (size_t)(b * SEQ + qtile * 128) * QKVS + h * HD;
    const __half* kroot = g_qkv + (size_t)(b * SEQ) * QKVS + HID + kvh * HD;
    const __half* vroot = g_qkv + (size_t)(b * SEQ) * QKVS + HID + KVDIM + kvh * HD;

    // ---- Q tile: 128 x 128 halves, 8 uint4/thread ----
#pragma unroll
    for (int it = 0; it < 8; it++) {
        int idx = it * 256 + tid;
        int r  = idx >> 4;
        int d0 = (idx & 15) * 8;
        *(uint4*)(Qh + r * FP + d0) = *(const uint4*)(qbase + (size_t)r * QKVS + d0);
    }

    // ---- issue K/V tile kt into stage stg ----
    auto issue = [&](int kt, int stg) {
        const __half* kb_ = kroot + (size_t)(kt * 64) * QKVS;
        const __half* vb_ = vroot + (size_t)(kt * 64) * QKVS;
        __half* kd = Kst + stg * KV_HALVES;
        __half* vd = Vst + stg * KV_HALVES;
#pragma unroll
        for (int it = 0; it < 4; it++) {
            int idx = it * 256 + tid;
            int r  = idx >> 4;
            int d0 = (idx & 15) * 8;
            cp_async16(kd + r * FP + d0, kb_ + (size_t)r * QKVS + d0);
            cp_async16(vd + r * FP + d0, vb_ + (size_t)r * QKVS + d0);
        }
        CP_COMMIT();
    };

    issue(0, 0);
    __syncthreads();   // Qh visible

    // ---- preload Q fragments (rows w*16+g, w*16+g+8) ----
    uint32_t qf[8][4];
    {
        const int r0 = w * 16 + g;
#pragma unroll
        for (int ks = 0; ks < 8; ks++) {
            const int c0 = ks * 16 + tg * 2;
            qf[ks][0] = *(const uint32_t*)(Qh + r0 * FP + c0);
            qf[ks][1] = *(const uint32_t*)(Qh + (r0 + 8) * FP + c0);
            qf[ks][2] = *(const uint32_t*)(Qh + r0 * FP + c0 + 8);
            qf[ks][3] = *(const uint32_t*)(Qh + (r0 + 8) * FP + c0 + 8);
        }
    }

    // ldmatrix per-lane address components
    const int mat  = lane >> 3;
    const int mr   = lane & 7;
    const int k_ro = ((mat & 2) ? 8 : 0) + mr;   // K: row offset within 16
    const int k_co = (mat & 1) ? 8 : 0;          // K: col (k) offset
    const int v_ro = ((mat & 1) ? 8 : 0) + mr;   // V: row (c) offset
    const int v_co = (mat & 2) ? 8 : 0;          // V: col (d) offset

    const uint32_t ksm = (uint32_t)__cvta_generic_to_shared(Kst);
    const uint32_t vsm = (uint32_t)__cvta_generic_to_shared(Vst);

    float m0 = -INFINITY, m1 = -INFINITY, l0 = 0.f, l1 = 0.f;
    float acc_o[16][4];
#pragma unroll
    for (int nb = 0; nb < 16; nb++)
#pragma unroll
        for (int t = 0; t < 4; t++) acc_o[nb][t] = 0.f;

    for (int kt = 0; kt < SEQ / 64; kt++) {
        CP_WAIT0();
        __syncthreads();
        if (kt + 1 < SEQ / 64) issue(kt + 1, (kt + 1) & 1);
        const int sb = kt & 1;
        const uint32_t kS = ksm + sb * KV_HALVES * 2;
        const uint32_t vS = vsm + sb * KV_HALVES * 2;

        // ---- S = Q K^T : 16 x 64 per warp ----
        float acc_s[8][4];
#pragma unroll
        for (int ni = 0; ni < 8; ni++)
#pragma unroll
            for (int t = 0; t < 4; t++) acc_s[ni][t] = 0.f;

#pragma unroll
        for (int ks = 0; ks < 8; ks++) {
            const int c0 = ks * 16;
#pragma unroll
            for (int np = 0; np < 4; np++) {
                uint32_t r0, r1, r2, r3;
                ldmx4(r0, r1, r2, r3,
                      kS + (uint32_t)(((np * 16 + k_ro) * FP + c0 + k_co) * 2));
                uint32_t b0[2] = {r0, r1};
                uint32_t b1[2] = {r2, r3};
                mma16816_f16(acc_s[2 * np],     qf[ks], b0);
                mma16816_f16(acc_s[2 * np + 1], qf[ks], b1);
            }
        }

        // ---- register online softmax (rows r0 = w*16+g, r1 = r0+8) ----
        {
            float mx0 = -INFINITY, mx1 = -INFINITY;
#pragma unroll
            for (int ni = 0; ni < 8; ni++) {
                mx0 = fmaxf(mx0, fmaxf(acc_s[ni][0], acc_s[ni][1]));
                mx1 = fmaxf(mx1, fmaxf(acc_s[ni][2], acc_s[ni][3]));
            }
            mx0 = fmaxf(mx0, __shfl_xor_sync(0xffffffffu, mx0, 1));
            mx0 = fmaxf(mx0, __shfl_xor_sync(0xffffffffu, mx0, 2));
            mx1 = fmaxf(mx1, __shfl_xor_sync(0xffffffffu, mx1, 1));
            mx1 = fmaxf(mx1, __shfl_xor_sync(0xffffffffu, mx1, 2));

            float mn0 = fmaxf(m0, mx0);
            float mn1 = fmaxf(m1, mx1);
            float corr0 = __expf(m0 - mn0);
            float corr1 = __expf(m1 - mn1);

            float s0 = 0.f, s1 = 0.f;
#pragma unroll
            for (int ni = 0; ni < 8; ni++) {
                acc_s[ni][0] = __expf(acc_s[ni][0] - mn0);
                acc_s[ni][1] = __expf(acc_s[ni][1] - mn0);
                acc_s[ni][2] = __expf(acc_s[ni][2] - mn1);
                acc_s[ni][3] = __expf(acc_s[ni][3] - mn1);
                s0 += acc_s[ni][0] + acc_s[ni][1];
                s1 += acc_s[ni][2] + acc_s[ni][3];
            }
            s0 += __shfl_xor_sync(0xffffffffu, s0, 1);
            s0 += __shfl_xor_sync(0xffffffffu, s0, 2);
            s1 += __shfl_xor_sync(0xffffffffu, s1, 1);
            s1 += __shfl_xor_sync(0xffffffffu, s1, 2);

            l0 = l0 * corr0 + s0;
            l1 = l1 * corr1 + s1;
            m0 = mn0;
            m1 = mn1;

#pragma unroll
            for (int nb = 0; nb < 16; nb++) {
                acc_o[nb][0] *= corr0; acc_o[nb][1] *= corr0;
                acc_o[nb][2] *= corr1; acc_o[nb][3] *= corr1;
            }
        }

        // ---- P -> A fragments (in registers) ----
        uint32_t pf[4][4];
#pragma unroll
        for (int kb = 0; kb < 4; kb++) {
            pf[kb][0] = pack_h2(acc_s[2 * kb][0],     acc_s[2 * kb][1]);
            pf[kb][1] = pack_h2(acc_s[2 * kb][2],     acc_s[2 * kb][3]);
            pf[kb][2] = pack_h2(acc_s[2 * kb + 1][0], acc_s[2 * kb + 1][1]);
            pf[kb][3] = pack_h2(acc_s[2 * kb + 1][2], acc_s[2 * kb + 1][3]);
        }

        // ---- O += P V : 16 x 128 per warp, V^T frags via ldmatrix.trans ----
#pragma unroll
        for (int ks = 0; ks < 4; ks++) {
            const int c0 = ks * 16;
#pragma unroll
            for (int nb = 0; nb < 8; nb++) {
                uint32_t r0, r1, r2, r3;
                ldmx4t(r0, r1, r2, r3,
                       vS + (uint32_t)(((c0 + v_ro) * FP + nb * 16 + v_co) * 2));
                uint32_t b0[2] = {r0, r1};
                uint32_t b1[2] = {r2, r3};
                mma16816_f16(acc_o[2 * nb],     pf[ks], b0);
                mma16816_f16(acc_o[2 * nb + 1], pf[ks], b1);
            }
        }
    }

    // ---- epilogue: normalize, write fp16 g_ao ----
    {
        const float inv0 = 1.0f / l0;
        const float inv1 = 1.0f / l1;
        const size_t tok0 = (size_t)(b * SEQ + qtile * 128 + w * 16 + g);
#pragma unroll
        for (int nb = 0; nb < 16; nb++) {
            const int col = nb * 8 + tg * 2;
            *(__half2*)(g_ao + tok0 * HID + h * HD + col) =
                __floats2half2_rn(acc_o[nb][0] * inv0, acc_o[nb][1] * inv0);
            *(__half2*)(g_ao + (tok0 + 8) * HID + h * HD + col) =
                __floats2half2_rn(acc_o[nb][2] * inv1, acc_o[nb][3] * inv1);
        }
    }
}

// ---------------------------------------------------------------------------
// kernel_launch
// ---------------------------------------------------------------------------
extern "C" void kernel_launch(void* const* d_in, const int* in_sizes, int n_in,
                              void* d_out, int out_size)
{
    (void)in_sizes; (void)n_in; (void)out_size;
    const float* hidden = (const float*)d_in[0];
    const float* Wq = (const float*)d_in[1];
    const float* bq = (const float*)d_in[2];
    const float* Wk = (const float*)d_in[3];
    const float* bk = (const float*)d_in[4];
    const float* Wv = (const float*)d_in[5];
    const float* bv = (const float*)d_in[6];
    const float* Wo = (const float*)d_in[7];
    const float* bo = (const float*)d_in[8];
    float* out = (float*)d_out;

    __half *ah, *qkv, *ao, *wt, *wot;
    float* biasp;
    cudaGetSymbolAddress((void**)&ah,    g_ah);
    cudaGetSymbolAddress((void**)&qkv,   g_qkv);
    cudaGetSymbolAddress((void**)&ao,    g_ao);
    cudaGetSymbolAddress((void**)&wt,    g_wt);
    cudaGetSymbolAddress((void**)&wot,   g_wo_t);
    cudaGetSymbolAddress((void**)&biasp, g_bias);

    static int attr_set = 0;
    if (!attr_set) {
        cudaFuncSetAttribute(flash_tc_kernel,
                             cudaFuncAttributeMaxDynamicSharedMemorySize, FA_SMEM);
        cudaFuncSetAttribute(gemm_h_kernel,
                             cudaFuncAttributeMaxDynamicSharedMemorySize, GEMM_SMEM);
        attr_set = 1;
    }

    const float scaling = 0.08838834764831845f;  // 128^-0.5

    // 1) prep
    convert_h_kernel<<<(BS_ROWS * HID / 8) / 256, 256>>>(hidden, ah);
    transpose_h_kernel<<<dim3(HID / 32,   HID / 32), 256>>>(Wq, wt,  HID, HID,   0,           scaling);
    transpose_h_kernel<<<dim3(KVDIM / 32, HID / 32), 256>>>(Wk, wt,  HID, KVDIM, HID,         1.0f);
    transpose_h_kernel<<<dim3(KVDIM / 32, HID / 32), 256>>>(Wv, wt,  HID, KVDIM, HID + KVDIM, 1.0f);
    transpose_h_kernel<<<dim3(HID / 32,   HID / 32), 256>>>(Wo, wot, HID, HID,   0,           1.0f);
    bias_pack_kernel<<<QKVS / 256, 256>>>(bq, bk, bv, scaling);

    // 2) fused QKV projection
    gemm_h_kernel<<<dim3(QKVS / 128, BS_ROWS / 128), 256, GEMM_SMEM>>>(
        ah, wt, biasp, nullptr, qkv, QKVS, HID);

    // 3) flash attention
    flash_tc_kernel<<<dim3(SEQ / 128, NH, BATCH), 256, FA_SMEM>>>();

    // 4) O-projection
    gemm_h_kernel<<<dim3(HID / 128, BS_ROWS / 128), 256, GEMM_SMEM>>>(
        ao, wot, bo, out, nullptr, HID, HID);
}

// round 8
// speedup vs baseline: 7.6729x; 1.0548x over previous
#include <cuda_runtime.h>
#include <cuda_fp16.h>
#include <math.h>
#include <stdint.h>

// ---------------------------------------------------------------------------
// MultiQueryAttention: B=2, S=2048, HIDDEN=2048, NH=16, NKV=2, D=128
// Round 8: GEMM fragment loads via ldmatrix.x4 (A non-trans + B non-trans,
//          same mapping validated in the round-7 flash kernel). Rest unchanged.
// ---------------------------------------------------------------------------

#define BATCH      2
#define SEQ        2048
#define HID        2048
#define NH         16
#define NKV        2
#define HD         128
#define KVDIM      (NKV * HD)          // 256
#define QKVS       (HID + 2 * KVDIM)   // 2560
#define BS_ROWS    (BATCH * SEQ)       // 4096
#define REP        (NH / NKV)          // 8

// ---------------- scratch ----------------
__device__ __half g_ah  [BS_ROWS * HID];
__device__ __half g_qkv [BS_ROWS * QKVS];
__device__ __half g_ao  [BS_ROWS * HID];
__device__ __half g_wt  [QKVS * HID];
__device__ __half g_wo_t[HID * HID];
__device__ float  g_bias[QKVS];

// ---------------------------------------------------------------------------
// PTX helpers
// ---------------------------------------------------------------------------
static __device__ __forceinline__ void mma16816_f16(
    float* d, const uint32_t* a, const uint32_t* b)
{
    asm volatile(
        "mma.sync.aligned.m16n8k16.row.col.f32.f16.f16.f32 "
        "{%0,%1,%2,%3}, {%4,%5,%6,%7}, {%8,%9}, {%0,%1,%2,%3};"
        : "+f"(d[0]), "+f"(d[1]), "+f"(d[2]), "+f"(d[3])
        : "r"(a[0]), "r"(a[1]), "r"(a[2]), "r"(a[3]), "r"(b[0]), "r"(b[1]));
}
static __device__ __forceinline__ void ldmx4(
    uint32_t& r0, uint32_t& r1, uint32_t& r2, uint32_t& r3, uint32_t addr)
{
    asm volatile("ldmatrix.sync.aligned.m8n8.x4.shared.b16 {%0,%1,%2,%3}, [%4];"
        : "=r"(r0), "=r"(r1), "=r"(r2), "=r"(r3) : "r"(addr));
}
static __device__ __forceinline__ void ldmx4t(
    uint32_t& r0, uint32_t& r1, uint32_t& r2, uint32_t& r3, uint32_t addr)
{
    asm volatile("ldmatrix.sync.aligned.m8n8.x4.trans.shared.b16 {%0,%1,%2,%3}, [%4];"
        : "=r"(r0), "=r"(r1), "=r"(r2), "=r"(r3) : "r"(addr));
}
static __device__ __forceinline__ void cp_async16(void* sptr, const void* gptr) {
    uint32_t s = (uint32_t)__cvta_generic_to_shared(sptr);
    asm volatile("cp.async.cg.shared.global [%0], [%1], 16;"
                 :: "r"(s), "l"(gptr) : "memory");
}
#define CP_COMMIT() asm volatile("cp.async.commit_group;" ::: "memory")
#define CP_WAIT0()  asm volatile("cp.async.wait_group 0;" ::: "memory")

static __device__ __forceinline__ uint32_t pack_h2(float a, float b) {
    __half2 h = __floats2half2_rn(a, b);
    return *reinterpret_cast<uint32_t*>(&h);
}

// ---------------------------------------------------------------------------
// fp16 GEMM: C[M,N] = A[M,K] @ Bt[N,K]^T + bias[N]  (fp32 accum)
// CTA 128x128, BK=64, cp.async 2-stage, 8 warps 2x4, warp tile 64x32.
// Round 8: fragments via ldmatrix.x4.
// ---------------------------------------------------------------------------
#define PITCH 72
#define BK    64
#define OPB   (128 * PITCH * 2)
#define STG   (2 * OPB)
#define GEMM_SMEM (2 * STG)

__global__ __launch_bounds__(256, 2) void gemm_h_kernel(
    const __half* __restrict__ A, const __half* __restrict__ Bt,
    const float* __restrict__ bias, float* __restrict__ C,
    __half* __restrict__ Ch, int N, int K)
{
    extern __shared__ char gsm[];

    const int tid    = threadIdx.x;
    const int lane   = tid & 31;
    const int wid    = tid >> 5;
    const int warp_m = wid >> 2;    // 0..1
    const int warp_n = wid & 3;     // 0..3
    const int g      = lane >> 2;
    const int tg     = lane & 3;

    const int blockRow = blockIdx.y * 128;
    const int blockCol = blockIdx.x * 128;

    // ldmatrix per-lane address components
    const int mat = lane >> 3;     // 0..3
    const int mr  = lane & 7;      // 0..7
    const int a_ro = ((mat & 1) ? 8 : 0) + mr;   // A: m0(r,c) m1(r+8,c) m2(r,c+8) m3(r+8,c+8)
    const int a_co = (mat & 2) ? 8 : 0;
    const int b_ro = ((mat & 2) ? 8 : 0) + mr;   // B: m0(n,c) m1(n,c+8) m2(n+8,c) m3(n+8,c+8)
    const int b_co = (mat & 1) ? 8 : 0;

    const uint32_t gbase = (uint32_t)__cvta_generic_to_shared(gsm);

    float acc[4][4][4];
#pragma unroll
    for (int mi = 0; mi < 4; mi++)
#pragma unroll
        for (int ni = 0; ni < 4; ni++)
#pragma unroll
            for (int t = 0; t < 4; t++) acc[mi][ni][t] = 0.f;

    const int nch = K / BK;

    auto issue = [&](int c, int stg) {
        char* base = gsm + stg * STG;
#pragma unroll
        for (int it = 0; it < 4; it++) {
            int idx = it * 256 + tid;
            int m  = idx >> 3;
            int kq = idx & 7;
            int so = (m * PITCH + kq * 8) * 2;
            cp_async16(base + so,
                       A + (size_t)(blockRow + m) * K + c * BK + kq * 8);
            cp_async16(base + OPB + so,
                       Bt + (size_t)(blockCol + m) * K + c * BK + kq * 8);
        }
        CP_COMMIT();
    };

    issue(0, 0);

    for (int c = 0; c < nch; c++) {
        const int b = c & 1;
        CP_WAIT0();
        __syncthreads();
        if (c + 1 < nch) issue(c + 1, 1 - b);

        const uint32_t aS = gbase + b * STG;
        const uint32_t bS = aS + OPB;

#pragma unroll
        for (int ks = 0; ks < 4; ks++) {
            const int c0 = ks * 16;
            uint32_t av[4][4];
#pragma unroll
            for (int mi = 0; mi < 4; mi++) {
                const int r = warp_m * 64 + mi * 16 + a_ro;
                ldmx4(av[mi][0], av[mi][1], av[mi][2], av[mi][3],
                      aS + (uint32_t)((r * PITCH + c0 + a_co) * 2));
            }
            uint32_t bv[2][4];
#pragma unroll
            for (int np = 0; np < 2; np++) {
                const int n = warp_n * 32 + np * 16 + b_ro;
                ldmx4(bv[np][0], bv[np][1], bv[np][2], bv[np][3],
                      bS + (uint32_t)((n * PITCH + c0 + b_co) * 2));
            }
#pragma unroll
            for (int ni = 0; ni < 4; ni++) {
                uint32_t bb[2] = { bv[ni >> 1][(ni & 1) * 2],
                                   bv[ni >> 1][(ni & 1) * 2 + 1] };
#pragma unroll
                for (int mi = 0; mi < 4; mi++)
                    mma16816_f16(acc[mi][ni], av[mi], bb);
            }
        }
        __syncthreads();
    }

#pragma unroll
    for (int mi = 0; mi < 4; mi++) {
#pragma unroll
        for (int ni = 0; ni < 4; ni++) {
            int row0 = blockRow + warp_m * 64 + mi * 16 + g;
            int col  = blockCol + warp_n * 32 + ni * 8 + tg * 2;
            float2 b2 = *(const float2*)(bias + col);
            float2 o0, o1;
            o0.x = acc[mi][ni][0] + b2.x;
            o0.y = acc[mi][ni][1] + b2.y;
            o1.x = acc[mi][ni][2] + b2.x;
            o1.y = acc[mi][ni][3] + b2.y;
            if (C) {
                *(float2*)(C + (size_t)row0 * N + col)       = o0;
                *(float2*)(C + (size_t)(row0 + 8) * N + col) = o1;
            }
            if (Ch) {
                *(__half2*)(Ch + (size_t)row0 * N + col) =
                    __floats2half2_rn(o0.x, o0.y);
                *(__half2*)(Ch + (size_t)(row0 + 8) * N + col) =
                    __floats2half2_rn(o1.x, o1.y);
            }
        }
    }
}

// ---------------------------------------------------------------------------
// prep kernels (unchanged)
// ---------------------------------------------------------------------------
__global__ __launch_bounds__(256) void convert_h_kernel(
    const float* __restrict__ X, __half* __restrict__ Y)
{
    size_t base = ((size_t)blockIdx.x * 256 + threadIdx.x) * 8;
    float4 a = *(const float4*)(X + base);
    float4 b = *(const float4*)(X + base + 4);
    __half h[8];
    h[0] = __float2half_rn(a.x); h[1] = __float2half_rn(a.y);
    h[2] = __float2half_rn(a.z); h[3] = __float2half_rn(a.w);
    h[4] = __float2half_rn(b.x); h[5] = __float2half_rn(b.y);
    h[6] = __float2half_rn(b.z); h[7] = __float2half_rn(b.w);
    *(uint4*)(Y + base) = *(uint4*)h;
}

__global__ __launch_bounds__(256) void transpose_h_kernel(
    const float* __restrict__ W, __half* __restrict__ T,
    int K, int N, int rowoff, float scale)
{
    __shared__ float tile[32][33];
    const int n0 = blockIdx.x * 32;
    const int k0 = blockIdx.y * 32;
    const int tx = threadIdx.x & 31;
    const int ty = threadIdx.x >> 5;
#pragma unroll
    for (int i = 0; i < 4; i++)
        tile[ty + i * 8][tx] = W[(size_t)(k0 + ty + i * 8) * N + n0 + tx];
    __syncthreads();
#pragma unroll
    for (int i = 0; i < 4; i++) {
        int r = ty + i * 8;
        T[(size_t)(rowoff + n0 + r) * K + k0 + tx] =
            __float2half_rn(tile[tx][r] * scale);
    }
}

__global__ __launch_bounds__(256) void bias_pack_kernel(
    const float* __restrict__ bq, const float* __restrict__ bk,
    const float* __restrict__ bv, float scale)
{
    int i = blockIdx.x * 256 + threadIdx.x;
    if (i < HID)              g_bias[i] = bq[i] * scale;
    else if (i < HID + KVDIM) g_bias[i] = bk[i - HID];
    else if (i < QKVS)        g_bias[i] = bv[i - HID - KVDIM];
}

// ---------------------------------------------------------------------------
// Flash attention (unchanged from round 7)
// ---------------------------------------------------------------------------
#define FP       136
#define Q_HALVES (128 * FP)
#define KV_HALVES (64 * FP)
#define FA_SMEM  ((Q_HALVES + 4 * KV_HALVES) * 2)   // 104448 B

__global__ __launch_bounds__(256, 1) void flash_tc_kernel()
{
    extern __shared__ __half sh[];
    __half* Qh  = sh;
    __half* Kst = sh + Q_HALVES;
    __half* Vst = sh + Q_HALVES + 2 * KV_HALVES;

    const int tid  = threadIdx.x;
    const int lane = tid & 31;
    const int w    = tid >> 5;
    const int g    = lane >> 2;
    const int tg   = lane & 3;

    const int qtile = blockIdx.x;
    const int h     = blockIdx.y;
    const int b     = blockIdx.z;
    const int kvh   = h / REP;

    const __half* qbase = g_qkv + (size_t)(b * SEQ + qtile * 128) * QKVS + h * HD;
    const __half* kroot = g_qkv + (size_t)(b * SEQ) * QKVS + HID + kvh * HD;
    const __half* vroot = g_qkv + (size_t)(b * SEQ) * QKVS + HID + KVDIM + kvh * HD;

#pragma unroll
    for (int it = 0; it < 8; it++) {
        int idx = it * 256 + tid;
        int r  = idx >> 4;
        int d0 = (idx & 15) * 8;
        *(uint4*)(Qh + r * FP + d0) = *(const uint4*)(qbase + (size_t)r * QKVS + d0);
    }

    auto issue = [&](int kt, int stg) {
        const __half* kb_ = kroot + (size_t)(kt * 64) * QKVS;
        const __half* vb_ = vroot + (size_t)(kt * 64) * QKVS;
        __half* kd = Kst + stg * KV_HALVES;
        __half* vd = Vst + stg * KV_HALVES;
#pragma unroll
        for (int it = 0; it < 4; it++) {
            int idx = it * 256 + tid;
            int r  = idx >> 4;
            int d0 = (idx & 15) * 8;
            cp_async16(kd + r * FP + d0, kb_ + (size_t)r * QKVS + d0);
            cp_async16(vd + r * FP + d0, vb_ + (size_t)r * QKVS + d0);
        }
        CP_COMMIT();
    };

    issue(0, 0);
    __syncthreads();

    uint32_t qf[8][4];
    {
        const int r0 = w * 16 + g;
#pragma unroll
        for (int ks = 0; ks < 8; ks++) {
            const int c0 = ks * 16 + tg * 2;
            qf[ks][0] = *(const uint32_t*)(Qh + r0 * FP + c0);
            qf[ks][1] = *(const uint32_t*)(Qh + (r0 + 8) * FP + c0);
            qf[ks][2] = *(const uint32_t*)(Qh + r0 * FP + c0 + 8);
            qf[ks][3] = *(const uint32_t*)(Qh + (r0 + 8) * FP + c0 + 8);
        }
    }

    const int mat  = lane >> 3;
    const int mr   = lane & 7;
    const int k_ro = ((mat & 2) ? 8 : 0) + mr;
    const int k_co = (mat & 1) ? 8 : 0;
    const int v_ro = ((mat & 1) ? 8 : 0) + mr;
    const int v_co = (mat & 2) ? 8 : 0;

    const uint32_t ksm = (uint32_t)__cvta_generic_to_shared(Kst);
    const uint32_t vsm = (uint32_t)__cvta_generic_to_shared(Vst);

    float m0 = -INFINITY, m1 = -INFINITY, l0 = 0.f, l1 = 0.f;
    float acc_o[16][4];
#pragma unroll
    for (int nb = 0; nb < 16; nb++)
#pragma unroll
        for (int t = 0; t < 4; t++) acc_o[nb][t] = 0.f;

    for (int kt = 0; kt < SEQ / 64; kt++) {
        CP_WAIT0();
        __syncthreads();
        if (kt + 1 < SEQ / 64) issue(kt + 1, (kt + 1) & 1);
        const int sb = kt & 1;
        const uint32_t kS = ksm + sb * KV_HALVES * 2;
        const uint32_t vS = vsm + sb * KV_HALVES * 2;

        float acc_s[8][4];
#pragma unroll
        for (int ni = 0; ni < 8; ni++)
#pragma unroll
            for (int t = 0; t < 4; t++) acc_s[ni][t] = 0.f;

#pragma unroll
        for (int ks = 0; ks < 8; ks++) {
            const int c0 = ks * 16;
#pragma unroll
            for (int np = 0; np < 4; np++) {
                uint32_t r0, r1, r2, r3;
                ldmx4(r0, r1, r2, r3,
                      kS + (uint32_t)(((np * 16 + k_ro) * FP + c0 + k_co) * 2));
                uint32_t b0[2] = {r0, r1};
                uint32_t b1[2] = {r2, r3};
                mma16816_f16(acc_s[2 * np],     qf[ks], b0);
                mma16816_f16(acc_s[2 * np + 1], qf[ks], b1);
            }
        }

        {
            float mx0 = -INFINITY, mx1 = -INFINITY;
#pragma unroll
            for (int ni = 0; ni < 8; ni++) {
                mx0 = fmaxf(mx0, fmaxf(acc_s[ni][0], acc_s[ni][1]));
                mx1 = fmaxf(mx1, fmaxf(acc_s[ni][2], acc_s[ni][3]));
            }
            mx0 = fmaxf(mx0, __shfl_xor_sync(0xffffffffu, mx0, 1));
            mx0 = fmaxf(mx0, __shfl_xor_sync(0xffffffffu, mx0, 2));
            mx1 = fmaxf(mx1, __shfl_xor_sync(0xffffffffu, mx1, 1));
            mx1 = fmaxf(mx1, __shfl_xor_sync(0xffffffffu, mx1, 2));

            float mn0 = fmaxf(m0, mx0);
            float mn1 = fmaxf(m1, mx1);
            float corr0 = __expf(m0 - mn0);
            float corr1 = __expf(m1 - mn1);

            float s0 = 0.f, s1 = 0.f;
#pragma unroll
            for (int ni = 0; ni < 8; ni++) {
                acc_s[ni][0] = __expf(acc_s[ni][0] - mn0);
                acc_s[ni][1] = __expf(acc_s[ni][1] - mn0);
                acc_s[ni][2] = __expf(acc_s[ni][2] - mn1);
                acc_s[ni][3] = __expf(acc_s[ni][3] - mn1);
                s0 += acc_s[ni][0] + acc_s[ni][1];
                s1 += acc_s[ni][2] + acc_s[ni][3];
            }
            s0 += __shfl_xor_sync(0xffffffffu, s0, 1);
            s0 += __shfl_xor_sync(0xffffffffu, s0, 2);
            s1 += __shfl_xor_sync(0xffffffffu, s1, 1);
            s1 += __shfl_xor_sync(0xffffffffu, s1, 2);

            l0 = l0 * corr0 + s0;
            l1 = l1 * corr1 + s1;
            m0 = mn0;
            m1 = mn1;

#pragma unroll
            for (int nb = 0; nb < 16; nb++) {
                acc_o[nb][0] *= corr0; acc_o[nb][1] *= corr0;
                acc_o[nb][2] *= corr1; acc_o[nb][3] *= corr1;
            }
        }

        uint32_t pf[4][4];
#pragma unroll
        for (int kb = 0; kb < 4; kb++) {
            pf[kb][0] = pack_h2(acc_s[2 * kb][0],     acc_s[2 * kb][1]);
            pf[kb][1] = pack_h2(acc_s[2 * kb][2],     acc_s[2 * kb][3]);
            pf[kb][2] = pack_h2(acc_s[2 * kb + 1][0], acc_s[2 * kb + 1][1]);
            pf[kb][3] = pack_h2(acc_s[2 * kb + 1][2], acc_s[2 * kb + 1][3]);
        }

#pragma unroll
        for (int ks = 0; ks < 4; ks++) {
            const int c0 = ks * 16;
#pragma unroll
            for (int nb = 0; nb < 8; nb++) {
                uint32_t r0, r1, r2, r3;
                ldmx4t(r0, r1, r2, r3,
                       vS + (uint32_t)(((c0 + v_ro) * FP + nb * 16 + v_co) * 2));
                uint32_t b0[2] = {r0, r1};
                uint32_t b1[2] = {r2, r3};
                mma16816_f16(acc_o[2 * nb],     pf[ks], b0);
                mma16816_f16(acc_o[2 * nb + 1], pf[ks], b1);
            }
        }
    }

    {
        const float inv0 = 1.0f / l0;
        const float inv1 = 1.0f / l1;
        const size_t tok0 = (size_t)(b * SEQ + qtile * 128 + w * 16 + g);
#pragma unroll
        for (int nb = 0; nb < 16; nb++) {
            const int col = nb * 8 + tg * 2;
            *(__half2*)(g_ao + tok0 * HID + h * HD + col) =
                __floats2half2_rn(acc_o[nb][0] * inv0, acc_o[nb][1] * inv0);
            *(__half2*)(g_ao + (tok0 + 8) * HID + h * HD + col) =
                __floats2half2_rn(acc_o[nb][2] * inv1, acc_o[nb][3] * inv1);
        }
    }
}

// ---------------------------------------------------------------------------
// kernel_launch
// ---------------------------------------------------------------------------
extern "C" void kernel_launch(void* const* d_in, const int* in_sizes, int n_in,
                              void* d_out, int out_size)
{
    (void)in_sizes; (void)n_in; (void)out_size;
    const float* hidden = (const float*)d_in[0];
    const float* Wq = (const float*)d_in[1];
    const float* bq = (const float*)d_in[2];
    const float* Wk = (const float*)d_in[3];
    const float* bk = (const float*)d_in[4];
    const float* Wv = (const float*)d_in[5];
    const float* bv = (const float*)d_in[6];
    const float* Wo = (const float*)d_in[7];
    const float* bo = (const float*)d_in[8];
    float* out = (float*)d_out;

    __half *ah, *qkv, *ao, *wt, *wot;
    float* biasp;
    cudaGetSymbolAddress((void**)&ah,    g_ah);
    cudaGetSymbolAddress((void**)&qkv,   g_qkv);
    cudaGetSymbolAddress((void**)&ao,    g_ao);
    cudaGetSymbolAddress((void**)&wt,    g_wt);
    cudaGetSymbolAddress((void**)&wot,   g_wo_t);
    cudaGetSymbolAddress((void**)&biasp, g_bias);

    static int attr_set = 0;
    if (!attr_set) {
        cudaFuncSetAttribute(flash_tc_kernel,
                             cudaFuncAttributeMaxDynamicSharedMemorySize, FA_SMEM);
        cudaFuncSetAttribute(gemm_h_kernel,
                             cudaFuncAttributeMaxDynamicSharedMemorySize, GEMM_SMEM);
        attr_set = 1;
    }

    const float scaling = 0.08838834764831845f;  // 128^-0.5

    // 1) prep
    convert_h_kernel<<<(BS_ROWS * HID / 8) / 256, 256>>>(hidden, ah);
    transpose_h_kernel<<<dim3(HID / 32,   HID / 32), 256>>>(Wq, wt,  HID, HID,   0,           scaling);
    transpose_h_kernel<<<dim3(KVDIM / 32, HID / 32), 256>>>(Wk, wt,  HID, KVDIM, HID,         1.0f);
    transpose_h_kernel<<<dim3(KVDIM / 32, HID / 32), 256>>>(Wv, wt,  HID, KVDIM, HID + KVDIM, 1.0f);
    transpose_h_kernel<<<dim3(HID / 32,   HID / 32), 256>>>(Wo, wot, HID, HID,   0,           1.0f);
    bias_pack_kernel<<<QKVS / 256, 256>>>(bq, bk, bv, scaling);

    // 2) fused QKV projection
    gemm_h_kernel<<<dim3(QKVS / 128, BS_ROWS / 128), 256, GEMM_SMEM>>>(
        ah, wt, biasp, nullptr, qkv, QKVS, HID);

    // 3) flash attention
    flash_tc_kernel<<<dim3(SEQ / 128, NH, BATCH), 256, FA_SMEM>>>();

    // 4) O-projection
    gemm_h_kernel<<<dim3(HID / 128, BS_ROWS / 128), 256, GEMM_SMEM>>>(
        ao, wot, bo, out, nullptr, HID, HID);
}

// round 9
// speedup vs baseline: 8.1790x; 1.0660x over previous
#include <cuda_runtime.h>
#include <cuda_fp16.h>
#include <math.h>
#include <stdint.h>

// ---------------------------------------------------------------------------
// MultiQueryAttention: B=2, S=2048, HIDDEN=2048, NH=16, NKV=2, D=128
// Round 9: flash -> 64-row/128-thread CTAs @2/SM (tail fix);
//          GEMM -> 3-stage cp.async ring, 1 sync/chunk; prep fused.
// ---------------------------------------------------------------------------

#define BATCH      2
#define SEQ        2048
#define HID        2048
#define NH         16
#define NKV        2
#define HD         128
#define KVDIM      (NKV * HD)          // 256
#define QKVS       (HID + 2 * KVDIM)   // 2560
#define BS_ROWS    (BATCH * SEQ)       // 4096
#define REP        (NH / NKV)          // 8

// ---------------- scratch ----------------
__device__ __half g_ah  [BS_ROWS * HID];
__device__ __half g_qkv [BS_ROWS * QKVS];
__device__ __half g_ao  [BS_ROWS * HID];
__device__ __half g_wt  [QKVS * HID];
__device__ __half g_wo_t[HID * HID];
__device__ float  g_bias[QKVS];

// ---------------------------------------------------------------------------
// PTX helpers
// ---------------------------------------------------------------------------
static __device__ __forceinline__ void mma16816_f16(
    float* d, const uint32_t* a, const uint32_t* b)
{
    asm volatile(
        "mma.sync.aligned.m16n8k16.row.col.f32.f16.f16.f32 "
        "{%0,%1,%2,%3}, {%4,%5,%6,%7}, {%8,%9}, {%0,%1,%2,%3};"
        : "+f"(d[0]), "+f"(d[1]), "+f"(d[2]), "+f"(d[3])
        : "r"(a[0]), "r"(a[1]), "r"(a[2]), "r"(a[3]), "r"(b[0]), "r"(b[1]));
}
static __device__ __forceinline__ void ldmx4(
    uint32_t& r0, uint32_t& r1, uint32_t& r2, uint32_t& r3, uint32_t addr)
{
    asm volatile("ldmatrix.sync.aligned.m8n8.x4.shared.b16 {%0,%1,%2,%3}, [%4];"
        : "=r"(r0), "=r"(r1), "=r"(r2), "=r"(r3) : "r"(addr));
}
static __device__ __forceinline__ void ldmx4t(
    uint32_t& r0, uint32_t& r1, uint32_t& r2, uint32_t& r3, uint32_t addr)
{
    asm volatile("ldmatrix.sync.aligned.m8n8.x4.trans.shared.b16 {%0,%1,%2,%3}, [%4];"
        : "=r"(r0), "=r"(r1), "=r"(r2), "=r"(r3) : "r"(addr));
}
static __device__ __forceinline__ void cp_async16(void* sptr, const void* gptr) {
    uint32_t s = (uint32_t)__cvta_generic_to_shared(sptr);
    asm volatile("cp.async.cg.shared.global [%0], [%1], 16;"
                 :: "r"(s), "l"(gptr) : "memory");
}
#define CP_COMMIT() asm volatile("cp.async.commit_group;" ::: "memory")
#define CP_WAIT0()  asm volatile("cp.async.wait_group 0;" ::: "memory")
#define CP_WAIT1()  asm volatile("cp.async.wait_group 1;" ::: "memory")

static __device__ __forceinline__ uint32_t pack_h2(float a, float b) {
    __half2 h = __floats2half2_rn(a, b);
    return *reinterpret_cast<uint32_t*>(&h);
}

// ---------------------------------------------------------------------------
// fp16 GEMM: C[M,N] = A[M,K] @ Bt[N,K]^T + bias[N]  (fp32 accum)
// CTA 128x128, BK=64, cp.async 3-stage ring (1 sync per chunk), 8 warps 2x4.
// ---------------------------------------------------------------------------
#define PITCH 72
#define BK    64
#define OPB   (128 * PITCH * 2)    // 18432 B
#define STG   (2 * OPB)            // 36864 B per stage
#define GEMM_SMEM (3 * STG)        // 110592 B

__global__ __launch_bounds__(256, 2) void gemm_h_kernel(
    const __half* __restrict__ A, const __half* __restrict__ Bt,
    const float* __restrict__ bias, float* __restrict__ C,
    __half* __restrict__ Ch, int N, int K)
{
    extern __shared__ char gsm[];

    const int tid    = threadIdx.x;
    const int lane   = tid & 31;
    const int wid    = tid >> 5;
    const int warp_m = wid >> 2;
    const int warp_n = wid & 3;
    const int g      = lane >> 2;
    const int tg     = lane & 3;

    const int blockRow = blockIdx.y * 128;
    const int blockCol = blockIdx.x * 128;

    const int mat = lane >> 3;
    const int mr  = lane & 7;
    const int a_ro = ((mat & 1) ? 8 : 0) + mr;
    const int a_co = (mat & 2) ? 8 : 0;
    const int b_ro = ((mat & 2) ? 8 : 0) + mr;
    const int b_co = (mat & 1) ? 8 : 0;

    const uint32_t gbase = (uint32_t)__cvta_generic_to_shared(gsm);

    float acc[4][4][4];
#pragma unroll
    for (int mi = 0; mi < 4; mi++)
#pragma unroll
        for (int ni = 0; ni < 4; ni++)
#pragma unroll
            for (int t = 0; t < 4; t++) acc[mi][ni][t] = 0.f;

    const int nch = K / BK;   // 32

    auto issue = [&](int c, int stg) {
        char* base = gsm + stg * STG;
#pragma unroll
        for (int it = 0; it < 4; it++) {
            int idx = it * 256 + tid;
            int m  = idx >> 3;
            int kq = idx & 7;
            int so = (m * PITCH + kq * 8) * 2;
            cp_async16(base + so,
                       A + (size_t)(blockRow + m) * K + c * BK + kq * 8);
            cp_async16(base + OPB + so,
                       Bt + (size_t)(blockCol + m) * K + c * BK + kq * 8);
        }
        CP_COMMIT();
    };

    issue(0, 0);
    issue(1, 1);

    int stg = 0;
    for (int c = 0; c < nch; c++) {
        CP_WAIT1();          // oldest outstanding group (chunk c) complete
        __syncthreads();     // all warps done reading stage being refilled
        if (c + 2 < nch) {
            int s2 = stg + 2; if (s2 >= 3) s2 -= 3;
            issue(c + 2, s2);
        } else {
            CP_COMMIT();     // empty group keeps wait_group 1 semantics uniform
        }

        const uint32_t aS = gbase + stg * STG;
        const uint32_t bS = aS + OPB;

#pragma unroll
        for (int ks = 0; ks < 4; ks++) {
            const int c0 = ks * 16;
            uint32_t av[4][4];
#pragma unroll
            for (int mi = 0; mi < 4; mi++) {
                const int r = warp_m * 64 + mi * 16 + a_ro;
                ldmx4(av[mi][0], av[mi][1], av[mi][2], av[mi][3],
                      aS + (uint32_t)((r * PITCH + c0 + a_co) * 2));
            }
            uint32_t bv[2][4];
#pragma unroll
            for (int np = 0; np < 2; np++) {
                const int n = warp_n * 32 + np * 16 + b_ro;
                ldmx4(bv[np][0], bv[np][1], bv[np][2], bv[np][3],
                      bS + (uint32_t)((n * PITCH + c0 + b_co) * 2));
            }
#pragma unroll
            for (int ni = 0; ni < 4; ni++) {
                uint32_t bb[2] = { bv[ni >> 1][(ni & 1) * 2],
                                   bv[ni >> 1][(ni & 1) * 2 + 1] };
#pragma unroll
                for (int mi = 0; mi < 4; mi++)
                    mma16816_f16(acc[mi][ni], av[mi], bb);
            }
        }
        stg = (stg + 1 == 3) ? 0 : stg + 1;
    }

#pragma unroll
    for (int mi = 0; mi < 4; mi++) {
#pragma unroll
        for (int ni = 0; ni < 4; ni++) {
            int row0 = blockRow + warp_m * 64 + mi * 16 + g;
            int col  = blockCol + warp_n * 32 + ni * 8 + tg * 2;
            float2 b2 = *(const float2*)(bias + col);
            float2 o0, o1;
            o0.x = acc[mi][ni][0] + b2.x;
            o0.y = acc[mi][ni][1] + b2.y;
            o1.x = acc[mi][ni][2] + b2.x;
            o1.y = acc[mi][ni][3] + b2.y;
            if (C) {
                *(float2*)(C + (size_t)row0 * N + col)       = o0;
                *(float2*)(C + (size_t)(row0 + 8) * N + col) = o1;
            }
            if (Ch) {
                *(__half2*)(Ch + (size_t)row0 * N + col) =
                    __floats2half2_rn(o0.x, o0.y);
                *(__half2*)(Ch + (size_t)(row0 + 8) * N + col) =
                    __floats2half2_rn(o1.x, o1.y);
            }
        }
    }
}

// ---------------------------------------------------------------------------
// prep: hidden fp32 -> fp16
// ---------------------------------------------------------------------------
__global__ __launch_bounds__(256) void convert_h_kernel(
    const float* __restrict__ X, __half* __restrict__ Y)
{
    size_t base = ((size_t)blockIdx.x * 256 + threadIdx.x) * 8;
    float4 a = *(const float4*)(X + base);
    float4 b = *(const float4*)(X + base + 4);
    __half h[8];
    h[0] = __float2half_rn(a.x); h[1] = __float2half_rn(a.y);
    h[2] = __float2half_rn(a.z); h[3] = __float2half_rn(a.w);
    h[4] = __float2half_rn(b.x); h[5] = __float2half_rn(b.y);
    h[6] = __float2half_rn(b.z); h[7] = __float2half_rn(b.w);
    *(uint4*)(Y + base) = *(uint4*)h;
}

// ---------------------------------------------------------------------------
// prep: ALL weight transposes + bias pack in one launch.
// grid (145, 64): x<144 -> 32x32 transpose tiles over packed rows
// [Wq | Wk | Wv | Wo] (all boundaries 32-aligned); x==144,y==0 -> bias pack.
// ---------------------------------------------------------------------------
__global__ __launch_bounds__(256) void prep_w_kernel(
    const float* __restrict__ Wq, const float* __restrict__ Wk,
    const float* __restrict__ Wv, const float* __restrict__ Wo,
    const float* __restrict__ bq, const float* __restrict__ bk,
    const float* __restrict__ bv, float scaling)
{
    if (blockIdx.x == 144) {
        if (blockIdx.y == 0) {
            for (int j = threadIdx.x; j < QKVS; j += 256) {
                g_bias[j] = (j < HID) ? bq[j] * scaling
                          : (j < HID + KVDIM) ? bk[j - HID]
                          : bv[j - HID - KVDIM];
            }
        }
        return;
    }

    const int nglob = blockIdx.x * 32;   // packed row base 0..4607
    const float* W; int srcN; int col0; float scale; __half* dst; int drow;
    if (nglob < HID)              { W = Wq; srcN = HID;   col0 = nglob;               scale = scaling; dst = g_wt;   drow = nglob; }
    else if (nglob < HID + KVDIM) { W = Wk; srcN = KVDIM; col0 = nglob - HID;         scale = 1.f;     dst = g_wt;   drow = nglob; }
    else if (nglob < QKVS)        { W = Wv; srcN = KVDIM; col0 = nglob - HID - KVDIM; scale = 1.f;     dst = g_wt;   drow = nglob; }
    else                          { W = Wo; srcN = HID;   col0 = nglob - QKVS;        scale = 1.f;     dst = g_wo_t; drow = nglob - QKVS; }

    __shared__ float tile[32][33];
    const int k0 = blockIdx.y * 32;
    const int tx = threadIdx.x & 31;
    const int ty = threadIdx.x >> 5;
#pragma unroll
    for (int i = 0; i < 4; i++)
        tile[ty + i * 8][tx] = W[(size_t)(k0 + ty + i * 8) * srcN + col0 + tx];
    __syncthreads();
#pragma unroll
    for (int i = 0; i < 4; i++) {
        int r = ty + i * 8;
        dst[(size_t)(drow + r) * HID + k0 + tx] =
            __float2half_rn(tile[tx][r] * scale);
    }
}

// ---------------------------------------------------------------------------
// Flash attention: 64 q-rows / 128 threads / 4 warps per CTA, 2 CTAs/SM.
// Per-warp code identical to round 7/8 (warp owns 16 rows, full stripes).
// ---------------------------------------------------------------------------
#define FP        136
#define Q_HALVES  (64 * FP)              // 8704
#define KV_HALVES (64 * FP)              // 8704
#define FA_SMEM   ((Q_HALVES + 4 * KV_HALVES) * 2)   // 87040 B

__global__ __launch_bounds__(128, 2) void flash_tc_kernel()
{
    extern __shared__ __half sh[];
    __half* Qh  = sh;
    __half* Kst = sh + Q_HALVES;
    __half* Vst = sh + Q_HALVES + 2 * KV_HALVES;

    const int tid  = threadIdx.x;
    const int lane = tid & 31;
    const int w    = tid >> 5;      // 0..3 -> q rows w*16..+15
    const int g    = lane >> 2;
    const int tg   = lane & 3;

    const int qtile = blockIdx.x;   // 0..31 (64 rows each)
    const int h     = blockIdx.y;
    const int b     = blockIdx.z;
    const int kvh   = h / REP;

    const __half* qbase = g_qkv + (size_t)(b * SEQ + qtile * 64) * QKVS + h * HD;
    const __half* kroot = g_qkv + (size_t)(b * SEQ) * QKVS + HID + kvh * HD;
    const __half* vroot = g_qkv + (size_t)(b * SEQ) * QKVS + HID + KVDIM + kvh * HD;

    // Q tile: 64 x 128 halves = 1024 uint4, 128 threads -> 8 iters
#pragma unroll
    for (int it = 0; it < 8; it++) {
        int idx = it * 128 + tid;
        int r  = idx >> 4;
        int d0 = (idx & 15) * 8;
        *(uint4*)(Qh + r * FP + d0) = *(const uint4*)(qbase + (size_t)r * QKVS + d0);
    }

    auto issue = [&](int kt, int stg) {
        const __half* kb_ = kroot + (size_t)(kt * 64) * QKVS;
        const __half* vb_ = vroot + (size_t)(kt * 64) * QKVS;
        __half* kd = Kst + stg * KV_HALVES;
        __half* vd = Vst + stg * KV_HALVES;
#pragma unroll
        for (int it = 0; it < 8; it++) {
            int idx = it * 128 + tid;
            int r  = idx >> 4;
            int d0 = (idx & 15) * 8;
            cp_async16(kd + r * FP + d0, kb_ + (size_t)r * QKVS + d0);
            cp_async16(vd + r * FP + d0, vb_ + (size_t)r * QKVS + d0);
        }
        CP_COMMIT();
    };

    issue(0, 0);
    __syncthreads();

    uint32_t qf[8][4];
    {
        const int r0 = w * 16 + g;
#pragma unroll
        for (int ks = 0; ks < 8; ks++) {
            const int c0 = ks * 16 + tg * 2;
            qf[ks][0] = *(const uint32_t*)(Qh + r0 * FP + c0);
            qf[ks][1] = *(const uint32_t*)(Qh + (r0 + 8) * FP + c0);
            qf[ks][2] = *(const uint32_t*)(Qh + r0 * FP + c0 + 8);
            qf[ks][3] = *(const uint32_t*)(Qh + (r0 + 8) * FP + c0 + 8);
        }
    }

    const int mat  = lane >> 3;
    const int mr   = lane & 7;
    const int k_ro = ((mat & 2) ? 8 : 0) + mr;
    const int k_co = (mat & 1) ? 8 : 0;
    const int v_ro = ((mat & 1) ? 8 : 0) + mr;
    const int v_co = (mat & 2) ? 8 : 0;

    const uint32_t ksm = (uint32_t)__cvta_generic_to_shared(Kst);
    const uint32_t vsm = (uint32_t)__cvta_generic_to_shared(Vst);

    float m0 = -INFINITY, m1 = -INFINITY, l0 = 0.f, l1 = 0.f;
    float acc_o[16][4];
#pragma unroll
    for (int nb = 0; nb < 16; nb++)
#pragma unroll
        for (int t = 0; t < 4; t++) acc_o[nb][t] = 0.f;

    for (int kt = 0; kt < SEQ / 64; kt++) {
        CP_WAIT0();
        __syncthreads();
        if (kt + 1 < SEQ / 64) issue(kt + 1, (kt + 1) & 1);
        const int sb = kt & 1;
        const uint32_t kS = ksm + sb * KV_HALVES * 2;
        const uint32_t vS = vsm + sb * KV_HALVES * 2;

        float acc_s[8][4];
#pragma unroll
        for (int ni = 0; ni < 8; ni++)
#pragma unroll
            for (int t = 0; t < 4; t++) acc_s[ni][t] = 0.f;

#pragma unroll
        for (int ks = 0; ks < 8; ks++) {
            const int c0 = ks * 16;
#pragma unroll
            for (int np = 0; np < 4; np++) {
                uint32_t r0, r1, r2, r3;
                ldmx4(r0, r1, r2, r3,
                      kS + (uint32_t)(((np * 16 + k_ro) * FP + c0 + k_co) * 2));
                uint32_t b0[2] = {r0, r1};
                uint32_t b1[2] = {r2, r3};
                mma16816_f16(acc_s[2 * np],     qf[ks], b0);
                mma16816_f16(acc_s[2 * np + 1], qf[ks], b1);
            }
        }

        {
            float mx0 = -INFINITY, mx1 = -INFINITY;
#pragma unroll
            for (int ni = 0; ni < 8; ni++) {
                mx0 = fmaxf(mx0, fmaxf(acc_s[ni][0], acc_s[ni][1]));
                mx1 = fmaxf(mx1, fmaxf(acc_s[ni][2], acc_s[ni][3]));
            }
            mx0 = fmaxf(mx0, __shfl_xor_sync(0xffffffffu, mx0, 1));
            mx0 = fmaxf(mx0, __shfl_xor_sync(0xffffffffu, mx0, 2));
            mx1 = fmaxf(mx1, __shfl_xor_sync(0xffffffffu, mx1, 1));
            mx1 = fmaxf(mx1, __shfl_xor_sync(0xffffffffu, mx1, 2));

            float mn0 = fmaxf(m0, mx0);
            float mn1 = fmaxf(m1, mx1);
            float corr0 = __expf(m0 - mn0);
            float corr1 = __expf(m1 - mn1);

            float s0 = 0.f, s1 = 0.f;
#pragma unroll
            for (int ni = 0; ni < 8; ni++) {
                acc_s[ni][0] = __expf(acc_s[ni][0] - mn0);
                acc_s[ni][1] = __expf(acc_s[ni][1] - mn0);
                acc_s[ni][2] = __expf(acc_s[ni][2] - mn1);
                acc_s[ni][3] = __expf(acc_s[ni][3] - mn1);
                s0 += acc_s[ni][0] + acc_s[ni][1];
                s1 += acc_s[ni][2] + acc_s[ni][3];
            }
            s0 += __shfl_xor_sync(0xffffffffu, s0, 1);
            s0 += __shfl_xor_sync(0xffffffffu, s0, 2);
            s1 += __shfl_xor_sync(0xffffffffu, s1, 1);
            s1 += __shfl_xor_sync(0xffffffffu, s1, 2);

            l0 = l0 * corr0 + s0;
            l1 = l1 * corr1 + s1;
            m0 = mn0;
            m1 = mn1;

#pragma unroll
            for (int nb = 0; nb < 16; nb++) {
                acc_o[nb][0] *= corr0; acc_o[nb][1] *= corr0;
                acc_o[nb][2] *= corr1; acc_o[nb][3] *= corr1;
            }
        }

        uint32_t pf[4][4];
#pragma unroll
        for (int kb = 0; kb < 4; kb++) {
            pf[kb][0] = pack_h2(acc_s[2 * kb][0],     acc_s[2 * kb][1]);
            pf[kb][1] = pack_h2(acc_s[2 * kb][2],     acc_s[2 * kb][3]);
            pf[kb][2] = pack_h2(acc_s[2 * kb + 1][0], acc_s[2 * kb + 1][1]);
            pf[kb][3] = pack_h2(acc_s[2 * kb + 1][2], acc_s[2 * kb + 1][3]);
        }

#pragma unroll
        for (int ks = 0; ks < 4; ks++) {
            const int c0 = ks * 16;
#pragma unroll
            for (int nb = 0; nb < 8; nb++) {
                uint32_t r0, r1, r2, r3;
                ldmx4t(r0, r1, r2, r3,
                       vS + (uint32_t)(((c0 + v_ro) * FP + nb * 16 + v_co) * 2));
                uint32_t b0[2] = {r0, r1};
                uint32_t b1[2] = {r2, r3};
                mma16816_f16(acc_o[2 * nb],     pf[ks], b0);
                mma16816_f16(acc_o[2 * nb + 1], pf[ks], b1);
            }
        }
    }

    {
        const float inv0 = 1.0f / l0;
        const float inv1 = 1.0f / l1;
        const size_t tok0 = (size_t)(b * SEQ + qtile * 64 + w * 16 + g);
#pragma unroll
        for (int nb = 0; nb < 16; nb++) {
            const int col = nb * 8 + tg * 2;
            *(__half2*)(g_ao + tok0 * HID + h * HD + col) =
                __floats2half2_rn(acc_o[nb][0] * inv0, acc_o[nb][1] * inv0);
            *(__half2*)(g_ao + (tok0 + 8) * HID + h * HD + col) =
                __floats2half2_rn(acc_o[nb][2] * inv1, acc_o[nb][3] * inv1);
        }
    }
}

// ---------------------------------------------------------------------------
// kernel_launch
// ---------------------------------------------------------------------------
extern "C" void kernel_launch(void* const* d_in, const int* in_sizes, int n_in,
                              void* d_out, int out_size)
{
    (void)in_sizes; (void)n_in; (void)out_size;
    const float* hidden = (const float*)d_in[0];
    const float* Wq = (const float*)d_in[1];
    const float* bq = (const float*)d_in[2];
    const float* Wk = (const float*)d_in[3];
    const float* bk = (const float*)d_in[4];
    const float* Wv = (const float*)d_in[5];
    const float* bv = (const float*)d_in[6];
    const float* Wo = (const float*)d_in[7];
    const float* bo = (const float*)d_in[8];
    float* out = (float*)d_out;

    __half *ah, *qkv, *ao, *wt, *wot;
    float* biasp;
    cudaGetSymbolAddress((void**)&ah,    g_ah);
    cudaGetSymbolAddress((void**)&qkv,   g_qkv);
    cudaGetSymbolAddress((void**)&ao,    g_ao);
    cudaGetSymbolAddress((void**)&wt,    g_wt);
    cudaGetSymbolAddress((void**)&wot,   g_wo_t);
    cudaGetSymbolAddress((void**)&biasp, g_bias);

    static int attr_set = 0;
    if (!attr_set) {
        cudaFuncSetAttribute(flash_tc_kernel,
                             cudaFuncAttributeMaxDynamicSharedMemorySize, FA_SMEM);
        cudaFuncSetAttribute(gemm_h_kernel,
                             cudaFuncAttributeMaxDynamicSharedMemorySize, GEMM_SMEM);
        attr_set = 1;
    }

    const float scaling = 0.08838834764831845f;  // 128^-0.5

    // 1) prep (2 launches)
    convert_h_kernel<<<(BS_ROWS * HID / 8) / 256, 256>>>(hidden, ah);
    prep_w_kernel<<<dim3(145, 64), 256>>>(Wq, Wk, Wv, Wo, bq, bk, bv, scaling);

    // 2) fused QKV projection
    gemm_h_kernel<<<dim3(QKVS / 128, BS_ROWS / 128), 256, GEMM_SMEM>>>(
        ah, wt, biasp, nullptr, qkv, QKVS, HID);

    // 3) flash attention (64-row CTAs, 2/SM)
    flash_tc_kernel<<<dim3(SEQ / 64, NH, BATCH), 128, FA_SMEM>>>();

    // 4) O-projection
    gemm_h_kernel<<<dim3(HID / 128, BS_ROWS / 128), 256, GEMM_SMEM>>>(
        ao, wot, bo, out, nullptr, HID, HID);
}

// round 10
// speedup vs baseline: 8.4066x; 1.0278x over previous
#include <cuda_runtime.h>
#include <cuda_fp16.h>
#include <math.h>
#include <stdint.h>

// ---------------------------------------------------------------------------
// MultiQueryAttention: B=2, S=2048, HIDDEN=2048, NH=16, NKV=2, D=128
// Round 10: flash software-pipelined (S(kt) || PV(kt-1) || softmax overlap),
//           V 3-stage ring, exp2 softmax. GEMMs/prep unchanged.
// ---------------------------------------------------------------------------

#define BATCH      2
#define SEQ        2048
#define HID        2048
#define NH         16
#define NKV        2
#define HD         128
#define KVDIM      (NKV * HD)          // 256
#define QKVS       (HID + 2 * KVDIM)   // 2560
#define BS_ROWS    (BATCH * SEQ)       // 4096
#define REP        (NH / NKV)          // 8

// ---------------- scratch ----------------
__device__ __half g_ah  [BS_ROWS * HID];
__device__ __half g_qkv [BS_ROWS * QKVS];
__device__ __half g_ao  [BS_ROWS * HID];
__device__ __half g_wt  [QKVS * HID];
__device__ __half g_wo_t[HID * HID];
__device__ float  g_bias[QKVS];

// ---------------------------------------------------------------------------
// PTX helpers
// ---------------------------------------------------------------------------
static __device__ __forceinline__ void mma16816_f16(
    float* d, const uint32_t* a, const uint32_t* b)
{
    asm volatile(
        "mma.sync.aligned.m16n8k16.row.col.f32.f16.f16.f32 "
        "{%0,%1,%2,%3}, {%4,%5,%6,%7}, {%8,%9}, {%0,%1,%2,%3};"
        : "+f"(d[0]), "+f"(d[1]), "+f"(d[2]), "+f"(d[3])
        : "r"(a[0]), "r"(a[1]), "r"(a[2]), "r"(a[3]), "r"(b[0]), "r"(b[1]));
}
static __device__ __forceinline__ void ldmx4(
    uint32_t& r0, uint32_t& r1, uint32_t& r2, uint32_t& r3, uint32_t addr)
{
    asm volatile("ldmatrix.sync.aligned.m8n8.x4.shared.b16 {%0,%1,%2,%3}, [%4];"
        : "=r"(r0), "=r"(r1), "=r"(r2), "=r"(r3) : "r"(addr));
}
static __device__ __forceinline__ void ldmx4t(
    uint32_t& r0, uint32_t& r1, uint32_t& r2, uint32_t& r3, uint32_t addr)
{
    asm volatile("ldmatrix.sync.aligned.m8n8.x4.trans.shared.b16 {%0,%1,%2,%3}, [%4];"
        : "=r"(r0), "=r"(r1), "=r"(r2), "=r"(r3) : "r"(addr));
}
static __device__ __forceinline__ void cp_async16(void* sptr, const void* gptr) {
    uint32_t s = (uint32_t)__cvta_generic_to_shared(sptr);
    asm volatile("cp.async.cg.shared.global [%0], [%1], 16;"
                 :: "r"(s), "l"(gptr) : "memory");
}
#define CP_COMMIT() asm volatile("cp.async.commit_group;" ::: "memory")
#define CP_WAIT0()  asm volatile("cp.async.wait_group 0;" ::: "memory")
#define CP_WAIT1()  asm volatile("cp.async.wait_group 1;" ::: "memory")

static __device__ __forceinline__ uint32_t pack_h2(float a, float b) {
    __half2 h = __floats2half2_rn(a, b);
    return *reinterpret_cast<uint32_t*>(&h);
}
static __device__ __forceinline__ float ex2f(float x) {
    float r;
    asm("ex2.approx.ftz.f32 %0, %1;" : "=f"(r) : "f"(x));
    return r;
}

// ---------------------------------------------------------------------------
// fp16 GEMM (unchanged from round 9): 3-stage cp.async ring, 1 sync/chunk.
// ---------------------------------------------------------------------------
#define PITCH 72
#define BK    64
#define OPB   (128 * PITCH * 2)
#define STG   (2 * OPB)
#define GEMM_SMEM (3 * STG)

__global__ __launch_bounds__(256, 2) void gemm_h_kernel(
    const __half* __restrict__ A, const __half* __restrict__ Bt,
    const float* __restrict__ bias, float* __restrict__ C,
    __half* __restrict__ Ch, int N, int K)
{
    extern __shared__ char gsm[];

    const int tid    = threadIdx.x;
    const int lane   = tid & 31;
    const int wid    = tid >> 5;
    const int warp_m = wid >> 2;
    const int warp_n = wid & 3;
    const int g      = lane >> 2;
    const int tg     = lane & 3;

    const int blockRow = blockIdx.y * 128;
    const int blockCol = blockIdx.x * 128;

    const int mat = lane >> 3;
    const int mr  = lane & 7;
    const int a_ro = ((mat & 1) ? 8 : 0) + mr;
    const int a_co = (mat & 2) ? 8 : 0;
    const int b_ro = ((mat & 2) ? 8 : 0) + mr;
    const int b_co = (mat & 1) ? 8 : 0;

    const uint32_t gbase = (uint32_t)__cvta_generic_to_shared(gsm);

    float acc[4][4][4];
#pragma unroll
    for (int mi = 0; mi < 4; mi++)
#pragma unroll
        for (int ni = 0; ni < 4; ni++)
#pragma unroll
            for (int t = 0; t < 4; t++) acc[mi][ni][t] = 0.f;

    const int nch = K / BK;

    auto issue = [&](int c, int stg) {
        char* base = gsm + stg * STG;
#pragma unroll
        for (int it = 0; it < 4; it++) {
            int idx = it * 256 + tid;
            int m  = idx >> 3;
            int kq = idx & 7;
            int so = (m * PITCH + kq * 8) * 2;
            cp_async16(base + so,
                       A + (size_t)(blockRow + m) * K + c * BK + kq * 8);
            cp_async16(base + OPB + so,
                       Bt + (size_t)(blockCol + m) * K + c * BK + kq * 8);
        }
        CP_COMMIT();
    };

    issue(0, 0);
    issue(1, 1);

    int stg = 0;
    for (int c = 0; c < nch; c++) {
        CP_WAIT1();
        __syncthreads();
        if (c + 2 < nch) {
            int s2 = stg + 2; if (s2 >= 3) s2 -= 3;
            issue(c + 2, s2);
        } else {
            CP_COMMIT();
        }

        const uint32_t aS = gbase + stg * STG;
        const uint32_t bS = aS + OPB;

#pragma unroll
        for (int ks = 0; ks < 4; ks++) {
            const int c0 = ks * 16;
            uint32_t av[4][4];
#pragma unroll
            for (int mi = 0; mi < 4; mi++) {
                const int r = warp_m * 64 + mi * 16 + a_ro;
                ldmx4(av[mi][0], av[mi][1], av[mi][2], av[mi][3],
                      aS + (uint32_t)((r * PITCH + c0 + a_co) * 2));
            }
            uint32_t bv[2][4];
#pragma unroll
            for (int np = 0; np < 2; np++) {
                const int n = warp_n * 32 + np * 16 + b_ro;
                ldmx4(bv[np][0], bv[np][1], bv[np][2], bv[np][3],
                      bS + (uint32_t)((n * PITCH + c0 + b_co) * 2));
            }
#pragma unroll
            for (int ni = 0; ni < 4; ni++) {
                uint32_t bb[2] = { bv[ni >> 1][(ni & 1) * 2],
                                   bv[ni >> 1][(ni & 1) * 2 + 1] };
#pragma unroll
                for (int mi = 0; mi < 4; mi++)
                    mma16816_f16(acc[mi][ni], av[mi], bb);
            }
        }
        stg = (stg + 1 == 3) ? 0 : stg + 1;
    }

#pragma unroll
    for (int mi = 0; mi < 4; mi++) {
#pragma unroll
        for (int ni = 0; ni < 4; ni++) {
            int row0 = blockRow + warp_m * 64 + mi * 16 + g;
            int col  = blockCol + warp_n * 32 + ni * 8 + tg * 2;
            float2 b2 = *(const float2*)(bias + col);
            float2 o0, o1;
            o0.x = acc[mi][ni][0] + b2.x;
            o0.y = acc[mi][ni][1] + b2.y;
            o1.x = acc[mi][ni][2] + b2.x;
            o1.y = acc[mi][ni][3] + b2.y;
            if (C) {
                *(float2*)(C + (size_t)row0 * N + col)       = o0;
                *(float2*)(C + (size_t)(row0 + 8) * N + col) = o1;
            }
            if (Ch) {
                *(__half2*)(Ch + (size_t)row0 * N + col) =
                    __floats2half2_rn(o0.x, o0.y);
                *(__half2*)(Ch + (size_t)(row0 + 8) * N + col) =
                    __floats2half2_rn(o1.x, o1.y);
            }
        }
    }
}

// ---------------------------------------------------------------------------
// prep kernels (unchanged)
// ---------------------------------------------------------------------------
__global__ __launch_bounds__(256) void convert_h_kernel(
    const float* __restrict__ X, __half* __restrict__ Y)
{
    size_t base = ((size_t)blockIdx.x * 256 + threadIdx.x) * 8;
    float4 a = *(const float4*)(X + base);
    float4 b = *(const float4*)(X + base + 4);
    __half h[8];
    h[0] = __float2half_rn(a.x); h[1] = __float2half_rn(a.y);
    h[2] = __float2half_rn(a.z); h[3] = __float2half_rn(a.w);
    h[4] = __float2half_rn(b.x); h[5] = __float2half_rn(b.y);
    h[6] = __float2half_rn(b.z); h[7] = __float2half_rn(b.w);
    *(uint4*)(Y + base) = *(uint4*)h;
}

__global__ __launch_bounds__(256) void prep_w_kernel(
    const float* __restrict__ Wq, const float* __restrict__ Wk,
    const float* __restrict__ Wv, const float* __restrict__ Wo,
    const float* __restrict__ bq, const float* __restrict__ bk,
    const float* __restrict__ bv, float scaling)
{
    if (blockIdx.x == 144) {
        if (blockIdx.y == 0) {
            for (int j = threadIdx.x; j < QKVS; j += 256) {
                g_bias[j] = (j < HID) ? bq[j] * scaling
                          : (j < HID + KVDIM) ? bk[j - HID]
                          : bv[j - HID - KVDIM];
            }
        }
        return;
    }

    const int nglob = blockIdx.x * 32;
    const float* W; int srcN; int col0; float scale; __half* dst; int drow;
    if (nglob < HID)              { W = Wq; srcN = HID;   col0 = nglob;               scale = scaling; dst = g_wt;   drow = nglob; }
    else if (nglob < HID + KVDIM) { W = Wk; srcN = KVDIM; col0 = nglob - HID;         scale = 1.f;     dst = g_wt;   drow = nglob; }
    else if (nglob < QKVS)        { W = Wv; srcN = KVDIM; col0 = nglob - HID - KVDIM; scale = 1.f;     dst = g_wt;   drow = nglob; }
    else                          { W = Wo; srcN = HID;   col0 = nglob - QKVS;        scale = 1.f;     dst = g_wo_t; drow = nglob - QKVS; }

    __shared__ float tile[32][33];
    const int k0 = blockIdx.y * 32;
    const int tx = threadIdx.x & 31;
    const int ty = threadIdx.x >> 5;
#pragma unroll
    for (int i = 0; i < 4; i++)
        tile[ty + i * 8][tx] = W[(size_t)(k0 + ty + i * 8) * srcN + col0 + tx];
    __syncthreads();
#pragma unroll
    for (int i = 0; i < 4; i++) {
        int r = ty + i * 8;
        dst[(size_t)(drow + r) * HID + k0 + tx] =
            __float2half_rn(tile[tx][r] * scale);
    }
}

// ---------------------------------------------------------------------------
// Flash attention, round-10: software-pipelined.
// Per iter kt: S(kt) MMAs -> PV(kt-1) MMAs -> softmax(kt) (overlaps PV) ->
// rescale acc_o -> pack pf(kt). K 2-stage, V 3-stage cp.async rings.
// 64 q-rows / 128 threads / 4 warps per CTA, 2 CTAs/SM.
// ---------------------------------------------------------------------------
#define FP        136
#define Q_HALVES  (64 * FP)
#define KV_HALVES (64 * FP)
#define FA_SMEM   ((Q_HALVES + 5 * KV_HALVES) * 2)   // 104448 B

__global__ __launch_bounds__(128, 2) void flash_tc_kernel()
{
    extern __shared__ __half sh[];
    __half* Qh  = sh;
    __half* Kst = sh + Q_HALVES;                   // 2 stages
    __half* Vst = sh + Q_HALVES + 2 * KV_HALVES;   // 3 stages

    const int tid  = threadIdx.x;
    const int lane = tid & 31;
    const int w    = tid >> 5;      // 0..3
    const int g    = lane >> 2;
    const int tg   = lane & 3;

    const int qtile = blockIdx.x;
    const int h     = blockIdx.y;
    const int b     = blockIdx.z;
    const int kvh   = h / REP;

    const __half* qbase = g_qkv + (size_t)(b * SEQ + qtile * 64) * QKVS + h * HD;
    const __half* kroot = g_qkv + (size_t)(b * SEQ) * QKVS + HID + kvh * HD;
    const __half* vroot = g_qkv + (size_t)(b * SEQ) * QKVS + HID + KVDIM + kvh * HD;

#pragma unroll
    for (int it = 0; it < 8; it++) {
        int idx = it * 128 + tid;
        int r  = idx >> 4;
        int d0 = (idx & 15) * 8;
        *(uint4*)(Qh + r * FP + d0) = *(const uint4*)(qbase + (size_t)r * QKVS + d0);
    }

    auto issue = [&](int kt) {
        const __half* kb_ = kroot + (size_t)(kt * 64) * QKVS;
        const __half* vb_ = vroot + (size_t)(kt * 64) * QKVS;
        __half* kd = Kst + (kt & 1) * KV_HALVES;
        __half* vd = Vst + (kt % 3) * KV_HALVES;
#pragma unroll
        for (int it = 0; it < 8; it++) {
            int idx = it * 128 + tid;
            int r  = idx >> 4;
            int d0 = (idx & 15) * 8;
            cp_async16(kd + r * FP + d0, kb_ + (size_t)r * QKVS + d0);
            cp_async16(vd + r * FP + d0, vb_ + (size_t)r * QKVS + d0);
        }
        CP_COMMIT();
    };

    issue(0);
    CP_WAIT0();
    __syncthreads();       // Q + K/V(0) visible to all warps
    issue(1);

    uint32_t qf[8][4];
    {
        const int r0 = w * 16 + g;
#pragma unroll
        for (int ks = 0; ks < 8; ks++) {
            const int c0 = ks * 16 + tg * 2;
            qf[ks][0] = *(const uint32_t*)(Qh + r0 * FP + c0);
            qf[ks][1] = *(const uint32_t*)(Qh + (r0 + 8) * FP + c0);
            qf[ks][2] = *(const uint32_t*)(Qh + r0 * FP + c0 + 8);
            qf[ks][3] = *(const uint32_t*)(Qh + (r0 + 8) * FP + c0 + 8);
        }
    }

    const int mat  = lane >> 3;
    const int mr   = lane & 7;
    const int k_ro = ((mat & 2) ? 8 : 0) + mr;
    const int k_co = (mat & 1) ? 8 : 0;
    const int v_ro = ((mat & 1) ? 8 : 0) + mr;
    const int v_co = (mat & 2) ? 8 : 0;

    const uint32_t ksm = (uint32_t)__cvta_generic_to_shared(Kst);
    const uint32_t vsm = (uint32_t)__cvta_generic_to_shared(Vst);

    float m0 = -INFINITY, m1 = -INFINITY, l0 = 0.f, l1 = 0.f;
    float acc_o[16][4];
#pragma unroll
    for (int nb = 0; nb < 16; nb++)
#pragma unroll
        for (int t = 0; t < 4; t++) acc_o[nb][t] = 0.f;

    uint32_t pf[4][4];

    // ======== S-MMA block (macro-ized via lambda) ========
    auto s_mma = [&](float (&acc_s)[8][4], uint32_t kS) {
#pragma unroll
        for (int ni = 0; ni < 8; ni++)
#pragma unroll
            for (int t = 0; t < 4; t++) acc_s[ni][t] = 0.f;
#pragma unroll
        for (int ks = 0; ks < 8; ks++) {
            const int c0 = ks * 16;
#pragma unroll
            for (int np = 0; np < 4; np++) {
                uint32_t r0, r1, r2, r3;
                ldmx4(r0, r1, r2, r3,
                      kS + (uint32_t)(((np * 16 + k_ro) * FP + c0 + k_co) * 2));
                uint32_t b0[2] = {r0, r1};
                uint32_t b1[2] = {r2, r3};
                mma16816_f16(acc_s[2 * np],     qf[ks], b0);
                mma16816_f16(acc_s[2 * np + 1], qf[ks], b1);
            }
        }
    };

    auto pv_mma = [&](uint32_t vS) {
#pragma unroll
        for (int ks = 0; ks < 4; ks++) {
            const int c0 = ks * 16;
#pragma unroll
            for (int nb = 0; nb < 8; nb++) {
                uint32_t r0, r1, r2, r3;
                ldmx4t(r0, r1, r2, r3,
                       vS + (uint32_t)(((c0 + v_ro) * FP + nb * 16 + v_co) * 2));
                uint32_t b0[2] = {r0, r1};
                uint32_t b1[2] = {r2, r3};
                mma16816_f16(acc_o[2 * nb],     pf[ks], b0);
                mma16816_f16(acc_o[2 * nb + 1], pf[ks], b1);
            }
        }
    };

    auto softmax_pack = [&](float (&acc_s)[8][4]) {
        float mx0 = -INFINITY, mx1 = -INFINITY;
#pragma unroll
        for (int ni = 0; ni < 8; ni++) {
            mx0 = fmaxf(mx0, fmaxf(acc_s[ni][0], acc_s[ni][1]));
            mx1 = fmaxf(mx1, fmaxf(acc_s[ni][2], acc_s[ni][3]));
        }
        mx0 = fmaxf(mx0, __shfl_xor_sync(0xffffffffu, mx0, 1));
        mx0 = fmaxf(mx0, __shfl_xor_sync(0xffffffffu, mx0, 2));
        mx1 = fmaxf(mx1, __shfl_xor_sync(0xffffffffu, mx1, 1));
        mx1 = fmaxf(mx1, __shfl_xor_sync(0xffffffffu, mx1, 2));

        float mn0 = fmaxf(m0, mx0);
        float mn1 = fmaxf(m1, mx1);
        float corr0 = ex2f(m0 - mn0);
        float corr1 = ex2f(m1 - mn1);

        float s0 = 0.f, s1 = 0.f;
#pragma unroll
        for (int ni = 0; ni < 8; ni++) {
            acc_s[ni][0] = ex2f(acc_s[ni][0] - mn0);
            acc_s[ni][1] = ex2f(acc_s[ni][1] - mn0);
            acc_s[ni][2] = ex2f(acc_s[ni][2] - mn1);
            acc_s[ni][3] = ex2f(acc_s[ni][3] - mn1);
            s0 += acc_s[ni][0] + acc_s[ni][1];
            s1 += acc_s[ni][2] + acc_s[ni][3];
        }
        s0 += __shfl_xor_sync(0xffffffffu, s0, 1);
        s0 += __shfl_xor_sync(0xffffffffu, s0, 2);
        s1 += __shfl_xor_sync(0xffffffffu, s1, 1);
        s1 += __shfl_xor_sync(0xffffffffu, s1, 2);

        l0 = l0 * corr0 + s0;
        l1 = l1 * corr1 + s1;
        m0 = mn0;
        m1 = mn1;

        // rescale O (after PV of previous tile has accumulated)
#pragma unroll
        for (int nb = 0; nb < 16; nb++) {
            acc_o[nb][0] *= corr0; acc_o[nb][1] *= corr0;
            acc_o[nb][2] *= corr1; acc_o[nb][3] *= corr1;
        }

        // pack new P fragments
#pragma unroll
        for (int kb = 0; kb < 4; kb++) {
            pf[kb][0] = pack_h2(acc_s[2 * kb][0],     acc_s[2 * kb][1]);
            pf[kb][1] = pack_h2(acc_s[2 * kb][2],     acc_s[2 * kb][3]);
            pf[kb][2] = pack_h2(acc_s[2 * kb + 1][0], acc_s[2 * kb + 1][1]);
            pf[kb][3] = pack_h2(acc_s[2 * kb + 1][2], acc_s[2 * kb + 1][3]);
        }
    };

    // ---- tile 0: S + softmax only ----
    {
        float acc_s[8][4];
        s_mma(acc_s, ksm + 0);
        softmax_pack(acc_s);
    }

    // ---- pipelined main loop ----
    for (int kt = 1; kt < SEQ / 64; kt++) {
        CP_WAIT0();
        __syncthreads();
        if (kt + 1 < SEQ / 64) issue(kt + 1);

        const uint32_t kS = ksm + (uint32_t)((kt & 1) * KV_HALVES * 2);
        const uint32_t vS = vsm + (uint32_t)(((kt - 1) % 3) * KV_HALVES * 2);

        float acc_s[8][4];
        s_mma(acc_s, kS);       // S(kt)
        pv_mma(vS);             // PV(kt-1) — overlaps with softmax below
        softmax_pack(acc_s);    // softmax(kt), rescale acc_o, pf(kt)
    }

    // ---- epilogue: PV(last tile) ----
    pv_mma(vsm + (uint32_t)(((SEQ / 64 - 1) % 3) * KV_HALVES * 2));

    {
        const float inv0 = 1.0f / l0;
        const float inv1 = 1.0f / l1;
        const size_t tok0 = (size_t)(b * SEQ + qtile * 64 + w * 16 + g);
#pragma unroll
        for (int nb = 0; nb < 16; nb++) {
            const int col = nb * 8 + tg * 2;
            *(__half2*)(g_ao + tok0 * HID + h * HD + col) =
                __floats2half2_rn(acc_o[nb][0] * inv0, acc_o[nb][1] * inv0);
            *(__half2*)(g_ao + (tok0 + 8) * HID + h * HD + col) =
                __floats2half2_rn(acc_o[nb][2] * inv1, acc_o[nb][3] * inv1);
        }
    }
}

// ---------------------------------------------------------------------------
// kernel_launch
// ---------------------------------------------------------------------------
extern "C" void kernel_launch(void* const* d_in, const int* in_sizes, int n_in,
                              void* d_out, int out_size)
{
    (void)in_sizes; (void)n_in; (void)out_size;
    const float* hidden = (const float*)d_in[0];
    const float* Wq = (const float*)d_in[1];
    const float* bq = (const float*)d_in[2];
    const float* Wk = (const float*)d_in[3];
    const float* bk = (const float*)d_in[4];
    const float* Wv = (const float*)d_in[5];
    const float* bv = (const float*)d_in[6];
    const float* Wo = (const float*)d_in[7];
    const float* bo = (const float*)d_in[8];
    float* out = (float*)d_out;

    __half *ah, *qkv, *ao, *wt, *wot;
    float* biasp;
    cudaGetSymbolAddress((void**)&ah,    g_ah);
    cudaGetSymbolAddress((void**)&qkv,   g_qkv);
    cudaGetSymbolAddress((void**)&ao,    g_ao);
    cudaGetSymbolAddress((void**)&wt,    g_wt);
    cudaGetSymbolAddress((void**)&wot,   g_wo_t);
    cudaGetSymbolAddress((void**)&biasp, g_bias);

    static int attr_set = 0;
    if (!attr_set) {
        cudaFuncSetAttribute(flash_tc_kernel,
                             cudaFuncAttributeMaxDynamicSharedMemorySize, FA_SMEM);
        cudaFuncSetAttribute(gemm_h_kernel,
                             cudaFuncAttributeMaxDynamicSharedMemorySize, GEMM_SMEM);
        attr_set = 1;
    }

    // 128^-0.5 * log2(e) — scores pre-scaled so softmax uses exp2
    const float scaling = 0.08838834764831845f * 1.4426950408889634f;

    // 1) prep
    convert_h_kernel<<<(BS_ROWS * HID / 8) / 256, 256>>>(hidden, ah);
    prep_w_kernel<<<dim3(145, 64), 256>>>(Wq, Wk, Wv, Wo, bq, bk, bv, scaling);

    // 2) fused QKV projection
    gemm_h_kernel<<<dim3(QKVS / 128, BS_ROWS / 128), 256, GEMM_SMEM>>>(
        ah, wt, biasp, nullptr, qkv, QKVS, HID);

    // 3) flash attention
    flash_tc_kernel<<<dim3(SEQ / 64, NH, BATCH), 128, FA_SMEM>>>();

    // 4) O-projection
    gemm_h_kernel<<<dim3(HID / 128, BS_ROWS / 128), 256, GEMM_SMEM>>>(
        ao, wot, bo, out, nullptr, HID, HID);
}